// round 7
// baseline (speedup 1.0000x reference)
#include <cuda_runtime.h>
#include <cstdint>
#include <math.h>

#define B_ 8
#define C_ 128
#define H_ 256
#define W_ 256
#define HW (H_*W_)

// ----------------------------- device scratch -----------------------------
__device__ __align__(16) float g_actv[(size_t)B_*C_*HW];   // 268 MB actv (tf32-rounded)
__device__ float g_nT[(size_t)B_*HW];                      // transposed noise [b][h][w]
__device__ float g_mean[B_*C_];
__device__ float g_rstd[B_*C_];
__device__ float g_mu[B_*20*64];                           // row j=19 = zeros
__device__ __align__(16) float g_G2[B_*20*9*C_*2];         // [b][j][tap][co][{g,b}]
__device__ __align__(16) float g_G4[B_*20*16*C_*2];        // [b][j][ph][pw][u][v][co][{g,b}]
__device__ unsigned char g_cls[B_*128*128];
__device__ __align__(16) float g_B1[171*128];              // [j*9+t][co]
__device__ __align__(16) float g_B2t[256*1152];            // [n=co*2+sel][k=t*128+ci], tf32
__device__ float g_Cg[C_], g_Cb[C_], g_scal[2];

// ----------------------------- helpers -----------------------------
__device__ __forceinline__ unsigned long long fma2(unsigned long long a,
                                                   unsigned long long b,
                                                   unsigned long long c) {
    unsigned long long d;
    asm("fma.rn.f32x2 %0, %1, %2, %3;" : "=l"(d) : "l"(a), "l"(b), "l"(c));
    return d;
}
__device__ __forceinline__ unsigned long long pack2(float x, float y) {
    unsigned long long d;
    asm("mov.b64 %0, {%1, %2};" : "=l"(d) : "f"(x), "f"(y));
    return d;
}
__device__ __forceinline__ uint32_t smem_u32(const void* p) {
    uint32_t a;
    asm("{ .reg .u64 t; cvta.to.shared.u64 t, %1; cvt.u32.u64 %0, t; }" : "=r"(a) : "l"(p));
    return a;
}
__device__ __forceinline__ float to_tf32(float v) {
    unsigned o;
    asm("cvt.rna.tf32.f32 %0, %1;" : "=r"(o) : "f"(v));
    return __uint_as_float(o);
}
__device__ __forceinline__ void cpa4(uint32_t d, const void* g, int sz) {
    asm volatile("cp.async.ca.shared.global [%0], [%1], 4, %2;"
                 :: "r"(d), "l"(g), "r"(sz) : "memory");
}
__device__ __forceinline__ void cpa16(uint32_t d, const void* g) {
    asm volatile("cp.async.ca.shared.global [%0], [%1], 16;"
                 :: "r"(d), "l"(g) : "memory");
}
__device__ __forceinline__ void cp_commit() {
    asm volatile("cp.async.commit_group;" ::: "memory");
}
__device__ __forceinline__ void cp_wait0() {
    asm volatile("cp.async.wait_group 0;" ::: "memory");
}
__device__ __forceinline__ void mma_tf32(float* d, unsigned a0, unsigned a1,
                                         unsigned a2, unsigned a3,
                                         unsigned b0, unsigned b1) {
    asm volatile("mma.sync.aligned.m16n8k8.row.col.f32.tf32.tf32.f32 "
                 "{%0,%1,%2,%3}, {%4,%5,%6,%7}, {%8,%9}, {%0,%1,%2,%3};"
                 : "+f"(d[0]), "+f"(d[1]), "+f"(d[2]), "+f"(d[3])
                 : "r"(a0), "r"(a1), "r"(a2), "r"(a3), "r"(b0), "r"(b1));
}

// ----------------------------- prep kernels -----------------------------
__global__ void k_scal(const float* bg, const float* bb, const float* cgb,
                       const float* cbb, const float* sgb, const float* sbb) {
    int co = threadIdx.x;
    float ga = 1.f / (1.f + expf(-bg[0]));
    float ba = 1.f / (1.f + expf(-bb[0]));
    g_Cg[co] = ga * cgb[co] + (1.f - ga) * sgb[co];
    g_Cb[co] = ba * cbb[co] + (1.f - ba) * sbb[co];
    if (co == 0) { g_scal[0] = ga; g_scal[1] = ba; }
}

__global__ void k_mu(const float* sc, const float* fcw, const float* fcb) {
    int bj = blockIdx.x;               // 160 = b*20+j
    int b = bj / 20, j = bj - b * 20;
    int o = threadIdx.x;               // 64
    float r = 0.f;
    if (j < 19) {
        const float* s = sc + (b * 19 + j) * 64;
        const float* w = fcw + (j * 64 + o) * 64;
        #pragma unroll 8
        for (int i = 0; i < 64; i++) r = fmaf(s[i], w[i], r);
        r += fcb[j * 64 + o];
        r = fmaxf(r, 0.f);
    }
    g_mu[bj * 64 + o] = r;
}

__global__ void k_cls(const float* segmap) {
    int idx = blockIdx.x * 256 + threadIdx.x;
    if (idx >= B_ * 128 * 128) return;
    int b = idx >> 14, p = idx & 16383;
    int cls = 19;
    for (int j = 18; j >= 0; j--) {
        if (segmap[(((size_t)b * 19 + j) << 14) + p] > 0.f) { cls = j; break; }
    }
    g_cls[idx] = (unsigned char)cls;
}

__global__ void k_w1(const float* ssw) {
    int idx = blockIdx.x * 256 + threadIdx.x;
    if (idx >= 171 * 128) return;
    int k = idx >> 7, co = idx & 127;
    int j = k / 9, t = k - j * 9;
    g_B1[idx] = ssw[(co * 19 + j) * 9 + t];
}

// B^T for mma: g_B2t[n][k], n = co*2+sel (even=gamma, odd=beta), k = t*128+ci, tf32-rounded
__global__ void k_w2(const float* gw, const float* bw) {
    int idx = blockIdx.x * 256 + threadIdx.x;
    if (idx >= 256 * 1152) return;
    int n = idx / 1152, k = idx - n * 1152;
    int t = k >> 7, ci = k & 127;
    int co = n >> 1;
    const float* w = (n & 1) ? bw : gw;
    g_B2t[idx] = to_tf32(w[(co * 128 + ci) * 9 + t]);
}

__global__ void k_ntr(const float* noise) {  // g_nT[b][h][w] = noise[b][w][h]
    __shared__ float t[32][33];
    int b = blockIdx.z;
    int w0 = blockIdx.x * 32, h0 = blockIdx.y * 32;
    int tx = threadIdx.x, ty = threadIdx.y;  // 32x8
    for (int i = 0; i < 32; i += 8)
        t[ty + i][tx] = noise[((size_t)b * 256 + w0 + ty + i) * 256 + h0 + tx];
    __syncthreads();
    for (int i = 0; i < 32; i += 8)
        g_nT[((size_t)b * 256 + h0 + ty + i) * 256 + w0 + tx] = t[tx][ty + i];
}

__global__ __launch_bounds__(256) void k_stats(const float* x, const float* nvar) {
    int bc = blockIdx.x;             // 1024
    int b = bc >> 7, c = bc & 127;
    float nv = nvar[c];
    const float* xb = x + (size_t)bc * HW;
    const float* nb = g_nT + (size_t)b * HW;
    float s = 0.f, q = 0.f;
    for (int i = threadIdx.x; i < HW; i += 256) {
        float v = xb[i] + nb[i] * nv;
        s += v; q = fmaf(v, v, q);
    }
    __shared__ float ss[8], sq[8];
    #pragma unroll
    for (int o = 16; o; o >>= 1) {
        s += __shfl_xor_sync(0xffffffffu, s, o);
        q += __shfl_xor_sync(0xffffffffu, q, o);
    }
    int wid = threadIdx.x >> 5, lane = threadIdx.x & 31;
    if (!lane) { ss[wid] = s; sq[wid] = q; }
    __syncthreads();
    if (threadIdx.x == 0) {
        float S = 0.f, Q = 0.f;
        #pragma unroll
        for (int k = 0; k < 8; k++) { S += ss[k]; Q += sq[k]; }
        float m = S * (1.f / HW);
        float var = Q * (1.f / HW) - m * m;
        g_mean[bc] = m;
        g_rstd[bc] = rsqrtf(var + 1e-5f);
    }
}

__global__ __launch_bounds__(128) void k_lut1(const float* gw, const float* bw) {
    int bj = blockIdx.x;    // 160
    int co = threadIdx.x;   // 128
    __shared__ float mu_s[64];
    if (co < 64) mu_s[co] = g_mu[bj * 64 + co];
    __syncthreads();
    for (int t = 0; t < 9; t++) {
        float sg = 0.f, sb = 0.f;
        #pragma unroll 8
        for (int ci = 0; ci < 64; ci++) {
            float m = mu_s[ci];
            sg = fmaf(gw[(co * 64 + ci) * 9 + t], m, sg);
            sb = fmaf(bw[(co * 64 + ci) * 9 + t], m, sb);
        }
        int o = ((bj * 9 + t) * 128 + co) * 2;
        g_G2[o] = sg; g_G2[o + 1] = sb;
    }
}

__global__ __launch_bounds__(256) void k_lut2() {
    int bj = blockIdx.x;    // 160
    int n = threadIdx.x;    // 256
    const float* G = g_G2 + (size_t)bj * 9 * 256;
    float* O = g_G4 + (size_t)bj * 16 * 256;
    for (int ph = 0; ph < 2; ph++)
    for (int pw = 0; pw < 2; pw++)
    for (int u = 0; u < 2; u++)
    for (int v = 0; v < 2; v++) {
        int rlo = (u == 0) ? 0 : (ph == 0 ? 1 : 2);
        int rhi = (u == 0) ? (ph == 0 ? 0 : 1) : 2;
        int clo = (v == 0) ? 0 : (pw == 0 ? 1 : 2);
        int chi = (v == 0) ? (pw == 0 ? 0 : 1) : 2;
        float s = 0.f;
        for (int dy = rlo; dy <= rhi; dy++)
            for (int dx = clo; dx <= chi; dx++)
                s += G[(dy * 3 + dx) * 256 + n];
        O[(((ph * 2 + pw) * 2 + u) * 2 + v) * 256 + n] = s;
    }
}

// ----------------------------- stage A: actv conv (19 -> 128), FFMA2 -----------------------------
__global__ __launch_bounds__(256, 2) void k_actv(const float* segmap, const float* ssb) {
    __shared__ float Sh[19][4][10];
    __shared__ __align__(16) float Bsj[9][128];
    int b = blockIdx.z;
    int x0 = blockIdx.x * 16, y0 = blockIdx.y * 4;
    int tid = threadIdx.x;
    int tx = tid & 15, ty = tid >> 4;
    int r = ty >> 2, c = (ty & 3) * 4;

    int hb = (y0 >> 1) - 1, cbh = (x0 >> 1) - 1;
    for (int idx = tid; idx < 19 * 40; idx += 256) {
        int j = idx / 40, pos = idx - j * 40;
        int hr = pos / 10, hc = pos - hr * 10;
        int gy = hb + hr, gx = cbh + hc;
        float v = 0.f;
        if ((unsigned)gy < 128u && (unsigned)gx < 128u)
            v = segmap[(((size_t)b * 19 + j) << 14) + gy * 128 + gx];
        Sh[j][hr][hc] = v;
    }

    int hrw[3], hcc[6];
    #pragma unroll
    for (int k = 0; k < 3; k++) hrw[k] = ((r + k - 1) >> 1) + 1;
    #pragma unroll
    for (int k = 0; k < 6; k++) hcc[k] = ((c + k - 1) >> 1) + 1;

    unsigned long long acc[4][4];
    #pragma unroll
    for (int p = 0; p < 4; p++)
        #pragma unroll
        for (int q = 0; q < 4; q++) acc[p][q] = 0ull;

    for (int j = 0; j < 19; j++) {
        __syncthreads();
        for (int idx = tid; idx < 1152; idx += 256)
            ((float*)Bsj)[idx] = g_B1[j * 1152 + idx];
        __syncthreads();
        #pragma unroll
        for (int t = 0; t < 9; t++) {
            const int tdy = t / 3, tdx = t - tdy * 3;
            unsigned long long Ap[4];
            #pragma unroll
            for (int i = 0; i < 4; i++) {
                float a = Sh[j][hrw[tdy]][hcc[tdx + i]];
                Ap[i] = pack2(a, a);
            }
            ulonglong2 b0 = *(const ulonglong2*)&Bsj[t][tx * 4];
            ulonglong2 b1 = *(const ulonglong2*)&Bsj[t][tx * 4 + 64];
            #pragma unroll
            for (int p = 0; p < 4; p++) {
                acc[p][0] = fma2(Ap[p], b0.x, acc[p][0]);
                acc[p][1] = fma2(Ap[p], b0.y, acc[p][1]);
                acc[p][2] = fma2(Ap[p], b1.x, acc[p][2]);
                acc[p][3] = fma2(Ap[p], b1.y, acc[p][3]);
            }
        }
    }

    int y = y0 + r, xg0 = x0 + c;
    #pragma unroll
    for (int q = 0; q < 4; q++) {
        int co0 = (q < 2) ? (tx * 4 + q * 2) : (tx * 4 + 64 + (q - 2) * 2);
        #pragma unroll
        for (int h2 = 0; h2 < 2; h2++) {
            int co = co0 + h2;
            float bias = ssb[co];
            float4 o;
            float* op = (float*)&o;
            #pragma unroll
            for (int p = 0; p < 4; p++) {
                unsigned long long v = acc[p][q];
                unsigned w32 = h2 ? (unsigned)(v >> 32) : (unsigned)v;
                op[p] = to_tf32(fmaxf(__uint_as_float(w32) + bias, 0.f));
            }
            *(float4*)&g_actv[(((size_t)b * 128 + co) * 256 + y) * 256 + xg0] = o;
        }
    }
}

// ------------- stage B: tf32 mma.sync implicit GEMM + fused epilogue -------------
// CTA: 128 pixels (8x16 tile) x N=256 (gamma/beta interleaved), K=1152 in 16-chunks
// (one 3x3 tap x 16 input channels per chunk). 8 warps, 2Mx4N, warp tile 64x64.
// smem pitch 20 floats -> conflict-free m16n8k8 fragment LDS. cp.async double buffer.
#define NQ 72
#define SMEM_MAIN (61440)

__global__ __launch_bounds__(256) void k_main_mma(const float* __restrict__ x,
                                                  const float* __restrict__ nvar,
                                                  float* __restrict__ out) {
    extern __shared__ float smf[];
    float* Asb[2] = { smf,        smf + 2560 };   // 128 rows x pitch 20
    float* Bsb[2] = { smf + 5120, smf + 10240 };  // 256 rows x pitch 20
    uint32_t AS_u[2] = { smem_u32(Asb[0]), smem_u32(Asb[1]) };
    uint32_t BS_u[2] = { smem_u32(Bsb[0]), smem_u32(Bsb[1]) };

    int tid = threadIdx.x, lane = tid & 31, wid = tid >> 5;
    int grp = lane >> 2, tg = lane & 3;
    int warp_m = (wid & 1) * 64, warp_n = (wid >> 1) * 64;
    int b = blockIdx.z;
    int x0 = blockIdx.x * 16, y0 = blockIdx.y * 8;

    // A-fill mapping: m = tid&127 (lane-consecutive => coalesced), k-half = tid>>7
    int mA = tid & 127, khA = (tid >> 7) * 8;
    int yA = y0 + (mA >> 4), xA = x0 + (mA & 15);
    uint32_t dstA0[2], dstB0[2];
    dstA0[0] = AS_u[0] + (uint32_t)(mA * 20 + khA) * 4u;
    dstA0[1] = AS_u[1] + (uint32_t)(mA * 20 + khA) * 4u;
    dstB0[0] = BS_u[0] + (uint32_t)tid * 80u;
    dstB0[1] = BS_u[1] + (uint32_t)tid * 80u;

    float acc[4][8][4];
    #pragma unroll
    for (int i = 0; i < 4; i++)
        #pragma unroll
        for (int j = 0; j < 8; j++)
            #pragma unroll
            for (int k = 0; k < 4; k++) acc[i][j][k] = 0.f;

    auto issue = [&](int q, int buf) {
        int t = q >> 3, ci0 = (q & 7) << 4;
        int tdy = t / 3;
        int dy = tdy - 1, dx = (t - tdy * 3) - 1;
        // A im2col: As[m][k] = actv[b][ci0+khA+k'][yA+dy][xA+dx]
        int yy = yA + dy, xx = xA + dx;
        bool ok = ((unsigned)yy < 256u) && ((unsigned)xx < 256u);
        int sz = ok ? 4 : 0;
        const float* gA = &g_actv[(((size_t)b * 128 + ci0 + khA) * 256
                                   + (ok ? yy : 0)) * 256 + (ok ? xx : 0)];
        uint32_t dA = dstA0[buf];
        #pragma unroll
        for (int i = 0; i < 8; i++)
            cpa4(dA + i * 4u, gA + (size_t)i * HW, sz);
        // B: Bs[n][k] from g_B2t[n*1152 + t*128 + ci0 + k]
        const float* gB = &g_B2t[(size_t)tid * 1152 + t * 128 + ci0];
        uint32_t dB = dstB0[buf];
        #pragma unroll
        for (int i = 0; i < 4; i++)
            cpa16(dB + i * 16u, gB + i * 4);
        cp_commit();
    };

    issue(0, 0);
    #pragma unroll 1
    for (int q = 0; q < NQ; q++) {
        cp_wait0();
        __syncthreads();
        if (q + 1 < NQ) issue(q + 1, (q + 1) & 1);
        const float* As_ = Asb[q & 1];
        const float* Bs_ = Bsb[q & 1];
        #pragma unroll
        for (int ks = 0; ks < 2; ks++) {
            int k0 = ks * 8 + tg;
            unsigned bf0[8], bf1[8];
            #pragma unroll
            for (int j = 0; j < 8; j++) {
                const float* p = Bs_ + (warp_n + j * 8 + grp) * 20 + k0;
                bf0[j] = __float_as_uint(p[0]);
                bf1[j] = __float_as_uint(p[4]);
            }
            #pragma unroll
            for (int i = 0; i < 4; i++) {
                const float* p = As_ + (warp_m + i * 16 + grp) * 20 + k0;
                unsigned a0 = __float_as_uint(p[0]);
                unsigned a2 = __float_as_uint(p[4]);
                unsigned a1 = __float_as_uint(p[160]);
                unsigned a3 = __float_as_uint(p[164]);
                #pragma unroll
                for (int j = 0; j < 8; j++)
                    mma_tf32(acc[i][j], a0, a1, a2, a3, bf0[j], bf1[j]);
            }
        }
    }

    // ---------------- fused epilogue ----------------
    float ga = g_scal[0], ba = g_scal[1];
    unsigned rowb[4][2][4];
    float nzv[4][2];
    int yv[4][2], xv_[4][2];
    #pragma unroll
    for (int i = 0; i < 4; i++)
        #pragma unroll
        for (int h = 0; h < 2; h++) {
            int m = warp_m + i * 16 + grp + h * 8;
            int y = y0 + (m >> 4), xg = x0 + (m & 15);
            yv[i][h] = y; xv_[i][h] = xg;
            nzv[i][h] = g_nT[((size_t)b * 256 + y) * 256 + xg];
            int ph = y & 1, pw = xg & 1;
            int r0 = (y - 1) >> 1, c0 = (xg - 1) >> 1;
            #pragma unroll
            for (int u = 0; u < 2; u++)
                #pragma unroll
                for (int v = 0; v < 2; v++) {
                    int cy = r0 + u, cx = c0 + v;
                    int cls = 19;
                    if ((unsigned)cy < 128u && (unsigned)cx < 128u)
                        cls = g_cls[((size_t)b << 14) + cy * 128 + cx];
                    rowb[i][h][u * 2 + v] =
                        (unsigned)(((((b * 20 + cls) * 2 + ph) * 2 + pw) * 2 + u) * 2 + v) * 256u;
                }
        }

    #pragma unroll 1
    for (int j = 0; j < 8; j++) {
        int co = (warp_n >> 1) + j * 4 + tg;
        float mean = g_mean[b * 128 + co];
        float rs = g_rstd[b * 128 + co];
        float nv = nvar[co];
        float cg = g_Cg[co], cb = g_Cb[co];
        #pragma unroll
        for (int i = 0; i < 4; i++)
            #pragma unroll
            for (int h = 0; h < 2; h++) {
                float gsp = acc[i][j][h * 2 + 0];
                float bsp = acc[i][j][h * 2 + 1];
                float ag = 0.f, ab = 0.f;
                #pragma unroll
                for (int k = 0; k < 4; k++) {
                    float2 gg = *(const float2*)&g_G4[rowb[i][h][k] + (unsigned)co * 2u];
                    ag += gg.x; ab += gg.y;
                }
                size_t idx = (((size_t)b * 128 + co) * 256 + yv[i][h]) * 256 + xv_[i][h];
                float xval = x[idx];
                float gf = ga * ag + (1.f - ga) * gsp + cg;
                float bf = ba * ab + (1.f - ba) * bsp + cb;
                float val = (xval + nzv[i][h] * nv - mean) * rs;
                out[idx] = fmaf(val, gf, val + bf);
            }
    }
}

// ----------------------------- launch -----------------------------
extern "C" void kernel_launch(void* const* d_in, const int* in_sizes, int n_in,
                              void* d_out, int out_size) {
    const float* x     = (const float*)d_in[0];
    const float* seg   = (const float*)d_in[1];
    const float* sc    = (const float*)d_in[2];
    const float* noise = (const float*)d_in[3];
    const float* nvar  = (const float*)d_in[4];
    const float* bg    = (const float*)d_in[5];
    const float* bb    = (const float*)d_in[6];
    const float* fcw   = (const float*)d_in[7];
    const float* fcb   = (const float*)d_in[8];
    const float* cgw   = (const float*)d_in[9];
    const float* cgb   = (const float*)d_in[10];
    const float* cbw   = (const float*)d_in[11];
    const float* cbb   = (const float*)d_in[12];
    const float* ssw   = (const float*)d_in[13];
    const float* ssb   = (const float*)d_in[14];
    const float* sgw   = (const float*)d_in[15];
    const float* sgb   = (const float*)d_in[16];
    const float* sbw   = (const float*)d_in[17];
    const float* sbb   = (const float*)d_in[18];
    float* out = (float*)d_out;

    cudaFuncSetAttribute(k_main_mma, cudaFuncAttributeMaxDynamicSharedMemorySize, SMEM_MAIN);

    k_scal<<<1, 128>>>(bg, bb, cgb, cbb, sgb, sbb);
    k_mu<<<160, 64>>>(sc, fcw, fcb);
    k_cls<<<512, 256>>>(seg);
    k_w1<<<86, 256>>>(ssw);
    k_w2<<<1152, 256>>>(sgw, sbw);
    k_ntr<<<dim3(8, 8, 8), dim3(32, 8)>>>(noise);
    k_stats<<<1024, 256>>>(x, nvar);
    k_lut1<<<160, 128>>>(cgw, cbw);
    k_lut2<<<160, 256>>>();
    k_actv<<<dim3(16, 64, 8), 256>>>(seg, ssb);
    k_main_mma<<<dim3(16, 32, 8), 256, SMEM_MAIN>>>(x, nvar, out);
}

// round 8
// speedup vs baseline: 1.0030x; 1.0030x over previous
#include <cuda_runtime.h>
#include <cstdint>
#include <math.h>

#define B_ 8
#define C_ 128
#define H_ 256
#define W_ 256
#define HW (H_*W_)

// ----------------------------- device scratch -----------------------------
__device__ __align__(16) float g_actv[(size_t)B_*C_*HW];   // 268 MB actv (tf32-rounded)
__device__ float g_nT[(size_t)B_*HW];                      // transposed noise [b][h][w]
__device__ float g_mean[B_*C_];
__device__ float g_rstd[B_*C_];
__device__ float g_mu[B_*20*64];                           // row j=19 = zeros
__device__ __align__(16) float g_G2[B_*20*9*C_*2];         // [b][j][tap][co][{g,b}]
__device__ __align__(16) float g_G4[B_*20*16*C_*2];        // [b][j][ph][pw][u][v][co][{g,b}]
__device__ unsigned char g_cls[B_*128*128];
__device__ __align__(16) float g_B1[171*128];              // [j*9+t][co]
__device__ __align__(16) float g_B2t[256*1152];            // [n=co*2+sel][k=t*128+ci], tf32
__device__ float g_Cg[C_], g_Cb[C_], g_scal[2];

// ----------------------------- helpers -----------------------------
__device__ __forceinline__ unsigned long long fma2(unsigned long long a,
                                                   unsigned long long b,
                                                   unsigned long long c) {
    unsigned long long d;
    asm("fma.rn.f32x2 %0, %1, %2, %3;" : "=l"(d) : "l"(a), "l"(b), "l"(c));
    return d;
}
__device__ __forceinline__ unsigned long long pack2(float x, float y) {
    unsigned long long d;
    asm("mov.b64 %0, {%1, %2};" : "=l"(d) : "f"(x), "f"(y));
    return d;
}
__device__ __forceinline__ uint32_t smem_u32(const void* p) {
    uint32_t a;
    asm("{ .reg .u64 t; cvta.to.shared.u64 t, %1; cvt.u32.u64 %0, t; }" : "=r"(a) : "l"(p));
    return a;
}
__device__ __forceinline__ float to_tf32(float v) {
    unsigned o;
    asm("cvt.rna.tf32.f32 %0, %1;" : "=r"(o) : "f"(v));
    return __uint_as_float(o);
}
__device__ __forceinline__ void cpa4(uint32_t d, const void* g, int sz) {
    asm volatile("cp.async.ca.shared.global [%0], [%1], 4, %2;"
                 :: "r"(d), "l"(g), "r"(sz) : "memory");
}
__device__ __forceinline__ void cpa16(uint32_t d, const void* g) {
    asm volatile("cp.async.ca.shared.global [%0], [%1], 16;"
                 :: "r"(d), "l"(g) : "memory");
}
__device__ __forceinline__ void cp_commit() {
    asm volatile("cp.async.commit_group;" ::: "memory");
}
__device__ __forceinline__ void cp_wait0() {
    asm volatile("cp.async.wait_group 0;" ::: "memory");
}
__device__ __forceinline__ void mma_tf32(float* d, unsigned a0, unsigned a1,
                                         unsigned a2, unsigned a3,
                                         unsigned b0, unsigned b1) {
    asm volatile("mma.sync.aligned.m16n8k8.row.col.f32.tf32.tf32.f32 "
                 "{%0,%1,%2,%3}, {%4,%5,%6,%7}, {%8,%9}, {%0,%1,%2,%3};"
                 : "+f"(d[0]), "+f"(d[1]), "+f"(d[2]), "+f"(d[3])
                 : "r"(a0), "r"(a1), "r"(a2), "r"(a3), "r"(b0), "r"(b1));
}

// ----------------------------- prep kernels -----------------------------
__global__ void k_scal(const float* bg, const float* bb, const float* cgb,
                       const float* cbb, const float* sgb, const float* sbb) {
    int co = threadIdx.x;
    float ga = 1.f / (1.f + expf(-bg[0]));
    float ba = 1.f / (1.f + expf(-bb[0]));
    g_Cg[co] = ga * cgb[co] + (1.f - ga) * sgb[co];
    g_Cb[co] = ba * cbb[co] + (1.f - ba) * sbb[co];
    if (co == 0) { g_scal[0] = ga; g_scal[1] = ba; }
}

__global__ void k_mu(const float* sc, const float* fcw, const float* fcb) {
    int bj = blockIdx.x;               // 160 = b*20+j
    int b = bj / 20, j = bj - b * 20;
    int o = threadIdx.x;               // 64
    float r = 0.f;
    if (j < 19) {
        const float* s = sc + (b * 19 + j) * 64;
        const float* w = fcw + (j * 64 + o) * 64;
        #pragma unroll 8
        for (int i = 0; i < 64; i++) r = fmaf(s[i], w[i], r);
        r += fcb[j * 64 + o];
        r = fmaxf(r, 0.f);
    }
    g_mu[bj * 64 + o] = r;
}

__global__ void k_cls(const float* segmap) {
    int idx = blockIdx.x * 256 + threadIdx.x;
    if (idx >= B_ * 128 * 128) return;
    int b = idx >> 14, p = idx & 16383;
    int cls = 19;
    for (int j = 18; j >= 0; j--) {
        if (segmap[(((size_t)b * 19 + j) << 14) + p] > 0.f) { cls = j; break; }
    }
    g_cls[idx] = (unsigned char)cls;
}

__global__ void k_w1(const float* ssw) {
    int idx = blockIdx.x * 256 + threadIdx.x;
    if (idx >= 171 * 128) return;
    int k = idx >> 7, co = idx & 127;
    int j = k / 9, t = k - j * 9;
    g_B1[idx] = ssw[(co * 19 + j) * 9 + t];
}

// B^T for mma: g_B2t[n][k], n = co*2+sel (even=gamma, odd=beta), k = t*128+ci, tf32-rounded
__global__ void k_w2(const float* gw, const float* bw) {
    int idx = blockIdx.x * 256 + threadIdx.x;
    if (idx >= 256 * 1152) return;
    int n = idx / 1152, k = idx - n * 1152;
    int t = k >> 7, ci = k & 127;
    int co = n >> 1;
    const float* w = (n & 1) ? bw : gw;
    g_B2t[idx] = to_tf32(w[(co * 128 + ci) * 9 + t]);
}

__global__ void k_ntr(const float* noise) {  // g_nT[b][h][w] = noise[b][w][h]
    __shared__ float t[32][33];
    int b = blockIdx.z;
    int w0 = blockIdx.x * 32, h0 = blockIdx.y * 32;
    int tx = threadIdx.x, ty = threadIdx.y;  // 32x8
    for (int i = 0; i < 32; i += 8)
        t[ty + i][tx] = noise[((size_t)b * 256 + w0 + ty + i) * 256 + h0 + tx];
    __syncthreads();
    for (int i = 0; i < 32; i += 8)
        g_nT[((size_t)b * 256 + h0 + ty + i) * 256 + w0 + tx] = t[tx][ty + i];
}

__global__ __launch_bounds__(256) void k_stats(const float* x, const float* nvar) {
    int bc = blockIdx.x;             // 1024
    int b = bc >> 7, c = bc & 127;
    float nv = nvar[c];
    const float* xb = x + (size_t)bc * HW;
    const float* nb = g_nT + (size_t)b * HW;
    float s = 0.f, q = 0.f;
    for (int i = threadIdx.x; i < HW; i += 256) {
        float v = xb[i] + nb[i] * nv;
        s += v; q = fmaf(v, v, q);
    }
    __shared__ float ss[8], sq[8];
    #pragma unroll
    for (int o = 16; o; o >>= 1) {
        s += __shfl_xor_sync(0xffffffffu, s, o);
        q += __shfl_xor_sync(0xffffffffu, q, o);
    }
    int wid = threadIdx.x >> 5, lane = threadIdx.x & 31;
    if (!lane) { ss[wid] = s; sq[wid] = q; }
    __syncthreads();
    if (threadIdx.x == 0) {
        float S = 0.f, Q = 0.f;
        #pragma unroll
        for (int k = 0; k < 8; k++) { S += ss[k]; Q += sq[k]; }
        float m = S * (1.f / HW);
        float var = Q * (1.f / HW) - m * m;
        g_mean[bc] = m;
        g_rstd[bc] = rsqrtf(var + 1e-5f);
    }
}

__global__ __launch_bounds__(128) void k_lut1(const float* gw, const float* bw) {
    int bj = blockIdx.x;    // 160
    int co = threadIdx.x;   // 128
    __shared__ float mu_s[64];
    if (co < 64) mu_s[co] = g_mu[bj * 64 + co];
    __syncthreads();
    for (int t = 0; t < 9; t++) {
        float sg = 0.f, sb = 0.f;
        #pragma unroll 8
        for (int ci = 0; ci < 64; ci++) {
            float m = mu_s[ci];
            sg = fmaf(gw[(co * 64 + ci) * 9 + t], m, sg);
            sb = fmaf(bw[(co * 64 + ci) * 9 + t], m, sb);
        }
        int o = ((bj * 9 + t) * 128 + co) * 2;
        g_G2[o] = sg; g_G2[o + 1] = sb;
    }
}

__global__ __launch_bounds__(256) void k_lut2() {
    int bj = blockIdx.x;    // 160
    int n = threadIdx.x;    // 256
    const float* G = g_G2 + (size_t)bj * 9 * 256;
    float* O = g_G4 + (size_t)bj * 16 * 256;
    for (int ph = 0; ph < 2; ph++)
    for (int pw = 0; pw < 2; pw++)
    for (int u = 0; u < 2; u++)
    for (int v = 0; v < 2; v++) {
        int rlo = (u == 0) ? 0 : (ph == 0 ? 1 : 2);
        int rhi = (u == 0) ? (ph == 0 ? 0 : 1) : 2;
        int clo = (v == 0) ? 0 : (pw == 0 ? 1 : 2);
        int chi = (v == 0) ? (pw == 0 ? 0 : 1) : 2;
        float s = 0.f;
        for (int dy = rlo; dy <= rhi; dy++)
            for (int dx = clo; dx <= chi; dx++)
                s += G[(dy * 3 + dx) * 256 + n];
        O[(((ph * 2 + pw) * 2 + u) * 2 + v) * 256 + n] = s;
    }
}

// ----------------------------- stage A: actv conv (19 -> 128), FFMA2 -----------------------------
__global__ __launch_bounds__(256, 2) void k_actv(const float* segmap, const float* ssb) {
    __shared__ float Sh[19][4][10];
    __shared__ __align__(16) float Bsj[9][128];
    int b = blockIdx.z;
    int x0 = blockIdx.x * 16, y0 = blockIdx.y * 4;
    int tid = threadIdx.x;
    int tx = tid & 15, ty = tid >> 4;
    int r = ty >> 2, c = (ty & 3) * 4;

    int hb = (y0 >> 1) - 1, cbh = (x0 >> 1) - 1;
    for (int idx = tid; idx < 19 * 40; idx += 256) {
        int j = idx / 40, pos = idx - j * 40;
        int hr = pos / 10, hc = pos - hr * 10;
        int gy = hb + hr, gx = cbh + hc;
        float v = 0.f;
        if ((unsigned)gy < 128u && (unsigned)gx < 128u)
            v = segmap[(((size_t)b * 19 + j) << 14) + gy * 128 + gx];
        Sh[j][hr][hc] = v;
    }

    int hrw[3], hcc[6];
    #pragma unroll
    for (int k = 0; k < 3; k++) hrw[k] = ((r + k - 1) >> 1) + 1;
    #pragma unroll
    for (int k = 0; k < 6; k++) hcc[k] = ((c + k - 1) >> 1) + 1;

    unsigned long long acc[4][4];
    #pragma unroll
    for (int p = 0; p < 4; p++)
        #pragma unroll
        for (int q = 0; q < 4; q++) acc[p][q] = 0ull;

    for (int j = 0; j < 19; j++) {
        __syncthreads();
        for (int idx = tid; idx < 1152; idx += 256)
            ((float*)Bsj)[idx] = g_B1[j * 1152 + idx];
        __syncthreads();
        #pragma unroll
        for (int t = 0; t < 9; t++) {
            const int tdy = t / 3, tdx = t - tdy * 3;
            unsigned long long Ap[4];
            #pragma unroll
            for (int i = 0; i < 4; i++) {
                float a = Sh[j][hrw[tdy]][hcc[tdx + i]];
                Ap[i] = pack2(a, a);
            }
            ulonglong2 b0 = *(const ulonglong2*)&Bsj[t][tx * 4];
            ulonglong2 b1 = *(const ulonglong2*)&Bsj[t][tx * 4 + 64];
            #pragma unroll
            for (int p = 0; p < 4; p++) {
                acc[p][0] = fma2(Ap[p], b0.x, acc[p][0]);
                acc[p][1] = fma2(Ap[p], b0.y, acc[p][1]);
                acc[p][2] = fma2(Ap[p], b1.x, acc[p][2]);
                acc[p][3] = fma2(Ap[p], b1.y, acc[p][3]);
            }
        }
    }

    int y = y0 + r, xg0 = x0 + c;
    #pragma unroll
    for (int q = 0; q < 4; q++) {
        int co0 = (q < 2) ? (tx * 4 + q * 2) : (tx * 4 + 64 + (q - 2) * 2);
        #pragma unroll
        for (int h2 = 0; h2 < 2; h2++) {
            int co = co0 + h2;
            float bias = ssb[co];
            float4 o;
            float* op = (float*)&o;
            #pragma unroll
            for (int p = 0; p < 4; p++) {
                unsigned long long v = acc[p][q];
                unsigned w32 = h2 ? (unsigned)(v >> 32) : (unsigned)v;
                op[p] = to_tf32(fmaxf(__uint_as_float(w32) + bias, 0.f));
            }
            *(float4*)&g_actv[(((size_t)b * 128 + co) * 256 + y) * 256 + xg0] = o;
        }
    }
}

// ------------- stage B: tf32 mma.sync implicit GEMM + fused epilogue -------------
// CTA: 128 pixels (8x16 tile) x N=256 (gamma/beta interleaved), K=1152 in 16-chunks
// (one 3x3 tap x 16 input channels per chunk). 8 warps, 2Mx4N, warp tile 64x64.
// smem pitch 20 floats -> conflict-free m16n8k8 fragment LDS. cp.async double buffer.
#define NQ 72
#define SMEM_MAIN (61440)

__global__ __launch_bounds__(256) void k_main_mma(const float* __restrict__ x,
                                                  const float* __restrict__ nvar,
                                                  float* __restrict__ out) {
    extern __shared__ float smf[];
    float* Asb[2] = { smf,        smf + 2560 };   // 128 rows x pitch 20
    float* Bsb[2] = { smf + 5120, smf + 10240 };  // 256 rows x pitch 20
    uint32_t AS_u[2] = { smem_u32(Asb[0]), smem_u32(Asb[1]) };
    uint32_t BS_u[2] = { smem_u32(Bsb[0]), smem_u32(Bsb[1]) };

    int tid = threadIdx.x, lane = tid & 31, wid = tid >> 5;
    int grp = lane >> 2, tg = lane & 3;
    int warp_m = (wid & 1) * 64, warp_n = (wid >> 1) * 64;
    int b = blockIdx.z;
    int x0 = blockIdx.x * 16, y0 = blockIdx.y * 8;

    // A-fill mapping: m = tid&127 (lane-consecutive => coalesced), k-half = tid>>7
    int mA = tid & 127, khA = (tid >> 7) * 8;
    int yA = y0 + (mA >> 4), xA = x0 + (mA & 15);
    uint32_t dstA0[2], dstB0[2];
    dstA0[0] = AS_u[0] + (uint32_t)(mA * 20 + khA) * 4u;
    dstA0[1] = AS_u[1] + (uint32_t)(mA * 20 + khA) * 4u;
    dstB0[0] = BS_u[0] + (uint32_t)tid * 80u;
    dstB0[1] = BS_u[1] + (uint32_t)tid * 80u;

    float acc[4][8][4];
    #pragma unroll
    for (int i = 0; i < 4; i++)
        #pragma unroll
        for (int j = 0; j < 8; j++)
            #pragma unroll
            for (int k = 0; k < 4; k++) acc[i][j][k] = 0.f;

    auto issue = [&](int q, int buf) {
        int t = q >> 3, ci0 = (q & 7) << 4;
        int tdy = t / 3;
        int dy = tdy - 1, dx = (t - tdy * 3) - 1;
        // A im2col: As[m][k] = actv[b][ci0+khA+k'][yA+dy][xA+dx]
        int yy = yA + dy, xx = xA + dx;
        bool ok = ((unsigned)yy < 256u) && ((unsigned)xx < 256u);
        int sz = ok ? 4 : 0;
        const float* gA = &g_actv[(((size_t)b * 128 + ci0 + khA) * 256
                                   + (ok ? yy : 0)) * 256 + (ok ? xx : 0)];
        uint32_t dA = dstA0[buf];
        #pragma unroll
        for (int i = 0; i < 8; i++)
            cpa4(dA + i * 4u, gA + (size_t)i * HW, sz);
        // B: Bs[n][k] from g_B2t[n*1152 + t*128 + ci0 + k]
        const float* gB = &g_B2t[(size_t)tid * 1152 + t * 128 + ci0];
        uint32_t dB = dstB0[buf];
        #pragma unroll
        for (int i = 0; i < 4; i++)
            cpa16(dB + i * 16u, gB + i * 4);
        cp_commit();
    };

    issue(0, 0);
    #pragma unroll 1
    for (int q = 0; q < NQ; q++) {
        cp_wait0();
        __syncthreads();
        if (q + 1 < NQ) issue(q + 1, (q + 1) & 1);
        const float* As_ = Asb[q & 1];
        const float* Bs_ = Bsb[q & 1];
        #pragma unroll
        for (int ks = 0; ks < 2; ks++) {
            int k0 = ks * 8 + tg;
            unsigned bf0[8], bf1[8];
            #pragma unroll
            for (int j = 0; j < 8; j++) {
                const float* p = Bs_ + (warp_n + j * 8 + grp) * 20 + k0;
                bf0[j] = __float_as_uint(p[0]);
                bf1[j] = __float_as_uint(p[4]);
            }
            #pragma unroll
            for (int i = 0; i < 4; i++) {
                const float* p = As_ + (warp_m + i * 16 + grp) * 20 + k0;
                unsigned a0 = __float_as_uint(p[0]);
                unsigned a2 = __float_as_uint(p[4]);
                unsigned a1 = __float_as_uint(p[160]);
                unsigned a3 = __float_as_uint(p[164]);
                #pragma unroll
                for (int j = 0; j < 8; j++)
                    mma_tf32(acc[i][j], a0, a1, a2, a3, bf0[j], bf1[j]);
            }
        }
    }

    // ---------------- fused epilogue ----------------
    float ga = g_scal[0], ba = g_scal[1];
    unsigned rowb[4][2][4];
    float nzv[4][2];
    int yv[4][2], xv_[4][2];
    #pragma unroll
    for (int i = 0; i < 4; i++)
        #pragma unroll
        for (int h = 0; h < 2; h++) {
            int m = warp_m + i * 16 + grp + h * 8;
            int y = y0 + (m >> 4), xg = x0 + (m & 15);
            yv[i][h] = y; xv_[i][h] = xg;
            nzv[i][h] = g_nT[((size_t)b * 256 + y) * 256 + xg];
            int ph = y & 1, pw = xg & 1;
            int r0 = (y - 1) >> 1, c0 = (xg - 1) >> 1;
            #pragma unroll
            for (int u = 0; u < 2; u++)
                #pragma unroll
                for (int v = 0; v < 2; v++) {
                    int cy = r0 + u, cx = c0 + v;
                    int cls = 19;
                    if ((unsigned)cy < 128u && (unsigned)cx < 128u)
                        cls = g_cls[((size_t)b << 14) + cy * 128 + cx];
                    rowb[i][h][u * 2 + v] =
                        (unsigned)(((((b * 20 + cls) * 2 + ph) * 2 + pw) * 2 + u) * 2 + v) * 256u;
                }
        }

    #pragma unroll 1
    for (int j = 0; j < 8; j++) {
        int co = (warp_n >> 1) + j * 4 + tg;
        float mean = g_mean[b * 128 + co];
        float rs = g_rstd[b * 128 + co];
        float nv = nvar[co];
        float cg = g_Cg[co], cb = g_Cb[co];
        #pragma unroll
        for (int i = 0; i < 4; i++)
            #pragma unroll
            for (int h = 0; h < 2; h++) {
                float gsp = acc[i][j][h * 2 + 0];
                float bsp = acc[i][j][h * 2 + 1];
                float ag = 0.f, ab = 0.f;
                #pragma unroll
                for (int k = 0; k < 4; k++) {
                    float2 gg = *(const float2*)&g_G4[rowb[i][h][k] + (unsigned)co * 2u];
                    ag += gg.x; ab += gg.y;
                }
                size_t idx = (((size_t)b * 128 + co) * 256 + yv[i][h]) * 256 + xv_[i][h];
                float xval = x[idx];
                float gf = ga * ag + (1.f - ga) * gsp + cg;
                float bf = ba * ab + (1.f - ba) * bsp + cb;
                float val = (xval + nzv[i][h] * nv - mean) * rs;
                out[idx] = fmaf(val, gf, val + bf);
            }
    }
}

// ----------------------------- launch -----------------------------
extern "C" void kernel_launch(void* const* d_in, const int* in_sizes, int n_in,
                              void* d_out, int out_size) {
    const float* x     = (const float*)d_in[0];
    const float* seg   = (const float*)d_in[1];
    const float* sc    = (const float*)d_in[2];
    const float* noise = (const float*)d_in[3];
    const float* nvar  = (const float*)d_in[4];
    const float* bg    = (const float*)d_in[5];
    const float* bb    = (const float*)d_in[6];
    const float* fcw   = (const float*)d_in[7];
    const float* fcb   = (const float*)d_in[8];
    const float* cgw   = (const float*)d_in[9];
    const float* cgb   = (const float*)d_in[10];
    const float* cbw   = (const float*)d_in[11];
    const float* cbb   = (const float*)d_in[12];
    const float* ssw   = (const float*)d_in[13];
    const float* ssb   = (const float*)d_in[14];
    const float* sgw   = (const float*)d_in[15];
    const float* sgb   = (const float*)d_in[16];
    const float* sbw   = (const float*)d_in[17];
    const float* sbb   = (const float*)d_in[18];
    float* out = (float*)d_out;

    cudaFuncSetAttribute(k_main_mma, cudaFuncAttributeMaxDynamicSharedMemorySize, SMEM_MAIN);

    k_scal<<<1, 128>>>(bg, bb, cgb, cbb, sgb, sbb);
    k_mu<<<160, 64>>>(sc, fcw, fcb);
    k_cls<<<512, 256>>>(seg);
    k_w1<<<86, 256>>>(ssw);
    k_w2<<<1152, 256>>>(sgw, sbw);
    k_ntr<<<dim3(8, 8, 8), dim3(32, 8)>>>(noise);
    k_stats<<<1024, 256>>>(x, nvar);
    k_lut1<<<160, 128>>>(cgw, cbw);
    k_lut2<<<160, 256>>>();
    k_actv<<<dim3(16, 64, 8), 256>>>(seg, ssb);
    k_main_mma<<<dim3(16, 32, 8), 256, SMEM_MAIN>>>(x, nvar, out);
}

// round 9
// speedup vs baseline: 1.9012x; 1.8955x over previous
#include <cuda_runtime.h>
#include <cstdint>
#include <math.h>

#define B_ 8
#define C_ 128
#define H_ 256
#define W_ 256
#define HW (H_*W_)
typedef unsigned long long ull;

// ----------------------------- device scratch -----------------------------
__device__ __align__(16) float g_actv[(size_t)B_*C_*HW];
__device__ float g_nT[(size_t)B_*HW];
__device__ float g_mean[B_*C_];
__device__ float g_rstd[B_*C_];
__device__ float g_mu[B_*20*64];
__device__ __align__(16) float g_G2[B_*20*9*C_*2];
__device__ __align__(16) float g_G4[B_*20*16*C_*2];
__device__ unsigned char g_cls[B_*128*128];
__device__ __align__(16) float g_B1[171*128];
__device__ __align__(16) float g_B2k[1152*256];   // [(ci*9+t)][n=co*2+sel]
__device__ float g_Cg[C_], g_Cb[C_], g_scal[2];

// ----------------------------- helpers -----------------------------
__device__ __forceinline__ ull fma2(ull a, ull b, ull c) {
    ull d;
    asm("fma.rn.f32x2 %0, %1, %2, %3;" : "=l"(d) : "l"(a), "l"(b), "l"(c));
    return d;
}
__device__ __forceinline__ ull pack2(float x, float y) {
    ull d;
    asm("mov.b64 %0, {%1, %2};" : "=l"(d) : "f"(x), "f"(y));
    return d;
}
__device__ __forceinline__ uint32_t smem_u32(const void* p) {
    uint32_t a;
    asm("{ .reg .u64 t; cvta.to.shared.u64 t, %1; cvt.u32.u64 %0, t; }" : "=r"(a) : "l"(p));
    return a;
}
__device__ __forceinline__ void cpa4(uint32_t d, const void* g, int sz) {
    asm volatile("cp.async.ca.shared.global [%0], [%1], 4, %2;"
                 :: "r"(d), "l"(g), "r"(sz) : "memory");
}
__device__ __forceinline__ void cpa16(uint32_t d, const void* g) {
    asm volatile("cp.async.ca.shared.global [%0], [%1], 16;"
                 :: "r"(d), "l"(g) : "memory");
}
__device__ __forceinline__ void cp_commit() {
    asm volatile("cp.async.commit_group;" ::: "memory");
}
__device__ __forceinline__ void cp_wait0() {
    asm volatile("cp.async.wait_group 0;" ::: "memory");
}

// ----------------------------- prep kernels -----------------------------
__global__ void k_scal(const float* bg, const float* bb, const float* cgb,
                       const float* cbb, const float* sgb, const float* sbb) {
    int co = threadIdx.x;
    float ga = 1.f / (1.f + expf(-bg[0]));
    float ba = 1.f / (1.f + expf(-bb[0]));
    g_Cg[co] = ga * cgb[co] + (1.f - ga) * sgb[co];
    g_Cb[co] = ba * cbb[co] + (1.f - ba) * sbb[co];
    if (co == 0) { g_scal[0] = ga; g_scal[1] = ba; }
}

__global__ void k_mu(const float* sc, const float* fcw, const float* fcb) {
    int bj = blockIdx.x;
    int b = bj / 20, j = bj - b * 20;
    int o = threadIdx.x;
    float r = 0.f;
    if (j < 19) {
        const float* s = sc + (b * 19 + j) * 64;
        const float* w = fcw + (j * 64 + o) * 64;
        #pragma unroll 8
        for (int i = 0; i < 64; i++) r = fmaf(s[i], w[i], r);
        r += fcb[j * 64 + o];
        r = fmaxf(r, 0.f);
    }
    g_mu[bj * 64 + o] = r;
}

__global__ void k_cls(const float* segmap) {
    int idx = blockIdx.x * 256 + threadIdx.x;
    if (idx >= B_ * 128 * 128) return;
    int b = idx >> 14, p = idx & 16383;
    int cls = 19;
    for (int j = 18; j >= 0; j--) {
        if (segmap[(((size_t)b * 19 + j) << 14) + p] > 0.f) { cls = j; break; }
    }
    g_cls[idx] = (unsigned char)cls;
}

__global__ void k_w1(const float* ssw) {
    int idx = blockIdx.x * 256 + threadIdx.x;
    if (idx >= 171 * 128) return;
    int k = idx >> 7, co = idx & 127;
    int j = k / 9, t = k - j * 9;
    g_B1[idx] = ssw[(co * 19 + j) * 9 + t];
}

// g_B2k[(ci*9+t)*256 + n]: contiguous per ci-chunk for bulk cp.async
__global__ void k_w2(const float* gw, const float* bw) {
    int idx = blockIdx.x * 256 + threadIdx.x;
    if (idx >= 1152 * 256) return;
    int k = idx >> 8, n = idx & 255;
    int ci = k / 9, t = k - ci * 9;
    int co = n >> 1;
    const float* w = (n & 1) ? bw : gw;
    g_B2k[idx] = w[(co * 128 + ci) * 9 + t];
}

__global__ void k_ntr(const float* noise) {
    __shared__ float t[32][33];
    int b = blockIdx.z;
    int w0 = blockIdx.x * 32, h0 = blockIdx.y * 32;
    int tx = threadIdx.x, ty = threadIdx.y;
    for (int i = 0; i < 32; i += 8)
        t[ty + i][tx] = noise[((size_t)b * 256 + w0 + ty + i) * 256 + h0 + tx];
    __syncthreads();
    for (int i = 0; i < 32; i += 8)
        g_nT[((size_t)b * 256 + h0 + ty + i) * 256 + w0 + tx] = t[tx][ty + i];
}

__global__ __launch_bounds__(256) void k_stats(const float* x, const float* nvar) {
    int bc = blockIdx.x;
    int b = bc >> 7, c = bc & 127;
    float nv = nvar[c];
    const float* xb = x + (size_t)bc * HW;
    const float* nb = g_nT + (size_t)b * HW;
    float s = 0.f, q = 0.f;
    for (int i = threadIdx.x; i < HW; i += 256) {
        float v = xb[i] + nb[i] * nv;
        s += v; q = fmaf(v, v, q);
    }
    __shared__ float ss[8], sq[8];
    #pragma unroll
    for (int o = 16; o; o >>= 1) {
        s += __shfl_xor_sync(0xffffffffu, s, o);
        q += __shfl_xor_sync(0xffffffffu, q, o);
    }
    int wid = threadIdx.x >> 5, lane = threadIdx.x & 31;
    if (!lane) { ss[wid] = s; sq[wid] = q; }
    __syncthreads();
    if (threadIdx.x == 0) {
        float S = 0.f, Q = 0.f;
        #pragma unroll
        for (int k = 0; k < 8; k++) { S += ss[k]; Q += sq[k]; }
        float m = S * (1.f / HW);
        float var = Q * (1.f / HW) - m * m;
        g_mean[bc] = m;
        g_rstd[bc] = rsqrtf(var + 1e-5f);
    }
}

__global__ __launch_bounds__(128) void k_lut1(const float* gw, const float* bw) {
    int bj = blockIdx.x;
    int co = threadIdx.x;
    __shared__ float mu_s[64];
    if (co < 64) mu_s[co] = g_mu[bj * 64 + co];
    __syncthreads();
    for (int t = 0; t < 9; t++) {
        float sg = 0.f, sb = 0.f;
        #pragma unroll 8
        for (int ci = 0; ci < 64; ci++) {
            float m = mu_s[ci];
            sg = fmaf(gw[(co * 64 + ci) * 9 + t], m, sg);
            sb = fmaf(bw[(co * 64 + ci) * 9 + t], m, sb);
        }
        int o = ((bj * 9 + t) * 128 + co) * 2;
        g_G2[o] = sg; g_G2[o + 1] = sb;
    }
}

__global__ __launch_bounds__(256) void k_lut2() {
    int bj = blockIdx.x;
    int n = threadIdx.x;
    const float* G = g_G2 + (size_t)bj * 9 * 256;
    float* O = g_G4 + (size_t)bj * 16 * 256;
    for (int ph = 0; ph < 2; ph++)
    for (int pw = 0; pw < 2; pw++)
    for (int u = 0; u < 2; u++)
    for (int v = 0; v < 2; v++) {
        int rlo = (u == 0) ? 0 : (ph == 0 ? 1 : 2);
        int rhi = (u == 0) ? (ph == 0 ? 0 : 1) : 2;
        int clo = (v == 0) ? 0 : (pw == 0 ? 1 : 2);
        int chi = (v == 0) ? (pw == 0 ? 0 : 1) : 2;
        float s = 0.f;
        for (int dy = rlo; dy <= rhi; dy++)
            for (int dx = clo; dx <= chi; dx++)
                s += G[(dy * 3 + dx) * 256 + n];
        O[(((ph * 2 + pw) * 2 + u) * 2 + v) * 256 + n] = s;
    }
}

// ----------------------------- stage A: actv conv (19 -> 128) -----------------------------
__global__ __launch_bounds__(256, 2) void k_actv(const float* segmap, const float* ssb) {
    __shared__ float Sh[19][4][10];
    __shared__ __align__(16) float Bsj[9][128];
    int b = blockIdx.z;
    int x0 = blockIdx.x * 16, y0 = blockIdx.y * 4;
    int tid = threadIdx.x;
    int tx = tid & 15, ty = tid >> 4;
    int r = ty >> 2, c = (ty & 3) * 4;

    int hb = (y0 >> 1) - 1, cbh = (x0 >> 1) - 1;
    for (int idx = tid; idx < 19 * 40; idx += 256) {
        int j = idx / 40, pos = idx - j * 40;
        int hr = pos / 10, hc = pos - hr * 10;
        int gy = hb + hr, gx = cbh + hc;
        float v = 0.f;
        if ((unsigned)gy < 128u && (unsigned)gx < 128u)
            v = segmap[(((size_t)b * 19 + j) << 14) + gy * 128 + gx];
        Sh[j][hr][hc] = v;
    }

    int hrw[3], hcc[6];
    #pragma unroll
    for (int k = 0; k < 3; k++) hrw[k] = ((r + k - 1) >> 1) + 1;
    #pragma unroll
    for (int k = 0; k < 6; k++) hcc[k] = ((c + k - 1) >> 1) + 1;

    ull acc[4][4];
    #pragma unroll
    for (int p = 0; p < 4; p++)
        #pragma unroll
        for (int q = 0; q < 4; q++) acc[p][q] = 0ull;

    for (int j = 0; j < 19; j++) {
        __syncthreads();
        for (int idx = tid; idx < 1152; idx += 256)
            ((float*)Bsj)[idx] = g_B1[j * 1152 + idx];
        __syncthreads();
        #pragma unroll
        for (int t = 0; t < 9; t++) {
            const int tdy = t / 3, tdx = t - tdy * 3;
            ull Ap[4];
            #pragma unroll
            for (int i = 0; i < 4; i++) {
                float a = Sh[j][hrw[tdy]][hcc[tdx + i]];
                Ap[i] = pack2(a, a);
            }
            ulonglong2 b0 = *(const ulonglong2*)&Bsj[t][tx * 4];
            ulonglong2 b1 = *(const ulonglong2*)&Bsj[t][tx * 4 + 64];
            #pragma unroll
            for (int p = 0; p < 4; p++) {
                acc[p][0] = fma2(Ap[p], b0.x, acc[p][0]);
                acc[p][1] = fma2(Ap[p], b0.y, acc[p][1]);
                acc[p][2] = fma2(Ap[p], b1.x, acc[p][2]);
                acc[p][3] = fma2(Ap[p], b1.y, acc[p][3]);
            }
        }
    }

    int y = y0 + r, xg0 = x0 + c;
    #pragma unroll
    for (int q = 0; q < 4; q++) {
        int co0 = (q < 2) ? (tx * 4 + q * 2) : (tx * 4 + 64 + (q - 2) * 2);
        #pragma unroll
        for (int h2 = 0; h2 < 2; h2++) {
            int co = co0 + h2;
            float bias = ssb[co];
            float4 o;
            float* op = (float*)&o;
            #pragma unroll
            for (int p = 0; p < 4; p++) {
                ull v = acc[p][q];
                unsigned w32 = h2 ? (unsigned)(v >> 32) : (unsigned)v;
                op[p] = fmaxf(__uint_as_float(w32) + bias, 0.f);
            }
            *(float4*)&g_actv[(((size_t)b * 128 + co) * 256 + y) * 256 + xg0] = o;
        }
    }
}

// ------------- stage B: direct conv, register-stencil, cp.async dbuf -------------
// CTA: 16x8 px, N=256 (gamma/beta interleaved). 512 threads.
// Thread: row r = tid>>6, xoff = ((tid>>5)&1)*8 (8 consecutive x), co = (tid&31)*4 .. +3.
// K chunks: 4 ci x 9 taps. smem: A halo [2][4ci][10][20], B [2][4ci*9][256].
#define A_FL 800            // per buf: 4*10*20
#define B_FL 9216           // per buf: 36*256
#define SMEM_MAIN ((2*A_FL + 2*B_FL) * 4)

__global__ __launch_bounds__(512, 1) void k_main_d2(const float* __restrict__ x,
                                                    const float* __restrict__ nvar,
                                                    float* __restrict__ out) {
    extern __shared__ float sm[];
    float* Asm = sm;                 // [2][A_FL]
    float* Bsm = sm + 2 * A_FL;      // [2][B_FL]
    uint32_t As_u = smem_u32(Asm), Bs_u = smem_u32(Bsm);

    int tid = threadIdx.x;
    int np4 = tid & 31;
    int r = tid >> 6;
    int xoff = ((tid >> 5) & 1) * 8;
    int b = blockIdx.z;
    int x0 = blockIdx.x * 16, y0 = blockIdx.y * 8;

    ull acc[8][4];
    #pragma unroll
    for (int p = 0; p < 8; p++)
        #pragma unroll
        for (int j = 0; j < 4; j++) acc[p][j] = 0ull;

    auto issue = [&](int ch, int buf) {
        // A halo: 4 ci x 10 rows x 18 cols (pitch 20)
        int ci0 = ch * 4;
        #pragma unroll
        for (int k = 0; k < 2; k++) {
            int idx = tid + k * 512;
            if (idx < 720) {
                int ci = idx / 180, rem = idx - ci * 180;
                int rr = rem / 18, cc = rem - rr * 18;
                int gy = y0 - 1 + rr, gx = x0 - 1 + cc;
                bool ok = ((unsigned)gy < 256u) && ((unsigned)gx < 256u);
                const float* src = &g_actv[(((size_t)b * 128 + ci0 + ci) * 256
                                            + (ok ? gy : 0)) * 256 + (ok ? gx : 0)];
                cpa4(As_u + (uint32_t)(buf * A_FL + ci * 200 + rr * 20 + cc) * 4u,
                     src, ok ? 4 : 0);
            }
        }
        // B: 2304 float4 contiguous
        const float4* srcB = (const float4*)(g_B2k + (size_t)ch * B_FL);
        uint32_t dB = Bs_u + (uint32_t)(buf * B_FL) * 4u;
        #pragma unroll
        for (int k = 0; k < 5; k++) {
            int idx = tid + k * 512;
            if (idx < 2304) cpa16(dB + (uint32_t)idx * 16u, srcB + idx);
        }
        cp_commit();
    };

    issue(0, 0);
    #pragma unroll 1
    for (int ch = 0; ch < 32; ch++) {
        cp_wait0();
        __syncthreads();
        if (ch + 1 < 32) issue(ch + 1, (ch + 1) & 1);
        const float* Asb = Asm + (ch & 1) * A_FL;
        const float* Bsb = Bsm + (ch & 1) * B_FL;
        #pragma unroll
        for (int ci = 0; ci < 4; ci++) {
            #pragma unroll
            for (int dy = 0; dy < 3; dy++) {
                const float* ap = Asb + ci * 200 + (r + dy) * 20 + xoff;
                float4 A0 = *(const float4*)ap;
                float4 A1 = *(const float4*)(ap + 4);
                float2 A2 = *(const float2*)(ap + 8);
                ull a2[10];
                a2[0] = pack2(A0.x, A0.x); a2[1] = pack2(A0.y, A0.y);
                a2[2] = pack2(A0.z, A0.z); a2[3] = pack2(A0.w, A0.w);
                a2[4] = pack2(A1.x, A1.x); a2[5] = pack2(A1.y, A1.y);
                a2[6] = pack2(A1.z, A1.z); a2[7] = pack2(A1.w, A1.w);
                a2[8] = pack2(A2.x, A2.x); a2[9] = pack2(A2.y, A2.y);
                const float* bp = Bsb + (ci * 9 + dy * 3) * 256 + np4 * 8;
                ulonglong2 b0a = *(const ulonglong2*)bp;
                ulonglong2 b0b = *(const ulonglong2*)(bp + 4);
                ulonglong2 b1a = *(const ulonglong2*)(bp + 256);
                ulonglong2 b1b = *(const ulonglong2*)(bp + 260);
                ulonglong2 b2a = *(const ulonglong2*)(bp + 512);
                ulonglong2 b2b = *(const ulonglong2*)(bp + 516);
                #pragma unroll
                for (int px = 0; px < 8; px++) {
                    acc[px][0] = fma2(a2[px], b0a.x, acc[px][0]);
                    acc[px][1] = fma2(a2[px], b0a.y, acc[px][1]);
                    acc[px][2] = fma2(a2[px], b0b.x, acc[px][2]);
                    acc[px][3] = fma2(a2[px], b0b.y, acc[px][3]);
                    acc[px][0] = fma2(a2[px + 1], b1a.x, acc[px][0]);
                    acc[px][1] = fma2(a2[px + 1], b1a.y, acc[px][1]);
                    acc[px][2] = fma2(a2[px + 1], b1b.x, acc[px][2]);
                    acc[px][3] = fma2(a2[px + 1], b1b.y, acc[px][3]);
                    acc[px][0] = fma2(a2[px + 2], b2a.x, acc[px][0]);
                    acc[px][1] = fma2(a2[px + 2], b2a.y, acc[px][1]);
                    acc[px][2] = fma2(a2[px + 2], b2b.x, acc[px][2]);
                    acc[px][3] = fma2(a2[px + 2], b2b.y, acc[px][3]);
                }
            }
        }
    }

    // ---------------- fused epilogue ----------------
    float ga = g_scal[0], ba = g_scal[1];
    int y = y0 + r, xb = x0 + xoff;
    float4 nz0 = *(const float4*)&g_nT[((size_t)b * 256 + y) * 256 + xb];
    float4 nz1 = *(const float4*)&g_nT[((size_t)b * 256 + y) * 256 + xb + 4];
    float nzv[8] = { nz0.x, nz0.y, nz0.z, nz0.w, nz1.x, nz1.y, nz1.z, nz1.w };

    int ph = y & 1, r0 = (y - 1) >> 1;
    unsigned rowb[8][4];
    #pragma unroll
    for (int px = 0; px < 8; px++) {
        int xg = xb + px;
        int pw = xg & 1, c0 = (xg - 1) >> 1;
        #pragma unroll
        for (int u = 0; u < 2; u++)
            #pragma unroll
            for (int v = 0; v < 2; v++) {
                int cy = r0 + u, cx = c0 + v;
                int cls = 19;
                if ((unsigned)cy < 128u && (unsigned)cx < 128u)
                    cls = g_cls[((size_t)b << 14) + cy * 128 + cx];
                rowb[px][u * 2 + v] =
                    (unsigned)(((((b * 20 + cls) * 2 + ph) * 2 + pw) * 2 + u) * 2 + v) * 256u;
            }
    }
    float4 m4 = *(const float4*)&g_mean[b * 128 + np4 * 4];
    float4 rs4 = *(const float4*)&g_rstd[b * 128 + np4 * 4];
    float4 nv4 = *(const float4*)&nvar[np4 * 4];
    float4 cg4 = *(const float4*)&g_Cg[np4 * 4];
    float4 cb4 = *(const float4*)&g_Cb[np4 * 4];
    float mA[4] = { m4.x, m4.y, m4.z, m4.w };
    float rsA[4] = { rs4.x, rs4.y, rs4.z, rs4.w };
    float nvA[4] = { nv4.x, nv4.y, nv4.z, nv4.w };
    float cgA[4] = { cg4.x, cg4.y, cg4.z, cg4.w };
    float cbA[4] = { cb4.x, cb4.y, cb4.z, cb4.w };

    #pragma unroll
    for (int j = 0; j < 4; j++) {
        int co = np4 * 4 + j;
        size_t base = (((size_t)b * 128 + co) * 256 + y) * 256 + xb;
        float4 xlo = *(const float4*)&x[base];
        float4 xhi = *(const float4*)&x[base + 4];
        float xvA[8] = { xlo.x, xlo.y, xlo.z, xlo.w, xhi.x, xhi.y, xhi.z, xhi.w };
        float o[8];
        #pragma unroll
        for (int px = 0; px < 8; px++) {
            ull v = acc[px][j];
            float gsp = __uint_as_float((unsigned)v);
            float bsp = __uint_as_float((unsigned)(v >> 32));
            float ag = 0.f, ab = 0.f;
            #pragma unroll
            for (int k = 0; k < 4; k++) {
                float2 gg = *(const float2*)&g_G4[rowb[px][k] + (unsigned)co * 2u];
                ag += gg.x; ab += gg.y;
            }
            float gf = ga * ag + (1.f - ga) * gsp + cgA[j];
            float bf = ba * ab + (1.f - ba) * bsp + cbA[j];
            float val = (xvA[px] + nzv[px] * nvA[j] - mA[j]) * rsA[j];
            o[px] = fmaf(val, gf, val + bf);
        }
        *(float4*)&out[base] = make_float4(o[0], o[1], o[2], o[3]);
        *(float4*)&out[base + 4] = make_float4(o[4], o[5], o[6], o[7]);
    }
}

// ----------------------------- launch -----------------------------
extern "C" void kernel_launch(void* const* d_in, const int* in_sizes, int n_in,
                              void* d_out, int out_size) {
    const float* x     = (const float*)d_in[0];
    const float* seg   = (const float*)d_in[1];
    const float* sc    = (const float*)d_in[2];
    const float* noise = (const float*)d_in[3];
    const float* nvar  = (const float*)d_in[4];
    const float* bg    = (const float*)d_in[5];
    const float* bb    = (const float*)d_in[6];
    const float* fcw   = (const float*)d_in[7];
    const float* fcb   = (const float*)d_in[8];
    const float* cgw   = (const float*)d_in[9];
    const float* cgb   = (const float*)d_in[10];
    const float* cbw   = (const float*)d_in[11];
    const float* cbb   = (const float*)d_in[12];
    const float* ssw   = (const float*)d_in[13];
    const float* ssb   = (const float*)d_in[14];
    const float* sgw   = (const float*)d_in[15];
    const float* sgb   = (const float*)d_in[16];
    const float* sbw   = (const float*)d_in[17];
    const float* sbb   = (const float*)d_in[18];
    float* out = (float*)d_out;

    cudaFuncSetAttribute(k_main_d2, cudaFuncAttributeMaxDynamicSharedMemorySize, SMEM_MAIN);

    k_scal<<<1, 128>>>(bg, bb, cgb, cbb, sgb, sbb);
    k_mu<<<160, 64>>>(sc, fcw, fcb);
    k_cls<<<512, 256>>>(seg);
    k_w1<<<86, 256>>>(ssw);
    k_w2<<<1152, 256>>>(sgw, sbw);
    k_ntr<<<dim3(8, 8, 8), dim3(32, 8)>>>(noise);
    k_stats<<<1024, 256>>>(x, nvar);
    k_lut1<<<160, 128>>>(cgw, cbw);
    k_lut2<<<160, 256>>>();
    k_actv<<<dim3(16, 64, 8), 256>>>(seg, ssb);
    k_main_d2<<<dim3(16, 32, 8), 512, SMEM_MAIN>>>(x, nvar, out);
}

// round 10
// speedup vs baseline: 1.9213x; 1.0106x over previous
#include <cuda_runtime.h>
#include <cstdint>
#include <math.h>

#define B_ 8
#define C_ 128
#define H_ 256
#define W_ 256
#define HW (H_*W_)
typedef unsigned long long ull;

// ----------------------------- device scratch -----------------------------
__device__ __align__(16) float g_actv[(size_t)B_*C_*HW];
__device__ float g_nT[(size_t)B_*HW];
__device__ float g_mean[B_*C_];
__device__ float g_rstd[B_*C_];
__device__ float g_mu[B_*20*64];
__device__ __align__(16) float g_G2[B_*20*9*C_*2];
__device__ __align__(16) float g_G4[B_*20*16*C_*2];
__device__ unsigned char g_cls[B_*128*128];
__device__ __align__(16) float g_B1[171*128];
// [(ci*9+t)] x [p(4)][g(32)][{gamma,beta}]  (conflict-free LDS.64 fragments)
__device__ __align__(16) float g_B2k[1152*256];
__device__ float g_Cg[C_], g_Cb[C_], g_scal[2];

// ----------------------------- helpers -----------------------------
__device__ __forceinline__ ull fma2(ull a, ull b, ull c) {
    ull d;
    asm("fma.rn.f32x2 %0, %1, %2, %3;" : "=l"(d) : "l"(a), "l"(b), "l"(c));
    return d;
}
__device__ __forceinline__ ull pack2(float x, float y) {
    ull d;
    asm("mov.b64 %0, {%1, %2};" : "=l"(d) : "f"(x), "f"(y));
    return d;
}
__device__ __forceinline__ uint32_t smem_u32(const void* p) {
    uint32_t a;
    asm("{ .reg .u64 t; cvta.to.shared.u64 t, %1; cvt.u32.u64 %0, t; }" : "=r"(a) : "l"(p));
    return a;
}
__device__ __forceinline__ void cpa4(uint32_t d, const void* g, int sz) {
    asm volatile("cp.async.ca.shared.global [%0], [%1], 4, %2;"
                 :: "r"(d), "l"(g), "r"(sz) : "memory");
}
__device__ __forceinline__ void cpa16(uint32_t d, const void* g) {
    asm volatile("cp.async.ca.shared.global [%0], [%1], 16;"
                 :: "r"(d), "l"(g) : "memory");
}
__device__ __forceinline__ void cp_commit() {
    asm volatile("cp.async.commit_group;" ::: "memory");
}
__device__ __forceinline__ void cp_wait0() {
    asm volatile("cp.async.wait_group 0;" ::: "memory");
}

// ----------------------------- merged prep (launch #1) -----------------------------
// blocks: [0] scal | [1,41) mu | [41,553) cls | [553,639) w1 | [639,1791) w2 | [1791,2303) ntr
__global__ __launch_bounds__(256) void k_prep(
    const float* bg, const float* bb, const float* cgb, const float* cbb,
    const float* sgb, const float* sbb,
    const float* sc, const float* fcw, const float* fcb,
    const float* segmap, const float* ssw,
    const float* gw, const float* bw, const float* noise) {
    __shared__ float tsh[32][33];
    int bk = blockIdx.x;
    int tid = threadIdx.x;

    if (bk == 0) {
        if (tid < 128) {
            int co = tid;
            float ga = 1.f / (1.f + expf(-bg[0]));
            float ba = 1.f / (1.f + expf(-bb[0]));
            g_Cg[co] = ga * cgb[co] + (1.f - ga) * sgb[co];
            g_Cb[co] = ba * cbb[co] + (1.f - ba) * sbb[co];
            if (co == 0) { g_scal[0] = ga; g_scal[1] = ba; }
        }
    } else if (bk < 41) {
        int bj = (bk - 1) * 4 + (tid >> 6);   // 0..159
        int o = tid & 63;
        int b = bj / 20, j = bj - b * 20;
        float r = 0.f;
        if (j < 19) {
            const float* s = sc + (b * 19 + j) * 64;
            const float* w = fcw + (j * 64 + o) * 64;
            #pragma unroll 8
            for (int i = 0; i < 64; i++) r = fmaf(s[i], w[i], r);
            r += fcb[j * 64 + o];
            r = fmaxf(r, 0.f);
        }
        g_mu[bj * 64 + o] = r;
    } else if (bk < 553) {
        int idx = (bk - 41) * 256 + tid;
        int b = idx >> 14, p = idx & 16383;
        int cls = 19;
        for (int j = 18; j >= 0; j--) {
            if (segmap[(((size_t)b * 19 + j) << 14) + p] > 0.f) { cls = j; break; }
        }
        g_cls[idx] = (unsigned char)cls;
    } else if (bk < 639) {
        int idx = (bk - 553) * 256 + tid;
        if (idx < 171 * 128) {
            int k = idx >> 7, co = idx & 127;
            int j = k / 9, t = k - j * 9;
            g_B1[idx] = ssw[(co * 19 + j) * 9 + t];
        }
    } else if (bk < 1791) {
        int idx = (bk - 639) * 256 + tid;      // 1152*256
        int k = idx >> 8, n = idx & 255;
        int ci = k / 9, t = k - ci * 9;
        int co = n >> 1;
        // new layout: row k, slot = p*64 + g*2 + sel, where g=n>>3, p=(n>>1)&3, sel=n&1
        int g = n >> 3, p = (n >> 1) & 3, sel = n & 1;
        const float* w = sel ? bw : gw;
        g_B2k[k * 256 + p * 64 + g * 2 + sel] = w[(co * 128 + ci) * 9 + t];
    } else {
        int bl = bk - 1791;                    // 512 tiles: b(8) x 64
        int b = bl >> 6, rem = bl & 63;
        int w0 = (rem & 7) * 32, h0 = (rem >> 3) * 32;
        int tx = tid & 31, ty = tid >> 5;      // 32 x 8
        for (int i = 0; i < 32; i += 8)
            tsh[ty + i][tx] = noise[((size_t)b * 256 + w0 + ty + i) * 256 + h0 + tx];
        __syncthreads();
        for (int i = 0; i < 32; i += 8)
            g_nT[((size_t)b * 256 + h0 + ty + i) * 256 + w0 + tx] = tsh[tx][ty + i];
    }
}

// ----------------------------- launch #2: per-(b,c) stats -----------------------------
__global__ __launch_bounds__(256) void k_stats(const float* x, const float* nvar) {
    int bc = blockIdx.x;
    int b = bc >> 7, c = bc & 127;
    float nv = nvar[c];
    const float* xb = x + (size_t)bc * HW;
    const float* nb = g_nT + (size_t)b * HW;
    float s = 0.f, q = 0.f;
    for (int i = threadIdx.x; i < HW; i += 256) {
        float v = xb[i] + nb[i] * nv;
        s += v; q = fmaf(v, v, q);
    }
    __shared__ float ss[8], sq[8];
    #pragma unroll
    for (int o = 16; o; o >>= 1) {
        s += __shfl_xor_sync(0xffffffffu, s, o);
        q += __shfl_xor_sync(0xffffffffu, q, o);
    }
    int wid = threadIdx.x >> 5, lane = threadIdx.x & 31;
    if (!lane) { ss[wid] = s; sq[wid] = q; }
    __syncthreads();
    if (threadIdx.x == 0) {
        float S = 0.f, Q = 0.f;
        #pragma unroll
        for (int k = 0; k < 8; k++) { S += ss[k]; Q += sq[k]; }
        float m = S * (1.f / HW);
        float var = Q * (1.f / HW) - m * m;
        g_mean[bc] = m;
        g_rstd[bc] = rsqrtf(var + 1e-5f);
    }
}

// ----------------------------- launch #3/#4: LUTs -----------------------------
__global__ __launch_bounds__(128) void k_lut1(const float* gw, const float* bw) {
    int bj = blockIdx.x;
    int co = threadIdx.x;
    __shared__ float mu_s[64];
    if (co < 64) mu_s[co] = g_mu[bj * 64 + co];
    __syncthreads();
    for (int t = 0; t < 9; t++) {
        float sg = 0.f, sb = 0.f;
        #pragma unroll 8
        for (int ci = 0; ci < 64; ci++) {
            float m = mu_s[ci];
            sg = fmaf(gw[(co * 64 + ci) * 9 + t], m, sg);
            sb = fmaf(bw[(co * 64 + ci) * 9 + t], m, sb);
        }
        int o = ((bj * 9 + t) * 128 + co) * 2;
        g_G2[o] = sg; g_G2[o + 1] = sb;
    }
}

__global__ __launch_bounds__(256) void k_lut2() {
    int bj = blockIdx.x;
    int n = threadIdx.x;
    const float* G = g_G2 + (size_t)bj * 9 * 256;
    float* O = g_G4 + (size_t)bj * 16 * 256;
    for (int ph = 0; ph < 2; ph++)
    for (int pw = 0; pw < 2; pw++)
    for (int u = 0; u < 2; u++)
    for (int v = 0; v < 2; v++) {
        int rlo = (u == 0) ? 0 : (ph == 0 ? 1 : 2);
        int rhi = (u == 0) ? (ph == 0 ? 0 : 1) : 2;
        int clo = (v == 0) ? 0 : (pw == 0 ? 1 : 2);
        int chi = (v == 0) ? (pw == 0 ? 0 : 1) : 2;
        float s = 0.f;
        for (int dy = rlo; dy <= rhi; dy++)
            for (int dx = clo; dx <= chi; dx++)
                s += G[(dy * 3 + dx) * 256 + n];
        O[(((ph * 2 + pw) * 2 + u) * 2 + v) * 256 + n] = s;
    }
}

// ----------------------------- launch #5: actv conv (19 -> 128) -----------------------------
__global__ __launch_bounds__(256, 2) void k_actv(const float* segmap, const float* ssb) {
    __shared__ float Sh[19][4][10];
    __shared__ __align__(16) float Bsj[9][128];
    int b = blockIdx.z;
    int x0 = blockIdx.x * 16, y0 = blockIdx.y * 4;
    int tid = threadIdx.x;
    int tx = tid & 15, ty = tid >> 4;
    int r = ty >> 2, c = (ty & 3) * 4;

    int hb = (y0 >> 1) - 1, cbh = (x0 >> 1) - 1;
    for (int idx = tid; idx < 19 * 40; idx += 256) {
        int j = idx / 40, pos = idx - j * 40;
        int hr = pos / 10, hc = pos - hr * 10;
        int gy = hb + hr, gx = cbh + hc;
        float v = 0.f;
        if ((unsigned)gy < 128u && (unsigned)gx < 128u)
            v = segmap[(((size_t)b * 19 + j) << 14) + gy * 128 + gx];
        Sh[j][hr][hc] = v;
    }

    int hrw[3], hcc[6];
    #pragma unroll
    for (int k = 0; k < 3; k++) hrw[k] = ((r + k - 1) >> 1) + 1;
    #pragma unroll
    for (int k = 0; k < 6; k++) hcc[k] = ((c + k - 1) >> 1) + 1;

    ull acc[4][4];
    #pragma unroll
    for (int p = 0; p < 4; p++)
        #pragma unroll
        for (int q = 0; q < 4; q++) acc[p][q] = 0ull;

    for (int j = 0; j < 19; j++) {
        __syncthreads();
        for (int idx = tid; idx < 1152; idx += 256)
            ((float*)Bsj)[idx] = g_B1[j * 1152 + idx];
        __syncthreads();
        #pragma unroll
        for (int t = 0; t < 9; t++) {
            const int tdy = t / 3, tdx = t - tdy * 3;
            ull Ap[4];
            #pragma unroll
            for (int i = 0; i < 4; i++) {
                float a = Sh[j][hrw[tdy]][hcc[tdx + i]];
                Ap[i] = pack2(a, a);
            }
            ulonglong2 b0 = *(const ulonglong2*)&Bsj[t][tx * 4];
            ulonglong2 b1 = *(const ulonglong2*)&Bsj[t][tx * 4 + 64];
            #pragma unroll
            for (int p = 0; p < 4; p++) {
                acc[p][0] = fma2(Ap[p], b0.x, acc[p][0]);
                acc[p][1] = fma2(Ap[p], b0.y, acc[p][1]);
                acc[p][2] = fma2(Ap[p], b1.x, acc[p][2]);
                acc[p][3] = fma2(Ap[p], b1.y, acc[p][3]);
            }
        }
    }

    int y = y0 + r, xg0 = x0 + c;
    #pragma unroll
    for (int q = 0; q < 4; q++) {
        int co0 = (q < 2) ? (tx * 4 + q * 2) : (tx * 4 + 64 + (q - 2) * 2);
        #pragma unroll
        for (int h2 = 0; h2 < 2; h2++) {
            int co = co0 + h2;
            float bias = ssb[co];
            float4 o;
            float* op = (float*)&o;
            #pragma unroll
            for (int p = 0; p < 4; p++) {
                ull v = acc[p][q];
                unsigned w32 = h2 ? (unsigned)(v >> 32) : (unsigned)v;
                op[p] = fmaxf(__uint_as_float(w32) + bias, 0.f);
            }
            *(float4*)&g_actv[(((size_t)b * 128 + co) * 256 + y) * 256 + xg0] = o;
        }
    }
}

// ------------- launch #6: direct conv, conflict-free LDS.64 B fragments -------------
#define A_FL 800            // per buf: 4*10*20
#define B_FL 9216           // per buf: 36*256
#define SMEM_MAIN ((2*A_FL + 2*B_FL) * 4)

__global__ __launch_bounds__(512, 1) void k_main_d2(const float* __restrict__ x,
                                                    const float* __restrict__ nvar,
                                                    float* __restrict__ out) {
    extern __shared__ float sm[];
    float* Asm = sm;                 // [2][A_FL]
    float* Bsm = sm + 2 * A_FL;      // [2][B_FL]
    uint32_t As_u = smem_u32(Asm), Bs_u = smem_u32(Bsm);

    int tid = threadIdx.x;
    int np4 = tid & 31;
    int r = tid >> 6;
    int xoff = ((tid >> 5) & 1) * 8;
    int b = blockIdx.z;
    int x0 = blockIdx.x * 16, y0 = blockIdx.y * 8;

    ull acc[8][4];
    #pragma unroll
    for (int p = 0; p < 8; p++)
        #pragma unroll
        for (int j = 0; j < 4; j++) acc[p][j] = 0ull;

    auto issue = [&](int ch, int buf) {
        int ci0 = ch * 4;
        #pragma unroll
        for (int k = 0; k < 2; k++) {
            int idx = tid + k * 512;
            if (idx < 720) {
                int ci = idx / 180, rem = idx - ci * 180;
                int rr = rem / 18, cc = rem - rr * 18;
                int gy = y0 - 1 + rr, gx = x0 - 1 + cc;
                bool ok = ((unsigned)gy < 256u) && ((unsigned)gx < 256u);
                const float* src = &g_actv[(((size_t)b * 128 + ci0 + ci) * 256
                                            + (ok ? gy : 0)) * 256 + (ok ? gx : 0)];
                cpa4(As_u + (uint32_t)(buf * A_FL + ci * 200 + rr * 20 + cc) * 4u,
                     src, ok ? 4 : 0);
            }
        }
        const float4* srcB = (const float4*)(g_B2k + (size_t)ch * B_FL);
        uint32_t dB = Bs_u + (uint32_t)(buf * B_FL) * 4u;
        #pragma unroll
        for (int k = 0; k < 5; k++) {
            int idx = tid + k * 512;
            if (idx < 2304) cpa16(dB + (uint32_t)idx * 16u, srcB + idx);
        }
        cp_commit();
    };

    issue(0, 0);
    #pragma unroll 1
    for (int ch = 0; ch < 32; ch++) {
        cp_wait0();
        __syncthreads();
        if (ch + 1 < 32) issue(ch + 1, (ch + 1) & 1);
        const float* Asb = Asm + (ch & 1) * A_FL;
        const float* Bsb = Bsm + (ch & 1) * B_FL;
        #pragma unroll
        for (int ci = 0; ci < 4; ci++) {
            #pragma unroll
            for (int dy = 0; dy < 3; dy++) {
                const float* ap = Asb + ci * 200 + (r + dy) * 20 + xoff;
                float4 A0 = *(const float4*)ap;
                float4 A1 = *(const float4*)(ap + 4);
                float2 A2 = *(const float2*)(ap + 8);
                ull a2[10];
                a2[0] = pack2(A0.x, A0.x); a2[1] = pack2(A0.y, A0.y);
                a2[2] = pack2(A0.z, A0.z); a2[3] = pack2(A0.w, A0.w);
                a2[4] = pack2(A1.x, A1.x); a2[5] = pack2(A1.y, A1.y);
                a2[6] = pack2(A1.z, A1.z); a2[7] = pack2(A1.w, A1.w);
                a2[8] = pack2(A2.x, A2.x); a2[9] = pack2(A2.y, A2.y);
                // conflict-free: lane np4 reads 8B at stride 8B (contiguous 256B per p-slot)
                const float* bp = Bsb + (ci * 9 + dy * 3) * 256 + np4 * 2;
                ull Bv[3][4];
                #pragma unroll
                for (int dx = 0; dx < 3; dx++)
                    #pragma unroll
                    for (int p = 0; p < 4; p++)
                        Bv[dx][p] = *(const ull*)(bp + dx * 256 + p * 64);
                #pragma unroll
                for (int px = 0; px < 8; px++) {
                    #pragma unroll
                    for (int dx = 0; dx < 3; dx++) {
                        acc[px][0] = fma2(a2[px + dx], Bv[dx][0], acc[px][0]);
                        acc[px][1] = fma2(a2[px + dx], Bv[dx][1], acc[px][1]);
                        acc[px][2] = fma2(a2[px + dx], Bv[dx][2], acc[px][2]);
                        acc[px][3] = fma2(a2[px + dx], Bv[dx][3], acc[px][3]);
                    }
                }
            }
        }
    }

    // ---------------- fused epilogue ----------------
    float ga = g_scal[0], ba = g_scal[1];
    int y = y0 + r, xb = x0 + xoff;
    float4 nz0 = *(const float4*)&g_nT[((size_t)b * 256 + y) * 256 + xb];
    float4 nz1 = *(const float4*)&g_nT[((size_t)b * 256 + y) * 256 + xb + 4];
    float nzv[8] = { nz0.x, nz0.y, nz0.z, nz0.w, nz1.x, nz1.y, nz1.z, nz1.w };

    int ph = y & 1, r0 = (y - 1) >> 1;
    unsigned rowb[8][4];
    #pragma unroll
    for (int px = 0; px < 8; px++) {
        int xg = xb + px;
        int pw = xg & 1, c0 = (xg - 1) >> 1;
        #pragma unroll
        for (int u = 0; u < 2; u++)
            #pragma unroll
            for (int v = 0; v < 2; v++) {
                int cy = r0 + u, cx = c0 + v;
                int cls = 19;
                if ((unsigned)cy < 128u && (unsigned)cx < 128u)
                    cls = g_cls[((size_t)b << 14) + cy * 128 + cx];
                rowb[px][u * 2 + v] =
                    (unsigned)(((((b * 20 + cls) * 2 + ph) * 2 + pw) * 2 + u) * 2 + v) * 256u;
            }
    }
    float4 m4 = *(const float4*)&g_mean[b * 128 + np4 * 4];
    float4 rs4 = *(const float4*)&g_rstd[b * 128 + np4 * 4];
    float4 nv4 = *(const float4*)&nvar[np4 * 4];
    float4 cg4 = *(const float4*)&g_Cg[np4 * 4];
    float4 cb4 = *(const float4*)&g_Cb[np4 * 4];
    float mA[4] = { m4.x, m4.y, m4.z, m4.w };
    float rsA[4] = { rs4.x, rs4.y, rs4.z, rs4.w };
    float nvA[4] = { nv4.x, nv4.y, nv4.z, nv4.w };
    float cgA[4] = { cg4.x, cg4.y, cg4.z, cg4.w };
    float cbA[4] = { cb4.x, cb4.y, cb4.z, cb4.w };

    #pragma unroll
    for (int j = 0; j < 4; j++) {
        int co = np4 * 4 + j;
        size_t base = (((size_t)b * 128 + co) * 256 + y) * 256 + xb;
        float4 xlo = *(const float4*)&x[base];
        float4 xhi = *(const float4*)&x[base + 4];
        float xvA[8] = { xlo.x, xlo.y, xlo.z, xlo.w, xhi.x, xhi.y, xhi.z, xhi.w };
        float o[8];
        #pragma unroll
        for (int px = 0; px < 8; px++) {
            ull v = acc[px][j];
            float gsp = __uint_as_float((unsigned)v);
            float bsp = __uint_as_float((unsigned)(v >> 32));
            float ag = 0.f, ab = 0.f;
            #pragma unroll
            for (int k = 0; k < 4; k++) {
                float2 gg = *(const float2*)&g_G4[rowb[px][k] + (unsigned)co * 2u];
                ag += gg.x; ab += gg.y;
            }
            float gf = ga * ag + (1.f - ga) * gsp + cgA[j];
            float bf = ba * ab + (1.f - ba) * bsp + cbA[j];
            float val = (xvA[px] + nzv[px] * nvA[j] - mA[j]) * rsA[j];
            o[px] = fmaf(val, gf, val + bf);
        }
        *(float4*)&out[base] = make_float4(o[0], o[1], o[2], o[3]);
        *(float4*)&out[base + 4] = make_float4(o[4], o[5], o[6], o[7]);
    }
}

// ----------------------------- launch -----------------------------
extern "C" void kernel_launch(void* const* d_in, const int* in_sizes, int n_in,
                              void* d_out, int out_size) {
    const float* x     = (const float*)d_in[0];
    const float* seg   = (const float*)d_in[1];
    const float* sc    = (const float*)d_in[2];
    const float* noise = (const float*)d_in[3];
    const float* nvar  = (const float*)d_in[4];
    const float* bg    = (const float*)d_in[5];
    const float* bb    = (const float*)d_in[6];
    const float* fcw   = (const float*)d_in[7];
    const float* fcb   = (const float*)d_in[8];
    const float* cgw   = (const float*)d_in[9];
    const float* cgb   = (const float*)d_in[10];
    const float* cbw   = (const float*)d_in[11];
    const float* cbb   = (const float*)d_in[12];
    const float* ssw   = (const float*)d_in[13];
    const float* ssb   = (const float*)d_in[14];
    const float* sgw   = (const float*)d_in[15];
    const float* sgb   = (const float*)d_in[16];
    const float* sbw   = (const float*)d_in[17];
    const float* sbb   = (const float*)d_in[18];
    float* out = (float*)d_out;

    cudaFuncSetAttribute(k_main_d2, cudaFuncAttributeMaxDynamicSharedMemorySize, SMEM_MAIN);

    // launch order fixed so k_main_d2 is launch #6 (ncu -s 5 -c 1 window)
    k_prep<<<2303, 256>>>(bg, bb, cgb, cbb, sgb, sbb, sc, fcw, fcb, seg, ssw,
                          sgw, sbw, noise);
    k_stats<<<1024, 256>>>(x, nvar);
    k_lut1<<<160, 128>>>(cgw, cbw);
    k_lut2<<<160, 256>>>();
    k_actv<<<dim3(16, 64, 8), 256>>>(seg, ssb);
    k_main_d2<<<dim3(16, 32, 8), 512, SMEM_MAIN>>>(x, nvar, out);
}

// round 11
// speedup vs baseline: 1.9219x; 1.0003x over previous
#include <cuda_runtime.h>
#include <cstdint>
#include <math.h>

#define B_ 8
#define C_ 128
#define H_ 256
#define W_ 256
#define HW (H_*W_)
typedef unsigned long long ull;

// ----------------------------- device scratch -----------------------------
__device__ __align__(16) float g_actv[(size_t)B_*C_*HW];
__device__ float g_nT[(size_t)B_*HW];
__device__ float g_mean[B_*C_];
__device__ float g_rstd[B_*C_];
__device__ float g_mu[B_*20*64];
__device__ __align__(16) float g_G2[B_*20*9*C_*2];
__device__ __align__(16) float g_G4[B_*20*16*C_*2];
__device__ unsigned char g_cls[B_*128*128];
__device__ __align__(16) float g_B1[171*128];
// [(ci*9+t)] x [p(4)][g(32)][{gamma,beta}]  (conflict-free LDS.64 fragments)
__device__ __align__(16) float g_B2k[1152*256];
__device__ float g_Cg[C_], g_Cb[C_], g_scal[2];

// ----------------------------- helpers -----------------------------
__device__ __forceinline__ ull fma2(ull a, ull b, ull c) {
    ull d;
    asm("fma.rn.f32x2 %0, %1, %2, %3;" : "=l"(d) : "l"(a), "l"(b), "l"(c));
    return d;
}
__device__ __forceinline__ ull pack2(float x, float y) {
    ull d;
    asm("mov.b64 %0, {%1, %2};" : "=l"(d) : "f"(x), "f"(y));
    return d;
}
__device__ __forceinline__ uint32_t smem_u32(const void* p) {
    uint32_t a;
    asm("{ .reg .u64 t; cvta.to.shared.u64 t, %1; cvt.u32.u64 %0, t; }" : "=r"(a) : "l"(p));
    return a;
}
__device__ __forceinline__ void cpa4(uint32_t d, const void* g, int sz) {
    asm volatile("cp.async.ca.shared.global [%0], [%1], 4, %2;"
                 :: "r"(d), "l"(g), "r"(sz) : "memory");
}
__device__ __forceinline__ void cpa16(uint32_t d, const void* g) {
    asm volatile("cp.async.ca.shared.global [%0], [%1], 16;"
                 :: "r"(d), "l"(g) : "memory");
}
__device__ __forceinline__ void cp_commit() {
    asm volatile("cp.async.commit_group;" ::: "memory");
}
__device__ __forceinline__ void cp_wait0() {
    asm volatile("cp.async.wait_group 0;" ::: "memory");
}

// ----------------------------- merged prep (launch #1) -----------------------------
// blocks: [0] scal | [1,41) mu | [41,553) cls | [553,639) w1 | [639,1791) w2 | [1791,2303) ntr
__global__ __launch_bounds__(256) void k_prep(
    const float* bg, const float* bb, const float* cgb, const float* cbb,
    const float* sgb, const float* sbb,
    const float* sc, const float* fcw, const float* fcb,
    const float* segmap, const float* ssw,
    const float* gw, const float* bw, const float* noise) {
    __shared__ float tsh[32][33];
    int bk = blockIdx.x;
    int tid = threadIdx.x;

    if (bk == 0) {
        if (tid < 128) {
            int co = tid;
            float ga = 1.f / (1.f + expf(-bg[0]));
            float ba = 1.f / (1.f + expf(-bb[0]));
            g_Cg[co] = ga * cgb[co] + (1.f - ga) * sgb[co];
            g_Cb[co] = ba * cbb[co] + (1.f - ba) * sbb[co];
            if (co == 0) { g_scal[0] = ga; g_scal[1] = ba; }
        }
    } else if (bk < 41) {
        int bj = (bk - 1) * 4 + (tid >> 6);   // 0..159
        int o = tid & 63;
        int b = bj / 20, j = bj - b * 20;
        float r = 0.f;
        if (j < 19) {
            const float* s = sc + (b * 19 + j) * 64;
            const float* w = fcw + (j * 64 + o) * 64;
            #pragma unroll 8
            for (int i = 0; i < 64; i++) r = fmaf(s[i], w[i], r);
            r += fcb[j * 64 + o];
            r = fmaxf(r, 0.f);
        }
        g_mu[bj * 64 + o] = r;
    } else if (bk < 553) {
        int idx = (bk - 41) * 256 + tid;
        int b = idx >> 14, p = idx & 16383;
        int cls = 19;
        for (int j = 18; j >= 0; j--) {
            if (segmap[(((size_t)b * 19 + j) << 14) + p] > 0.f) { cls = j; break; }
        }
        g_cls[idx] = (unsigned char)cls;
    } else if (bk < 639) {
        int idx = (bk - 553) * 256 + tid;
        if (idx < 171 * 128) {
            int k = idx >> 7, co = idx & 127;
            int j = k / 9, t = k - j * 9;
            g_B1[idx] = ssw[(co * 19 + j) * 9 + t];
        }
    } else if (bk < 1791) {
        int idx = (bk - 639) * 256 + tid;      // 1152*256
        int k = idx >> 8, n = idx & 255;
        int ci = k / 9, t = k - ci * 9;
        int co = n >> 1;
        // new layout: row k, slot = p*64 + g*2 + sel, where g=n>>3, p=(n>>1)&3, sel=n&1
        int g = n >> 3, p = (n >> 1) & 3, sel = n & 1;
        const float* w = sel ? bw : gw;
        g_B2k[k * 256 + p * 64 + g * 2 + sel] = w[(co * 128 + ci) * 9 + t];
    } else {
        int bl = bk - 1791;                    // 512 tiles: b(8) x 64
        int b = bl >> 6, rem = bl & 63;
        int w0 = (rem & 7) * 32, h0 = (rem >> 3) * 32;
        int tx = tid & 31, ty = tid >> 5;      // 32 x 8
        for (int i = 0; i < 32; i += 8)
            tsh[ty + i][tx] = noise[((size_t)b * 256 + w0 + ty + i) * 256 + h0 + tx];
        __syncthreads();
        for (int i = 0; i < 32; i += 8)
            g_nT[((size_t)b * 256 + h0 + ty + i) * 256 + w0 + tx] = tsh[tx][ty + i];
    }
}

// ----------------------------- launch #2: per-(b,c) stats -----------------------------
__global__ __launch_bounds__(256) void k_stats(const float* x, const float* nvar) {
    int bc = blockIdx.x;
    int b = bc >> 7, c = bc & 127;
    float nv = nvar[c];
    const float* xb = x + (size_t)bc * HW;
    const float* nb = g_nT + (size_t)b * HW;
    float s = 0.f, q = 0.f;
    for (int i = threadIdx.x; i < HW; i += 256) {
        float v = xb[i] + nb[i] * nv;
        s += v; q = fmaf(v, v, q);
    }
    __shared__ float ss[8], sq[8];
    #pragma unroll
    for (int o = 16; o; o >>= 1) {
        s += __shfl_xor_sync(0xffffffffu, s, o);
        q += __shfl_xor_sync(0xffffffffu, q, o);
    }
    int wid = threadIdx.x >> 5, lane = threadIdx.x & 31;
    if (!lane) { ss[wid] = s; sq[wid] = q; }
    __syncthreads();
    if (threadIdx.x == 0) {
        float S = 0.f, Q = 0.f;
        #pragma unroll
        for (int k = 0; k < 8; k++) { S += ss[k]; Q += sq[k]; }
        float m = S * (1.f / HW);
        float var = Q * (1.f / HW) - m * m;
        g_mean[bc] = m;
        g_rstd[bc] = rsqrtf(var + 1e-5f);
    }
}

// ----------------------------- launch #3/#4: LUTs -----------------------------
__global__ __launch_bounds__(128) void k_lut1(const float* gw, const float* bw) {
    int bj = blockIdx.x;
    int co = threadIdx.x;
    __shared__ float mu_s[64];
    if (co < 64) mu_s[co] = g_mu[bj * 64 + co];
    __syncthreads();
    for (int t = 0; t < 9; t++) {
        float sg = 0.f, sb = 0.f;
        #pragma unroll 8
        for (int ci = 0; ci < 64; ci++) {
            float m = mu_s[ci];
            sg = fmaf(gw[(co * 64 + ci) * 9 + t], m, sg);
            sb = fmaf(bw[(co * 64 + ci) * 9 + t], m, sb);
        }
        int o = ((bj * 9 + t) * 128 + co) * 2;
        g_G2[o] = sg; g_G2[o + 1] = sb;
    }
}

__global__ __launch_bounds__(256) void k_lut2() {
    int bj = blockIdx.x;
    int n = threadIdx.x;
    const float* G = g_G2 + (size_t)bj * 9 * 256;
    float* O = g_G4 + (size_t)bj * 16 * 256;
    for (int ph = 0; ph < 2; ph++)
    for (int pw = 0; pw < 2; pw++)
    for (int u = 0; u < 2; u++)
    for (int v = 0; v < 2; v++) {
        int rlo = (u == 0) ? 0 : (ph == 0 ? 1 : 2);
        int rhi = (u == 0) ? (ph == 0 ? 0 : 1) : 2;
        int clo = (v == 0) ? 0 : (pw == 0 ? 1 : 2);
        int chi = (v == 0) ? (pw == 0 ? 0 : 1) : 2;
        float s = 0.f;
        for (int dy = rlo; dy <= rhi; dy++)
            for (int dx = clo; dx <= chi; dx++)
                s += G[(dy * 3 + dx) * 256 + n];
        O[(((ph * 2 + pw) * 2 + u) * 2 + v) * 256 + n] = s;
    }
}

// ----------------------------- launch #5: actv conv (19 -> 128) -----------------------------
__global__ __launch_bounds__(256, 2) void k_actv(const float* segmap, const float* ssb) {
    __shared__ float Sh[19][4][10];
    __shared__ __align__(16) float Bsj[9][128];
    int b = blockIdx.z;
    int x0 = blockIdx.x * 16, y0 = blockIdx.y * 4;
    int tid = threadIdx.x;
    int tx = tid & 15, ty = tid >> 4;
    int r = ty >> 2, c = (ty & 3) * 4;

    int hb = (y0 >> 1) - 1, cbh = (x0 >> 1) - 1;
    for (int idx = tid; idx < 19 * 40; idx += 256) {
        int j = idx / 40, pos = idx - j * 40;
        int hr = pos / 10, hc = pos - hr * 10;
        int gy = hb + hr, gx = cbh + hc;
        float v = 0.f;
        if ((unsigned)gy < 128u && (unsigned)gx < 128u)
            v = segmap[(((size_t)b * 19 + j) << 14) + gy * 128 + gx];
        Sh[j][hr][hc] = v;
    }

    int hrw[3], hcc[6];
    #pragma unroll
    for (int k = 0; k < 3; k++) hrw[k] = ((r + k - 1) >> 1) + 1;
    #pragma unroll
    for (int k = 0; k < 6; k++) hcc[k] = ((c + k - 1) >> 1) + 1;

    ull acc[4][4];
    #pragma unroll
    for (int p = 0; p < 4; p++)
        #pragma unroll
        for (int q = 0; q < 4; q++) acc[p][q] = 0ull;

    for (int j = 0; j < 19; j++) {
        __syncthreads();
        for (int idx = tid; idx < 1152; idx += 256)
            ((float*)Bsj)[idx] = g_B1[j * 1152 + idx];
        __syncthreads();
        #pragma unroll
        for (int t = 0; t < 9; t++) {
            const int tdy = t / 3, tdx = t - tdy * 3;
            ull Ap[4];
            #pragma unroll
            for (int i = 0; i < 4; i++) {
                float a = Sh[j][hrw[tdy]][hcc[tdx + i]];
                Ap[i] = pack2(a, a);
            }
            ulonglong2 b0 = *(const ulonglong2*)&Bsj[t][tx * 4];
            ulonglong2 b1 = *(const ulonglong2*)&Bsj[t][tx * 4 + 64];
            #pragma unroll
            for (int p = 0; p < 4; p++) {
                acc[p][0] = fma2(Ap[p], b0.x, acc[p][0]);
                acc[p][1] = fma2(Ap[p], b0.y, acc[p][1]);
                acc[p][2] = fma2(Ap[p], b1.x, acc[p][2]);
                acc[p][3] = fma2(Ap[p], b1.y, acc[p][3]);
            }
        }
    }

    int y = y0 + r, xg0 = x0 + c;
    #pragma unroll
    for (int q = 0; q < 4; q++) {
        int co0 = (q < 2) ? (tx * 4 + q * 2) : (tx * 4 + 64 + (q - 2) * 2);
        #pragma unroll
        for (int h2 = 0; h2 < 2; h2++) {
            int co = co0 + h2;
            float bias = ssb[co];
            float4 o;
            float* op = (float*)&o;
            #pragma unroll
            for (int p = 0; p < 4; p++) {
                ull v = acc[p][q];
                unsigned w32 = h2 ? (unsigned)(v >> 32) : (unsigned)v;
                op[p] = fmaxf(__uint_as_float(w32) + bias, 0.f);
            }
            *(float4*)&g_actv[(((size_t)b * 128 + co) * 256 + y) * 256 + xg0] = o;
        }
    }
}

// ------------- launch #6: direct conv, conflict-free LDS.64 B fragments -------------
#define A_FL 800            // per buf: 4*10*20
#define B_FL 9216           // per buf: 36*256
#define SMEM_MAIN ((2*A_FL + 2*B_FL) * 4)

__global__ __launch_bounds__(512, 1) void k_main_d2(const float* __restrict__ x,
                                                    const float* __restrict__ nvar,
                                                    float* __restrict__ out) {
    extern __shared__ float sm[];
    float* Asm = sm;                 // [2][A_FL]
    float* Bsm = sm + 2 * A_FL;      // [2][B_FL]
    uint32_t As_u = smem_u32(Asm), Bs_u = smem_u32(Bsm);

    int tid = threadIdx.x;
    int np4 = tid & 31;
    int r = tid >> 6;
    int xoff = ((tid >> 5) & 1) * 8;
    int b = blockIdx.z;
    int x0 = blockIdx.x * 16, y0 = blockIdx.y * 8;

    ull acc[8][4];
    #pragma unroll
    for (int p = 0; p < 8; p++)
        #pragma unroll
        for (int j = 0; j < 4; j++) acc[p][j] = 0ull;

    auto issue = [&](int ch, int buf) {
        int ci0 = ch * 4;
        #pragma unroll
        for (int k = 0; k < 2; k++) {
            int idx = tid + k * 512;
            if (idx < 720) {
                int ci = idx / 180, rem = idx - ci * 180;
                int rr = rem / 18, cc = rem - rr * 18;
                int gy = y0 - 1 + rr, gx = x0 - 1 + cc;
                bool ok = ((unsigned)gy < 256u) && ((unsigned)gx < 256u);
                const float* src = &g_actv[(((size_t)b * 128 + ci0 + ci) * 256
                                            + (ok ? gy : 0)) * 256 + (ok ? gx : 0)];
                cpa4(As_u + (uint32_t)(buf * A_FL + ci * 200 + rr * 20 + cc) * 4u,
                     src, ok ? 4 : 0);
            }
        }
        const float4* srcB = (const float4*)(g_B2k + (size_t)ch * B_FL);
        uint32_t dB = Bs_u + (uint32_t)(buf * B_FL) * 4u;
        #pragma unroll
        for (int k = 0; k < 5; k++) {
            int idx = tid + k * 512;
            if (idx < 2304) cpa16(dB + (uint32_t)idx * 16u, srcB + idx);
        }
        cp_commit();
    };

    issue(0, 0);
    #pragma unroll 1
    for (int ch = 0; ch < 32; ch++) {
        cp_wait0();
        __syncthreads();
        if (ch + 1 < 32) issue(ch + 1, (ch + 1) & 1);
        const float* Asb = Asm + (ch & 1) * A_FL;
        const float* Bsb = Bsm + (ch & 1) * B_FL;
        #pragma unroll
        for (int ci = 0; ci < 4; ci++) {
            #pragma unroll
            for (int dy = 0; dy < 3; dy++) {
                const float* ap = Asb + ci * 200 + (r + dy) * 20 + xoff;
                float4 A0 = *(const float4*)ap;
                float4 A1 = *(const float4*)(ap + 4);
                float2 A2 = *(const float2*)(ap + 8);
                ull a2[10];
                a2[0] = pack2(A0.x, A0.x); a2[1] = pack2(A0.y, A0.y);
                a2[2] = pack2(A0.z, A0.z); a2[3] = pack2(A0.w, A0.w);
                a2[4] = pack2(A1.x, A1.x); a2[5] = pack2(A1.y, A1.y);
                a2[6] = pack2(A1.z, A1.z); a2[7] = pack2(A1.w, A1.w);
                a2[8] = pack2(A2.x, A2.x); a2[9] = pack2(A2.y, A2.y);
                // conflict-free: lane np4 reads 8B at stride 8B (contiguous 256B per p-slot)
                const float* bp = Bsb + (ci * 9 + dy * 3) * 256 + np4 * 2;
                ull Bv[3][4];
                #pragma unroll
                for (int dx = 0; dx < 3; dx++)
                    #pragma unroll
                    for (int p = 0; p < 4; p++)
                        Bv[dx][p] = *(const ull*)(bp + dx * 256 + p * 64);
                #pragma unroll
                for (int px = 0; px < 8; px++) {
                    #pragma unroll
                    for (int dx = 0; dx < 3; dx++) {
                        acc[px][0] = fma2(a2[px + dx], Bv[dx][0], acc[px][0]);
                        acc[px][1] = fma2(a2[px + dx], Bv[dx][1], acc[px][1]);
                        acc[px][2] = fma2(a2[px + dx], Bv[dx][2], acc[px][2]);
                        acc[px][3] = fma2(a2[px + dx], Bv[dx][3], acc[px][3]);
                    }
                }
            }
        }
    }

    // ---------------- fused epilogue ----------------
    float ga = g_scal[0], ba = g_scal[1];
    int y = y0 + r, xb = x0 + xoff;
    float4 nz0 = *(const float4*)&g_nT[((size_t)b * 256 + y) * 256 + xb];
    float4 nz1 = *(const float4*)&g_nT[((size_t)b * 256 + y) * 256 + xb + 4];
    float nzv[8] = { nz0.x, nz0.y, nz0.z, nz0.w, nz1.x, nz1.y, nz1.z, nz1.w };

    int ph = y & 1, r0 = (y - 1) >> 1;
    unsigned rowb[8][4];
    #pragma unroll
    for (int px = 0; px < 8; px++) {
        int xg = xb + px;
        int pw = xg & 1, c0 = (xg - 1) >> 1;
        #pragma unroll
        for (int u = 0; u < 2; u++)
            #pragma unroll
            for (int v = 0; v < 2; v++) {
                int cy = r0 + u, cx = c0 + v;
                int cls = 19;
                if ((unsigned)cy < 128u && (unsigned)cx < 128u)
                    cls = g_cls[((size_t)b << 14) + cy * 128 + cx];
                rowb[px][u * 2 + v] =
                    (unsigned)(((((b * 20 + cls) * 2 + ph) * 2 + pw) * 2 + u) * 2 + v) * 256u;
            }
    }
    float4 m4 = *(const float4*)&g_mean[b * 128 + np4 * 4];
    float4 rs4 = *(const float4*)&g_rstd[b * 128 + np4 * 4];
    float4 nv4 = *(const float4*)&nvar[np4 * 4];
    float4 cg4 = *(const float4*)&g_Cg[np4 * 4];
    float4 cb4 = *(const float4*)&g_Cb[np4 * 4];
    float mA[4] = { m4.x, m4.y, m4.z, m4.w };
    float rsA[4] = { rs4.x, rs4.y, rs4.z, rs4.w };
    float nvA[4] = { nv4.x, nv4.y, nv4.z, nv4.w };
    float cgA[4] = { cg4.x, cg4.y, cg4.z, cg4.w };
    float cbA[4] = { cb4.x, cb4.y, cb4.z, cb4.w };

    #pragma unroll
    for (int j = 0; j < 4; j++) {
        int co = np4 * 4 + j;
        size_t base = (((size_t)b * 128 + co) * 256 + y) * 256 + xb;
        float4 xlo = *(const float4*)&x[base];
        float4 xhi = *(const float4*)&x[base + 4];
        float xvA[8] = { xlo.x, xlo.y, xlo.z, xlo.w, xhi.x, xhi.y, xhi.z, xhi.w };
        float o[8];
        #pragma unroll
        for (int px = 0; px < 8; px++) {
            ull v = acc[px][j];
            float gsp = __uint_as_float((unsigned)v);
            float bsp = __uint_as_float((unsigned)(v >> 32));
            float ag = 0.f, ab = 0.f;
            #pragma unroll
            for (int k = 0; k < 4; k++) {
                float2 gg = *(const float2*)&g_G4[rowb[px][k] + (unsigned)co * 2u];
                ag += gg.x; ab += gg.y;
            }
            float gf = ga * ag + (1.f - ga) * gsp + cgA[j];
            float bf = ba * ab + (1.f - ba) * bsp + cbA[j];
            float val = (xvA[px] + nzv[px] * nvA[j] - mA[j]) * rsA[j];
            o[px] = fmaf(val, gf, val + bf);
        }
        *(float4*)&out[base] = make_float4(o[0], o[1], o[2], o[3]);
        *(float4*)&out[base + 4] = make_float4(o[4], o[5], o[6], o[7]);
    }
}

// ----------------------------- launch -----------------------------
extern "C" void kernel_launch(void* const* d_in, const int* in_sizes, int n_in,
                              void* d_out, int out_size) {
    const float* x     = (const float*)d_in[0];
    const float* seg   = (const float*)d_in[1];
    const float* sc    = (const float*)d_in[2];
    const float* noise = (const float*)d_in[3];
    const float* nvar  = (const float*)d_in[4];
    const float* bg    = (const float*)d_in[5];
    const float* bb    = (const float*)d_in[6];
    const float* fcw   = (const float*)d_in[7];
    const float* fcb   = (const float*)d_in[8];
    const float* cgw   = (const float*)d_in[9];
    const float* cgb   = (const float*)d_in[10];
    const float* cbw   = (const float*)d_in[11];
    const float* cbb   = (const float*)d_in[12];
    const float* ssw   = (const float*)d_in[13];
    const float* ssb   = (const float*)d_in[14];
    const float* sgw   = (const float*)d_in[15];
    const float* sgb   = (const float*)d_in[16];
    const float* sbw   = (const float*)d_in[17];
    const float* sbb   = (const float*)d_in[18];
    float* out = (float*)d_out;

    cudaFuncSetAttribute(k_main_d2, cudaFuncAttributeMaxDynamicSharedMemorySize, SMEM_MAIN);

    // launch order fixed so k_main_d2 is launch #6 (ncu -s 5 -c 1 window)
    k_prep<<<2303, 256>>>(bg, bb, cgb, cbb, sgb, sbb, sc, fcw, fcb, seg, ssw,
                          sgw, sbw, noise);
    k_stats<<<1024, 256>>>(x, nvar);
    k_lut1<<<160, 128>>>(cgw, cbw);
    k_lut2<<<160, 256>>>();
    k_actv<<<dim3(16, 64, 8), 256>>>(seg, ssb);
    k_main_d2<<<dim3(16, 32, 8), 512, SMEM_MAIN>>>(x, nvar, out);
}

// round 12
// speedup vs baseline: 2.2898x; 1.1914x over previous
#include <cuda_runtime.h>
#include <cstdint>
#include <math.h>

#define B_ 8
#define C_ 128
#define H_ 256
#define W_ 256
#define HW (H_*W_)
typedef unsigned long long ull;

// ----------------------------- device scratch -----------------------------
__device__ __align__(16) float g_actv[(size_t)B_*C_*HW];      // 268MB
__device__ __align__(16) float g_V[(size_t)16*C_*16384];      // 134MB (per-b, reused)
__device__ __align__(16) float g_M[(size_t)16*C_*16384*2];    // 268MB (per-b, reused)
__device__ __align__(16) float g_U[16*C_*256];                // [k][ci][n]
__device__ float g_nT[(size_t)B_*HW];
__device__ float g_mean[B_*C_];
__device__ float g_rstd[B_*C_];
__device__ float g_mu[B_*20*64];
__device__ __align__(16) float g_G2[B_*20*9*C_*2];
__device__ __align__(16) float g_G4[B_*20*16*C_*2];
__device__ unsigned char g_cls[B_*128*128];
__device__ __align__(16) float g_B1[171*128];
__device__ float g_Cg[C_], g_Cb[C_], g_scal[2];

// ----------------------------- helpers -----------------------------
__device__ __forceinline__ ull fma2(ull a, ull b, ull c) {
    ull d;
    asm("fma.rn.f32x2 %0, %1, %2, %3;" : "=l"(d) : "l"(a), "l"(b), "l"(c));
    return d;
}
__device__ __forceinline__ ull pack2(float x, float y) {
    ull d;
    asm("mov.b64 %0, {%1, %2};" : "=l"(d) : "f"(x), "f"(y));
    return d;
}
__device__ __forceinline__ uint32_t smem_u32(const void* p) {
    uint32_t a;
    asm("{ .reg .u64 t; cvta.to.shared.u64 t, %1; cvt.u32.u64 %0, t; }" : "=r"(a) : "l"(p));
    return a;
}
__device__ __forceinline__ void cpa16(uint32_t d, const void* g) {
    asm volatile("cp.async.ca.shared.global [%0], [%1], 16;" :: "r"(d), "l"(g) : "memory");
}
__device__ __forceinline__ void cp_commit() { asm volatile("cp.async.commit_group;" ::: "memory"); }
__device__ __forceinline__ void cp_wait0() { asm volatile("cp.async.wait_group 0;" ::: "memory"); }

// ----------------------------- launch #1: merged prep -----------------------------
// blocks: [0] scal | [1,41) mu | [41,553) cls | [553,639) B1 | [639,767) U | [767,1279) ntr
__global__ __launch_bounds__(256) void k_prep(
    const float* bg, const float* bb, const float* cgb, const float* cbb,
    const float* sgb, const float* sbb, const float* sc, const float* fcw,
    const float* fcb, const float* segmap, const float* ssw,
    const float* sgw, const float* sbw, const float* noise) {
    __shared__ float tsh[32][33];
    int bk = blockIdx.x, tid = threadIdx.x;
    if (bk == 0) {
        if (tid < 128) {
            float ga = 1.f / (1.f + expf(-bg[0]));
            float ba = 1.f / (1.f + expf(-bb[0]));
            g_Cg[tid] = ga * cgb[tid] + (1.f - ga) * sgb[tid];
            g_Cb[tid] = ba * cbb[tid] + (1.f - ba) * sbb[tid];
            if (tid == 0) { g_scal[0] = ga; g_scal[1] = ba; }
        }
    } else if (bk < 41) {
        int bj = (bk - 1) * 4 + (tid >> 6), o = tid & 63;
        int b = bj / 20, j = bj - b * 20;
        float r = 0.f;
        if (j < 19) {
            const float* s = sc + (b * 19 + j) * 64;
            const float* w = fcw + (j * 64 + o) * 64;
            #pragma unroll 8
            for (int i = 0; i < 64; i++) r = fmaf(s[i], w[i], r);
            r = fmaxf(r + fcb[j * 64 + o], 0.f);
        }
        g_mu[bj * 64 + o] = r;
    } else if (bk < 553) {
        int idx = (bk - 41) * 256 + tid;
        int b = idx >> 14, p = idx & 16383;
        int cls = 19;
        for (int j = 18; j >= 0; j--)
            if (segmap[(((size_t)b * 19 + j) << 14) + p] > 0.f) { cls = j; break; }
        g_cls[idx] = (unsigned char)cls;
    } else if (bk < 639) {
        int idx = (bk - 553) * 256 + tid;
        if (idx < 171 * 128) {
            int k = idx >> 7, co = idx & 127;
            int j = k / 9, t = k - j * 9;
            g_B1[idx] = ssw[(co * 19 + j) * 9 + t];
        }
    } else if (bk < 767) {
        int idx = (bk - 639) * 256 + tid;   // 32768 = 128ci x 256n
        int ci = idx >> 8, n = idx & 255;
        int co = n >> 1, sel = n & 1;
        const float* w = sel ? sbw : sgw;
        float g[3][3];
        #pragma unroll
        for (int t = 0; t < 9; t++) g[t / 3][t % 3] = w[(co * 128 + ci) * 9 + t];
        float r[4][3];
        #pragma unroll
        for (int j = 0; j < 3; j++) {
            r[0][j] = g[0][j];
            r[1][j] = (g[0][j] + g[1][j] + g[2][j]) * 0.5f;
            r[2][j] = (g[0][j] - g[1][j] + g[2][j]) * 0.5f;
            r[3][j] = g[2][j];
        }
        #pragma unroll
        for (int a = 0; a < 4; a++) {
            g_U[((a * 4 + 0) * 128 + ci) * 256 + n] = r[a][0];
            g_U[((a * 4 + 1) * 128 + ci) * 256 + n] = (r[a][0] + r[a][1] + r[a][2]) * 0.5f;
            g_U[((a * 4 + 2) * 128 + ci) * 256 + n] = (r[a][0] - r[a][1] + r[a][2]) * 0.5f;
            g_U[((a * 4 + 3) * 128 + ci) * 256 + n] = r[a][2];
        }
    } else {
        int bl = bk - 767;
        int b = bl >> 6, rem = bl & 63;
        int w0 = (rem & 7) * 32, h0 = (rem >> 3) * 32;
        int tx = tid & 31, ty = tid >> 5;
        for (int i = 0; i < 32; i += 8)
            tsh[ty + i][tx] = noise[((size_t)b * 256 + w0 + ty + i) * 256 + h0 + tx];
        __syncthreads();
        for (int i = 0; i < 32; i += 8)
            g_nT[((size_t)b * 256 + h0 + ty + i) * 256 + w0 + tx] = tsh[tx][ty + i];
    }
}

// ----------------------------- launch #2: stats -----------------------------
__global__ __launch_bounds__(256) void k_stats(const float* x, const float* nvar) {
    int bc = blockIdx.x;
    int b = bc >> 7, c = bc & 127;
    float nv = nvar[c];
    const float* xb = x + (size_t)bc * HW;
    const float* nb = g_nT + (size_t)b * HW;
    float s = 0.f, q = 0.f;
    for (int i = threadIdx.x; i < HW; i += 256) {
        float v = xb[i] + nb[i] * nv;
        s += v; q = fmaf(v, v, q);
    }
    __shared__ float ss[8], sq[8];
    #pragma unroll
    for (int o = 16; o; o >>= 1) {
        s += __shfl_xor_sync(0xffffffffu, s, o);
        q += __shfl_xor_sync(0xffffffffu, q, o);
    }
    int wid = threadIdx.x >> 5, lane = threadIdx.x & 31;
    if (!lane) { ss[wid] = s; sq[wid] = q; }
    __syncthreads();
    if (threadIdx.x == 0) {
        float S = 0.f, Q = 0.f;
        #pragma unroll
        for (int k = 0; k < 8; k++) { S += ss[k]; Q += sq[k]; }
        float m = S * (1.f / HW);
        g_mean[bc] = m;
        g_rstd[bc] = rsqrtf(Q * (1.f / HW) - m * m + 1e-5f);
    }
}

// ----------------------------- LUTs -----------------------------
__global__ __launch_bounds__(128) void k_lut1(const float* gw, const float* bw) {
    int bj = blockIdx.x, co = threadIdx.x;
    __shared__ float mu_s[64];
    if (co < 64) mu_s[co] = g_mu[bj * 64 + co];
    __syncthreads();
    for (int t = 0; t < 9; t++) {
        float sg = 0.f, sb = 0.f;
        #pragma unroll 8
        for (int ci = 0; ci < 64; ci++) {
            float m = mu_s[ci];
            sg = fmaf(gw[(co * 64 + ci) * 9 + t], m, sg);
            sb = fmaf(bw[(co * 64 + ci) * 9 + t], m, sb);
        }
        int o = ((bj * 9 + t) * 128 + co) * 2;
        g_G2[o] = sg; g_G2[o + 1] = sb;
    }
}

__global__ __launch_bounds__(256) void k_lut2() {
    int bj = blockIdx.x, n = threadIdx.x;
    const float* G = g_G2 + (size_t)bj * 9 * 256;
    float* O = g_G4 + (size_t)bj * 16 * 256;
    for (int ph = 0; ph < 2; ph++)
    for (int pw = 0; pw < 2; pw++)
    for (int u = 0; u < 2; u++)
    for (int v = 0; v < 2; v++) {
        int rlo = (u == 0) ? 0 : (ph == 0 ? 1 : 2);
        int rhi = (u == 0) ? (ph == 0 ? 0 : 1) : 2;
        int clo = (v == 0) ? 0 : (pw == 0 ? 1 : 2);
        int chi = (v == 0) ? (pw == 0 ? 0 : 1) : 2;
        float s = 0.f;
        for (int dy = rlo; dy <= rhi; dy++)
            for (int dx = clo; dx <= chi; dx++)
                s += G[(dy * 3 + dx) * 256 + n];
        O[(((ph * 2 + pw) * 2 + u) * 2 + v) * 256 + n] = s;
    }
}

// ----------------------------- actv conv (19->128) -----------------------------
__global__ __launch_bounds__(256, 2) void k_actv(const float* segmap, const float* ssb) {
    __shared__ float Sh[19][4][10];
    __shared__ __align__(16) float Bsj[9][128];
    int b = blockIdx.z;
    int x0 = blockIdx.x * 16, y0 = blockIdx.y * 4;
    int tid = threadIdx.x;
    int tx = tid & 15, ty = tid >> 4;
    int r = ty >> 2, c = (ty & 3) * 4;

    int hb = (y0 >> 1) - 1, cbh = (x0 >> 1) - 1;
    for (int idx = tid; idx < 19 * 40; idx += 256) {
        int j = idx / 40, pos = idx - j * 40;
        int hr = pos / 10, hc = pos - hr * 10;
        int gy = hb + hr, gx = cbh + hc;
        float v = 0.f;
        if ((unsigned)gy < 128u && (unsigned)gx < 128u)
            v = segmap[(((size_t)b * 19 + j) << 14) + gy * 128 + gx];
        Sh[j][hr][hc] = v;
    }
    int hrw[3], hcc[6];
    #pragma unroll
    for (int k = 0; k < 3; k++) hrw[k] = ((r + k - 1) >> 1) + 1;
    #pragma unroll
    for (int k = 0; k < 6; k++) hcc[k] = ((c + k - 1) >> 1) + 1;

    ull acc[4][4];
    #pragma unroll
    for (int p = 0; p < 4; p++)
        #pragma unroll
        for (int q = 0; q < 4; q++) acc[p][q] = 0ull;

    for (int j = 0; j < 19; j++) {
        __syncthreads();
        for (int idx = tid; idx < 1152; idx += 256)
            ((float*)Bsj)[idx] = g_B1[j * 1152 + idx];
        __syncthreads();
        #pragma unroll
        for (int t = 0; t < 9; t++) {
            const int tdy = t / 3, tdx = t - tdy * 3;
            ull Ap[4];
            #pragma unroll
            for (int i = 0; i < 4; i++) {
                float a = Sh[j][hrw[tdy]][hcc[tdx + i]];
                Ap[i] = pack2(a, a);
            }
            ulonglong2 b0 = *(const ulonglong2*)&Bsj[t][tx * 4];
            ulonglong2 b1 = *(const ulonglong2*)&Bsj[t][tx * 4 + 64];
            #pragma unroll
            for (int p = 0; p < 4; p++) {
                acc[p][0] = fma2(Ap[p], b0.x, acc[p][0]);
                acc[p][1] = fma2(Ap[p], b0.y, acc[p][1]);
                acc[p][2] = fma2(Ap[p], b1.x, acc[p][2]);
                acc[p][3] = fma2(Ap[p], b1.y, acc[p][3]);
            }
        }
    }
    int y = y0 + r, xg0 = x0 + c;
    #pragma unroll
    for (int q = 0; q < 4; q++) {
        int co0 = (q < 2) ? (tx * 4 + q * 2) : (tx * 4 + 64 + (q - 2) * 2);
        #pragma unroll
        for (int h2 = 0; h2 < 2; h2++) {
            int co = co0 + h2;
            float bias = ssb[co];
            float4 o;
            float* op = (float*)&o;
            #pragma unroll
            for (int p = 0; p < 4; p++) {
                ull v = acc[p][q];
                unsigned w32 = h2 ? (unsigned)(v >> 32) : (unsigned)v;
                op[p] = fmaxf(__uint_as_float(w32) + bias, 0.f);
            }
            *(float4*)&g_actv[(((size_t)b * 128 + co) * 256 + y) * 256 + xg0] = o;
        }
    }
}

// ----------------------------- Winograd input transform V = Bt d B -----------------
__global__ __launch_bounds__(256) void k_vt(int b) {
    __shared__ float sm[34][35];
    int tid = threadIdx.x;
    int ci = blockIdx.y;
    int y0 = (blockIdx.x >> 3) * 32, x0 = (blockIdx.x & 7) * 32;
    const float* src = g_actv + ((size_t)b * 128 + ci) * HW;
    for (int idx = tid; idx < 34 * 34; idx += 256) {
        int r = idx / 34, c = idx - r * 34;
        int gy = y0 - 1 + r, gx = x0 - 1 + c;
        float v = 0.f;
        if ((unsigned)gy < 256u && (unsigned)gx < 256u) v = src[gy * 256 + gx];
        sm[r][c] = v;
    }
    __syncthreads();
    int ty = tid >> 4, tx = tid & 15;
    float d[4][4];
    #pragma unroll
    for (int i = 0; i < 4; i++)
        #pragma unroll
        for (int j = 0; j < 4; j++) d[i][j] = sm[2 * ty + i][2 * tx + j];
    float t[4][4];
    #pragma unroll
    for (int j = 0; j < 4; j++) {
        t[0][j] = d[0][j] - d[2][j];
        t[1][j] = d[1][j] + d[2][j];
        t[2][j] = d[2][j] - d[1][j];
        t[3][j] = d[1][j] - d[3][j];
    }
    int gtile = ((y0 >> 1) + ty) * 128 + ((x0 >> 1) + tx);
    float* dst = g_V + (size_t)ci * 16384 + gtile;
    const size_t ks = (size_t)128 * 16384;
    #pragma unroll
    for (int a = 0; a < 4; a++) {
        dst[(a * 4 + 0) * ks] = t[a][0] - t[a][2];
        dst[(a * 4 + 1) * ks] = t[a][1] + t[a][2];
        dst[(a * 4 + 2) * ks] = t[a][2] - t[a][1];
        dst[(a * 4 + 3) * ks] = t[a][1] - t[a][3];
    }
}

// ----------------------------- batched GEMM: M[k] = U[k]^T V[k] ---------------------
// grid (128 mb, 32 = k*2+nb). CTA 128 tiles x 128 n. thread: 8 m (mg*8) x 4 (gamma,beta) pairs.
__global__ __launch_bounds__(256, 2) void k_gemm() {
    __shared__ __align__(16) float As[2][16][128];
    __shared__ __align__(16) float Us[2][16][128];
    uint32_t As_u = smem_u32(As), Us_u = smem_u32(Us);
    int tid = threadIdx.x, mg = tid & 15, ng = tid >> 4;
    int mb = blockIdx.x;
    int k = blockIdx.y >> 1, nb = blockIdx.y & 1;
    const float* Vb = g_V + (size_t)k * 128 * 16384 + mb * 128;
    const float* Ub = g_U + k * 128 * 256 + nb * 128;

    ull acc[8][4];
    #pragma unroll
    for (int i = 0; i < 8; i++)
        #pragma unroll
        for (int c = 0; c < 4; c++) acc[i][c] = 0ull;

    auto issue = [&](int c, int buf) {
        #pragma unroll
        for (int j = 0; j < 2; j++) {
            int idx = tid * 2 + j;               // 0..511
            int row = idx >> 5, col = (idx & 31) * 4;
            cpa16(As_u + (uint32_t)((buf * 16 + row) * 128 + col) * 4u,
                  Vb + (size_t)(c * 16 + row) * 16384 + col);
            cpa16(Us_u + (uint32_t)((buf * 16 + row) * 128 + col) * 4u,
                  Ub + (size_t)(c * 16 + row) * 256 + col);
        }
        cp_commit();
    };

    issue(0, 0);
    #pragma unroll 1
    for (int c = 0; c < 8; c++) {
        cp_wait0();
        __syncthreads();
        if (c + 1 < 8) issue(c + 1, (c + 1) & 1);
        int buf = c & 1;
        #pragma unroll
        for (int ci = 0; ci < 16; ci++) {
            float4 a0 = *(const float4*)&As[buf][ci][mg * 8];
            float4 a1 = *(const float4*)&As[buf][ci][mg * 8 + 4];
            ulonglong2 u0 = *(const ulonglong2*)&Us[buf][ci][ng * 8];
            ulonglong2 u1 = *(const ulonglong2*)&Us[buf][ci][ng * 8 + 4];
            ull ap[8];
            ap[0] = pack2(a0.x, a0.x); ap[1] = pack2(a0.y, a0.y);
            ap[2] = pack2(a0.z, a0.z); ap[3] = pack2(a0.w, a0.w);
            ap[4] = pack2(a1.x, a1.x); ap[5] = pack2(a1.y, a1.y);
            ap[6] = pack2(a1.z, a1.z); ap[7] = pack2(a1.w, a1.w);
            #pragma unroll
            for (int i = 0; i < 8; i++) {
                acc[i][0] = fma2(ap[i], u0.x, acc[i][0]);
                acc[i][1] = fma2(ap[i], u0.y, acc[i][1]);
                acc[i][2] = fma2(ap[i], u1.x, acc[i][2]);
                acc[i][3] = fma2(ap[i], u1.y, acc[i][3]);
            }
        }
    }
    // store M: [k][co][tile] float2, co = nb*64 + ng*4 + c, tiles mg*8..+7
    #pragma unroll
    for (int c = 0; c < 4; c++) {
        int co = nb * 64 + ng * 4 + c;
        ull* Mr = (ull*)g_M + ((size_t)k * 128 + co) * 16384 + mb * 128 + mg * 8;
        ulonglong2 s0, s1, s2, s3;
        s0.x = acc[0][c]; s0.y = acc[1][c];
        s1.x = acc[2][c]; s1.y = acc[3][c];
        s2.x = acc[4][c]; s2.y = acc[5][c];
        s3.x = acc[6][c]; s3.y = acc[7][c];
        *(ulonglong2*)(Mr + 0) = s0;
        *(ulonglong2*)(Mr + 2) = s1;
        *(ulonglong2*)(Mr + 4) = s2;
        *(ulonglong2*)(Mr + 6) = s3;
    }
}

// ----------------------------- inverse transform + fused epilogue -------------------
// grid (64, 4): 256 tiles/CTA, co-range 32.
__global__ __launch_bounds__(256) void k_inv(int b, const float* __restrict__ x,
                                             const float* __restrict__ nvar,
                                             float* __restrict__ out) {
    int tid = threadIdx.x;
    int gtile = blockIdx.x * 256 + tid;
    int ty = gtile >> 7, tx = gtile & 127;
    int co0 = blockIdx.y * 32;

    int cls9[3][3];
    #pragma unroll
    for (int i = 0; i < 3; i++)
        #pragma unroll
        for (int j = 0; j < 3; j++) {
            int cy = ty - 1 + i, cx = tx - 1 + j;
            int cls = 19;
            if ((unsigned)cy < 128u && (unsigned)cx < 128u)
                cls = g_cls[((size_t)b << 14) + cy * 128 + cx];
            cls9[i][j] = cls;
        }
    unsigned rowb[2][2][4];   // [h][w][u*2+v]
    #pragma unroll
    for (int h = 0; h < 2; h++)
        #pragma unroll
        for (int w = 0; w < 2; w++)
            #pragma unroll
            for (int u = 0; u < 2; u++)
                #pragma unroll
                for (int v = 0; v < 2; v++) {
                    int cls = cls9[h + u][w + v];
                    rowb[h][w][u * 2 + v] =
                        (unsigned)(((((b * 20 + cls) * 2 + h) * 2 + w) * 2 + u) * 2 + v) * 256u;
                }
    int y0 = 2 * ty, x0 = 2 * tx;
    float2 nz0 = *(const float2*)&g_nT[((size_t)b * 256 + y0) * 256 + x0];
    float2 nz1 = *(const float2*)&g_nT[((size_t)b * 256 + y0 + 1) * 256 + x0];
    float ga = g_scal[0], ba = g_scal[1];

    #pragma unroll 1
    for (int ic = 0; ic < 32; ic++) {
        int co = co0 + ic;
        const float2* Mp = (const float2*)g_M + (size_t)co * 16384 + gtile;
        const size_t ks = (size_t)128 * 16384;
        float2 Mv[16];
        #pragma unroll
        for (int k = 0; k < 16; k++) Mv[k] = Mp[(size_t)k * 128 * 16384];
        // inverse: tmp[i][j], Y[h][w] for gamma (.x) and beta (.y)
        float tg[2][4], tb[2][4];
        #pragma unroll
        for (int j = 0; j < 4; j++) {
            tg[0][j] = Mv[j].x + Mv[4 + j].x + Mv[8 + j].x;
            tg[1][j] = Mv[4 + j].x - Mv[8 + j].x - Mv[12 + j].x;
            tb[0][j] = Mv[j].y + Mv[4 + j].y + Mv[8 + j].y;
            tb[1][j] = Mv[4 + j].y - Mv[8 + j].y - Mv[12 + j].y;
        }
        float Yg[2][2], Yb[2][2];
        #pragma unroll
        for (int h = 0; h < 2; h++) {
            Yg[h][0] = tg[h][0] + tg[h][1] + tg[h][2];
            Yg[h][1] = tg[h][1] - tg[h][2] - tg[h][3];
            Yb[h][0] = tb[h][0] + tb[h][1] + tb[h][2];
            Yb[h][1] = tb[h][1] - tb[h][2] - tb[h][3];
        }
        float mean = g_mean[b * 128 + co];
        float rs = g_rstd[b * 128 + co];
        float nv = nvar[co];
        float cg = g_Cg[co], cb = g_Cb[co];
        size_t base = (((size_t)b * 128 + co) * 256 + y0) * 256 + x0;
        float2 xv0 = *(const float2*)&x[base];
        float2 xv1 = *(const float2*)&x[base + 256];
        float xa[2][2] = { { xv0.x, xv0.y }, { xv1.x, xv1.y } };
        float na[2][2] = { { nz0.x, nz0.y }, { nz1.x, nz1.y } };
        float oo[2][2];
        #pragma unroll
        for (int h = 0; h < 2; h++)
            #pragma unroll
            for (int w = 0; w < 2; w++) {
                float ag = 0.f, ab = 0.f;
                #pragma unroll
                for (int kk = 0; kk < 4; kk++) {
                    float2 gg = *(const float2*)&g_G4[rowb[h][w][kk] + (unsigned)co * 2u];
                    ag += gg.x; ab += gg.y;
                }
                float gf = ga * ag + (1.f - ga) * Yg[h][w] + cg;
                float bf = ba * ab + (1.f - ba) * Yb[h][w] + cb;
                float val = (xa[h][w] + na[h][w] * nv - mean) * rs;
                oo[h][w] = fmaf(val, gf, val + bf);
            }
        *(float2*)&out[base] = make_float2(oo[0][0], oo[0][1]);
        *(float2*)&out[base + 256] = make_float2(oo[1][0], oo[1][1]);
    }
}

// ----------------------------- launch -----------------------------
extern "C" void kernel_launch(void* const* d_in, const int* in_sizes, int n_in,
                              void* d_out, int out_size) {
    const float* x     = (const float*)d_in[0];
    const float* seg   = (const float*)d_in[1];
    const float* sc    = (const float*)d_in[2];
    const float* noise = (const float*)d_in[3];
    const float* nvar  = (const float*)d_in[4];
    const float* bg    = (const float*)d_in[5];
    const float* bb    = (const float*)d_in[6];
    const float* fcw   = (const float*)d_in[7];
    const float* fcb   = (const float*)d_in[8];
    const float* cgw   = (const float*)d_in[9];
    const float* cbw   = (const float*)d_in[11];
    const float* cgb   = (const float*)d_in[10];
    const float* cbb   = (const float*)d_in[12];
    const float* ssw   = (const float*)d_in[13];
    const float* ssb   = (const float*)d_in[14];
    const float* sgw   = (const float*)d_in[15];
    const float* sgb   = (const float*)d_in[16];
    const float* sbw   = (const float*)d_in[17];
    const float* sbb   = (const float*)d_in[18];
    float* out = (float*)d_out;

    k_prep<<<1279, 256>>>(bg, bb, cgb, cbb, sgb, sbb, sc, fcw, fcb, seg, ssw,
                          sgw, sbw, noise);
    k_stats<<<1024, 256>>>(x, nvar);
    k_lut1<<<160, 128>>>(cgw, cbw);
    k_actv<<<dim3(16, 64, 8), 256>>>(seg, ssb);
    // b=0 chain first so k_gemm is launch #6 for ncu
    k_vt<<<dim3(64, 128), 256>>>(0);
    k_gemm<<<dim3(128, 32), 256>>>();
    k_lut2<<<160, 256>>>();
    k_inv<<<dim3(64, 4), 256>>>(0, x, nvar, out);
    for (int b = 1; b < 8; b++) {
        k_vt<<<dim3(64, 128), 256>>>(b);
        k_gemm<<<dim3(128, 32), 256>>>();
        k_inv<<<dim3(64, 4), 256>>>(b, x, nvar, out);
    }
}

// round 13
// speedup vs baseline: 2.6963x; 1.1775x over previous
#include <cuda_runtime.h>
#include <cuda_fp16.h>
#include <cstdint>
#include <math.h>

#define B_ 8
#define C_ 128
#define HW (256*256)
typedef unsigned long long ull;

// ----------------------------- device scratch -----------------------------
__device__ __align__(16) float g_actv[(size_t)B_*C_*HW];      // 268MB
__device__ __align__(16) float g_V[(size_t)16*C_*16384];      // 134MB (per-b)
__device__ __align__(16) __half2 g_M[(size_t)16*C_*16384];    // 134MB (per-b, fp16 gb-pairs)
__device__ __align__(16) float g_U[16*C_*256];                // [k][ci][n]
__device__ __align__(16) float g_Wp[19*16*128];               // [j][slot][co]
__device__ float g_nT[(size_t)B_*HW];
__device__ float g_mean[B_*C_];
__device__ float g_rstd[B_*C_];
__device__ float g_mu[B_*20*64];
__device__ __align__(16) float g_G2[B_*20*9*C_*2];
__device__ __align__(16) float g_G4[B_*20*16*C_*2];
__device__ unsigned char g_cls[B_*128*128];
__device__ float g_Cg[C_], g_Cb[C_], g_scal[2];

// ----------------------------- helpers -----------------------------
__device__ __forceinline__ ull fma2(ull a, ull b, ull c) {
    ull d;
    asm("fma.rn.f32x2 %0, %1, %2, %3;" : "=l"(d) : "l"(a), "l"(b), "l"(c));
    return d;
}
__device__ __forceinline__ ull pack2(float x, float y) {
    ull d;
    asm("mov.b64 %0, {%1, %2};" : "=l"(d) : "f"(x), "f"(y));
    return d;
}
__device__ __forceinline__ uint32_t smem_u32(const void* p) {
    uint32_t a;
    asm("{ .reg .u64 t; cvta.to.shared.u64 t, %1; cvt.u32.u64 %0, t; }" : "=r"(a) : "l"(p));
    return a;
}
__device__ __forceinline__ void cpa16(uint32_t d, const void* g) {
    asm volatile("cp.async.ca.shared.global [%0], [%1], 16;" :: "r"(d), "l"(g) : "memory");
}
__device__ __forceinline__ void cp_commit() { asm volatile("cp.async.commit_group;" ::: "memory"); }
__device__ __forceinline__ void cp_wait0() { asm volatile("cp.async.wait_group 0;" ::: "memory"); }

// ----------------------------- launch #1: merged prep -----------------------------
// [0] scal | [1,41) mu | [41,553) cls | [553,705) Wp | [705,833) U | [833,1345) ntr
__global__ __launch_bounds__(256) void k_prep(
    const float* bg, const float* bb, const float* cgb, const float* cbb,
    const float* sgb, const float* sbb, const float* sc, const float* fcw,
    const float* fcb, const float* segmap, const float* ssw,
    const float* sgw, const float* sbw, const float* noise) {
    __shared__ float tsh[32][33];
    int bk = blockIdx.x, tid = threadIdx.x;
    if (bk == 0) {
        if (tid < 128) {
            float ga = 1.f / (1.f + expf(-bg[0]));
            float ba = 1.f / (1.f + expf(-bb[0]));
            g_Cg[tid] = ga * cgb[tid] + (1.f - ga) * sgb[tid];
            g_Cb[tid] = ba * cbb[tid] + (1.f - ba) * sbb[tid];
            if (tid == 0) { g_scal[0] = ga; g_scal[1] = ba; }
        }
    } else if (bk < 41) {
        int bj = (bk - 1) * 4 + (tid >> 6), o = tid & 63;
        int b = bj / 20, j = bj - b * 20;
        float r = 0.f;
        if (j < 19) {
            const float* s = sc + (b * 19 + j) * 64;
            const float* w = fcw + (j * 64 + o) * 64;
            #pragma unroll 8
            for (int i = 0; i < 64; i++) r = fmaf(s[i], w[i], r);
            r = fmaxf(r + fcb[j * 64 + o], 0.f);
        }
        g_mu[bj * 64 + o] = r;
    } else if (bk < 553) {
        int idx = (bk - 41) * 256 + tid;
        int b = idx >> 14, p = idx & 16383;
        int cls = 19;
        for (int j = 18; j >= 0; j--)
            if (segmap[(((size_t)b * 19 + j) << 14) + p] > 0.f) { cls = j; break; }
        g_cls[idx] = (unsigned char)cls;
    } else if (bk < 705) {
        int idx = (bk - 553) * 256 + tid;       // 19*16*128 = 38912
        if (idx < 38912) {
            int j = idx >> 11, rem = idx & 2047;
            int slot = rem >> 7, co = rem & 127;
            int ph = slot >> 3, pw = (slot >> 2) & 1, u = (slot >> 1) & 1, v = slot & 1;
            int ylo = (ph == 0) ? (u ? 0 : -1) : (u ? 1 : -1);
            int yhi = (ph == 0) ? (u ? 1 : -1) : (u ? 1 : 0);
            int xlo = (pw == 0) ? (v ? 0 : -1) : (v ? 1 : -1);
            int xhi = (pw == 0) ? (v ? 1 : -1) : (v ? 1 : 0);
            float s = 0.f;
            for (int dy = ylo; dy <= yhi; dy++)
                for (int dx = xlo; dx <= xhi; dx++)
                    s += ssw[(co * 19 + j) * 9 + (dy + 1) * 3 + (dx + 1)];
            g_Wp[idx] = s;
        }
    } else if (bk < 833) {
        int idx = (bk - 705) * 256 + tid;   // 32768 = 128ci x 256n
        int ci = idx >> 8, n = idx & 255;
        int co = n >> 1, sel = n & 1;
        const float* w = sel ? sbw : sgw;
        float g[3][3];
        #pragma unroll
        for (int t = 0; t < 9; t++) g[t / 3][t % 3] = w[(co * 128 + ci) * 9 + t];
        float r[4][3];
        #pragma unroll
        for (int j = 0; j < 3; j++) {
            r[0][j] = g[0][j];
            r[1][j] = (g[0][j] + g[1][j] + g[2][j]) * 0.5f;
            r[2][j] = (g[0][j] - g[1][j] + g[2][j]) * 0.5f;
            r[3][j] = g[2][j];
        }
        #pragma unroll
        for (int a = 0; a < 4; a++) {
            g_U[((a * 4 + 0) * 128 + ci) * 256 + n] = r[a][0];
            g_U[((a * 4 + 1) * 128 + ci) * 256 + n] = (r[a][0] + r[a][1] + r[a][2]) * 0.5f;
            g_U[((a * 4 + 2) * 128 + ci) * 256 + n] = (r[a][0] - r[a][1] + r[a][2]) * 0.5f;
            g_U[((a * 4 + 3) * 128 + ci) * 256 + n] = r[a][2];
        }
    } else {
        int bl = bk - 833;
        int b = bl >> 6, rem = bl & 63;
        int w0 = (rem & 7) * 32, h0 = (rem >> 3) * 32;
        int tx = tid & 31, ty = tid >> 5;
        for (int i = 0; i < 32; i += 8)
            tsh[ty + i][tx] = noise[((size_t)b * 256 + w0 + ty + i) * 256 + h0 + tx];
        __syncthreads();
        for (int i = 0; i < 32; i += 8)
            g_nT[((size_t)b * 256 + h0 + ty + i) * 256 + w0 + tx] = tsh[tx][ty + i];
    }
}

// ----------------------------- launch #2: stats -----------------------------
__global__ __launch_bounds__(256) void k_stats(const float* x, const float* nvar) {
    int bc = blockIdx.x;
    int b = bc >> 7, c = bc & 127;
    float nv = nvar[c];
    const float* xb = x + (size_t)bc * HW;
    const float* nb = g_nT + (size_t)b * HW;
    float s = 0.f, q = 0.f;
    for (int i = threadIdx.x; i < HW; i += 256) {
        float v = xb[i] + nb[i] * nv;
        s += v; q = fmaf(v, v, q);
    }
    __shared__ float ss[8], sq[8];
    #pragma unroll
    for (int o = 16; o; o >>= 1) {
        s += __shfl_xor_sync(0xffffffffu, s, o);
        q += __shfl_xor_sync(0xffffffffu, q, o);
    }
    int wid = threadIdx.x >> 5, lane = threadIdx.x & 31;
    if (!lane) { ss[wid] = s; sq[wid] = q; }
    __syncthreads();
    if (threadIdx.x == 0) {
        float S = 0.f, Q = 0.f;
        #pragma unroll
        for (int k = 0; k < 8; k++) { S += ss[k]; Q += sq[k]; }
        float m = S * (1.f / HW);
        g_mean[bc] = m;
        g_rstd[bc] = rsqrtf(Q * (1.f / HW) - m * m + 1e-5f);
    }
}

// ----------------------------- launch #3: LUT1 -----------------------------
__global__ __launch_bounds__(128) void k_lut1(const float* gw, const float* bw) {
    int bj = blockIdx.x, co = threadIdx.x;
    __shared__ float mu_s[64];
    if (co < 64) mu_s[co] = g_mu[bj * 64 + co];
    __syncthreads();
    for (int t = 0; t < 9; t++) {
        float sg = 0.f, sb = 0.f;
        #pragma unroll 8
        for (int ci = 0; ci < 64; ci++) {
            float m = mu_s[ci];
            sg = fmaf(gw[(co * 64 + ci) * 9 + t], m, sg);
            sb = fmaf(bw[(co * 64 + ci) * 9 + t], m, sb);
        }
        int o = ((bj * 9 + t) * 128 + co) * 2;
        g_G2[o] = sg; g_G2[o + 1] = sb;
    }
}

__global__ __launch_bounds__(256) void k_lut2() {
    int bj = blockIdx.x, n = threadIdx.x;
    const float* G = g_G2 + (size_t)bj * 9 * 256;
    float* O = g_G4 + (size_t)bj * 16 * 256;
    for (int ph = 0; ph < 2; ph++)
    for (int pw = 0; pw < 2; pw++)
    for (int u = 0; u < 2; u++)
    for (int v = 0; v < 2; v++) {
        int rlo = (u == 0) ? 0 : (ph == 0 ? 1 : 2);
        int rhi = (u == 0) ? (ph == 0 ? 0 : 1) : 2;
        int clo = (v == 0) ? 0 : (pw == 0 ? 1 : 2);
        int chi = (v == 0) ? (pw == 0 ? 0 : 1) : 2;
        float s = 0.f;
        for (int dy = rlo; dy <= rhi; dy++)
            for (int dx = clo; dx <= chi; dx++)
                s += G[(dy * 3 + dx) * 256 + n];
        O[(((ph * 2 + pw) * 2 + u) * 2 + v) * 256 + n] = s;
    }
}

// ----------------------------- launch #4: actv via parity LUT -----------------------------
__global__ __launch_bounds__(256, 2) void k_actv(const float* segmap, const float* ssb) {
    __shared__ float Sh[19][4][10];
    __shared__ __align__(16) float Wb[2][16][128];
    uint32_t Wb_u = smem_u32(Wb);
    int b = blockIdx.z;
    int x0 = blockIdx.x * 16, y0 = blockIdx.y * 4;
    int tid = threadIdx.x;
    int tx = tid & 15, ty = tid >> 4;
    int r = ty >> 2, c = (ty & 3) * 4;

    int hb = (y0 >> 1) - 1, cbh = (x0 >> 1) - 1;
    for (int idx = tid; idx < 19 * 40; idx += 256) {
        int j = idx / 40, pos = idx - j * 40;
        int hr = pos / 10, hc = pos - hr * 10;
        int gy = hb + hr, gx = cbh + hc;
        float v = 0.f;
        if ((unsigned)gy < 128u && (unsigned)gx < 128u)
            v = segmap[(((size_t)b * 19 + j) << 14) + gy * 128 + gx];
        Sh[j][hr][hc] = v;
    }

    int ph = r & 1;
    int row0 = (r >> 1) + ph;
    int col0 = c >> 1;

    ull acc[4][4];
    #pragma unroll
    for (int i = 0; i < 4; i++)
        #pragma unroll
        for (int q = 0; q < 4; q++) acc[i][q] = 0ull;

    auto issueW = [&](int j, int buf) {
        const float* src = g_Wp + j * 2048;
        #pragma unroll
        for (int k = 0; k < 2; k++) {
            int idx = tid * 2 + k;          // 0..511 float4
            cpa16(Wb_u + (uint32_t)(buf * 2048 + idx * 4) * 4u, src + idx * 4);
        }
        cp_commit();
    };

    issueW(0, 0);
    #pragma unroll 1
    for (int j = 0; j < 19; j++) {
        cp_wait0();
        __syncthreads();
        if (j + 1 < 19) issueW(j + 1, (j + 1) & 1);
        int buf = j & 1;
        float Sv[2][4];
        #pragma unroll
        for (int u = 0; u < 2; u++)
            #pragma unroll
            for (int v = 0; v < 4; v++) Sv[u][v] = Sh[j][row0 + u][col0 + v];
        ulonglong2 Wl[2][2][2][2];   // [pw][u][v][half]
        #pragma unroll
        for (int pw = 0; pw < 2; pw++)
            #pragma unroll
            for (int u = 0; u < 2; u++)
                #pragma unroll
                for (int v = 0; v < 2; v++) {
                    int slot = ((ph * 2 + pw) * 2 + u) * 2 + v;
                    Wl[pw][u][v][0] = *(const ulonglong2*)&Wb[buf][slot][tx * 4];
                    Wl[pw][u][v][1] = *(const ulonglong2*)&Wb[buf][slot][tx * 4 + 64];
                }
        #pragma unroll
        for (int i = 0; i < 4; i++) {
            int pw = i & 1, cb2 = (i >> 1) + (i & 1);
            #pragma unroll
            for (int u = 0; u < 2; u++)
                #pragma unroll
                for (int v = 0; v < 2; v++) {
                    float s = Sv[u][cb2 + v];
                    ull a = pack2(s, s);
                    acc[i][0] = fma2(a, Wl[pw][u][v][0].x, acc[i][0]);
                    acc[i][1] = fma2(a, Wl[pw][u][v][0].y, acc[i][1]);
                    acc[i][2] = fma2(a, Wl[pw][u][v][1].x, acc[i][2]);
                    acc[i][3] = fma2(a, Wl[pw][u][v][1].y, acc[i][3]);
                }
        }
        __syncthreads();
    }

    int y = y0 + r, xg0 = x0 + c;
    #pragma unroll
    for (int q = 0; q < 4; q++) {
        int co0 = (q < 2) ? (tx * 4 + q * 2) : (tx * 4 + 64 + (q - 2) * 2);
        #pragma unroll
        for (int h2 = 0; h2 < 2; h2++) {
            int co = co0 + h2;
            float bias = ssb[co];
            float4 o;
            float* op = (float*)&o;
            #pragma unroll
            for (int p = 0; p < 4; p++) {
                ull v = acc[p][q];
                unsigned w32 = h2 ? (unsigned)(v >> 32) : (unsigned)v;
                op[p] = fmaxf(__uint_as_float(w32) + bias, 0.f);
            }
            *(float4*)&g_actv[(((size_t)b * 128 + co) * 256 + y) * 256 + xg0] = o;
        }
    }
}

// ----------------------------- Winograd input transform -----------------------------
__global__ __launch_bounds__(256) void k_vt(int b) {
    __shared__ float sm[34][35];
    int tid = threadIdx.x;
    int ci = blockIdx.y;
    int y0 = (blockIdx.x >> 3) * 32, x0 = (blockIdx.x & 7) * 32;
    const float* src = g_actv + ((size_t)b * 128 + ci) * HW;
    for (int idx = tid; idx < 34 * 34; idx += 256) {
        int r = idx / 34, c = idx - r * 34;
        int gy = y0 - 1 + r, gx = x0 - 1 + c;
        float v = 0.f;
        if ((unsigned)gy < 256u && (unsigned)gx < 256u) v = src[gy * 256 + gx];
        sm[r][c] = v;
    }
    __syncthreads();
    int ty = tid >> 4, tx = tid & 15;
    float d[4][4];
    #pragma unroll
    for (int i = 0; i < 4; i++)
        #pragma unroll
        for (int j = 0; j < 4; j++) d[i][j] = sm[2 * ty + i][2 * tx + j];
    float t[4][4];
    #pragma unroll
    for (int j = 0; j < 4; j++) {
        t[0][j] = d[0][j] - d[2][j];
        t[1][j] = d[1][j] + d[2][j];
        t[2][j] = d[2][j] - d[1][j];
        t[3][j] = d[1][j] - d[3][j];
    }
    int gtile = ((y0 >> 1) + ty) * 128 + ((x0 >> 1) + tx);
    float* dst = g_V + (size_t)ci * 16384 + gtile;
    const size_t ks = (size_t)128 * 16384;
    #pragma unroll
    for (int a = 0; a < 4; a++) {
        dst[(a * 4 + 0) * ks] = t[a][0] - t[a][2];
        dst[(a * 4 + 1) * ks] = t[a][1] + t[a][2];
        dst[(a * 4 + 2) * ks] = t[a][2] - t[a][1];
        dst[(a * 4 + 3) * ks] = t[a][1] - t[a][3];
    }
}

// ----------------------------- batched GEMM -> fp16 M -----------------------------
__global__ __launch_bounds__(256, 2) void k_gemm() {
    __shared__ __align__(16) float As[2][16][128];
    __shared__ __align__(16) float Us[2][16][128];
    uint32_t As_u = smem_u32(As), Us_u = smem_u32(Us);
    int tid = threadIdx.x, mg = tid & 15, ng = tid >> 4;
    int mb = blockIdx.x;
    int k = blockIdx.y >> 1, nb = blockIdx.y & 1;
    const float* Vb = g_V + (size_t)k * 128 * 16384 + mb * 128;
    const float* Ub = g_U + k * 128 * 256 + nb * 128;

    ull acc[8][4];
    #pragma unroll
    for (int i = 0; i < 8; i++)
        #pragma unroll
        for (int c = 0; c < 4; c++) acc[i][c] = 0ull;

    auto issue = [&](int c, int buf) {
        #pragma unroll
        for (int j = 0; j < 2; j++) {
            int idx = tid * 2 + j;
            int row = idx >> 5, col = (idx & 31) * 4;
            cpa16(As_u + (uint32_t)((buf * 16 + row) * 128 + col) * 4u,
                  Vb + (size_t)(c * 16 + row) * 16384 + col);
            cpa16(Us_u + (uint32_t)((buf * 16 + row) * 128 + col) * 4u,
                  Ub + (size_t)(c * 16 + row) * 256 + col);
        }
        cp_commit();
    };

    issue(0, 0);
    #pragma unroll 1
    for (int c = 0; c < 8; c++) {
        cp_wait0();
        __syncthreads();
        if (c + 1 < 8) issue(c + 1, (c + 1) & 1);
        int buf = c & 1;
        #pragma unroll
        for (int ci = 0; ci < 16; ci++) {
            float4 a0 = *(const float4*)&As[buf][ci][mg * 8];
            float4 a1 = *(const float4*)&As[buf][ci][mg * 8 + 4];
            ulonglong2 u0 = *(const ulonglong2*)&Us[buf][ci][ng * 8];
            ulonglong2 u1 = *(const ulonglong2*)&Us[buf][ci][ng * 8 + 4];
            ull ap[8];
            ap[0] = pack2(a0.x, a0.x); ap[1] = pack2(a0.y, a0.y);
            ap[2] = pack2(a0.z, a0.z); ap[3] = pack2(a0.w, a0.w);
            ap[4] = pack2(a1.x, a1.x); ap[5] = pack2(a1.y, a1.y);
            ap[6] = pack2(a1.z, a1.z); ap[7] = pack2(a1.w, a1.w);
            #pragma unroll
            for (int i = 0; i < 8; i++) {
                acc[i][0] = fma2(ap[i], u0.x, acc[i][0]);
                acc[i][1] = fma2(ap[i], u0.y, acc[i][1]);
                acc[i][2] = fma2(ap[i], u1.x, acc[i][2]);
                acc[i][3] = fma2(ap[i], u1.y, acc[i][3]);
            }
        }
        __syncthreads();
    }
    #pragma unroll
    for (int c = 0; c < 4; c++) {
        int co = nb * 64 + ng * 4 + c;
        union { __half2 h[8]; uint4 u[2]; } pk;
        #pragma unroll
        for (int i = 0; i < 8; i++) {
            ull v = acc[i][c];
            float2 f = make_float2(__uint_as_float((unsigned)v),
                                   __uint_as_float((unsigned)(v >> 32)));
            pk.h[i] = __float22half2_rn(f);
        }
        __half2* Mr = g_M + ((size_t)k * 128 + co) * 16384 + mb * 128 + mg * 8;
        *(uint4*)(Mr + 0) = pk.u[0];
        *(uint4*)(Mr + 4) = pk.u[1];
    }
}

// ----------------------------- inverse transform + fused epilogue -----------------------------
__global__ __launch_bounds__(256) void k_inv(int b, const float* __restrict__ x,
                                             const float* __restrict__ nvar,
                                             float* __restrict__ out) {
    int tid = threadIdx.x;
    int gtile = blockIdx.x * 256 + tid;
    int ty = gtile >> 7, tx = gtile & 127;
    int co0 = blockIdx.y * 32;

    int cls9[3][3];
    #pragma unroll
    for (int i = 0; i < 3; i++)
        #pragma unroll
        for (int j = 0; j < 3; j++) {
            int cy = ty - 1 + i, cx = tx - 1 + j;
            int cls = 19;
            if ((unsigned)cy < 128u && (unsigned)cx < 128u)
                cls = g_cls[((size_t)b << 14) + cy * 128 + cx];
            cls9[i][j] = cls;
        }
    unsigned rowb[2][2][4];
    #pragma unroll
    for (int h = 0; h < 2; h++)
        #pragma unroll
        for (int w = 0; w < 2; w++)
            #pragma unroll
            for (int u = 0; u < 2; u++)
                #pragma unroll
                for (int v = 0; v < 2; v++)
                    rowb[h][w][u * 2 + v] =
                        (unsigned)(((((b * 20 + cls9[h + u][w + v]) * 2 + h) * 2 + w) * 2 + u) * 2 + v) * 256u;
    int y0 = 2 * ty, x0 = 2 * tx;
    float2 nz0 = *(const float2*)&g_nT[((size_t)b * 256 + y0) * 256 + x0];
    float2 nz1 = *(const float2*)&g_nT[((size_t)b * 256 + y0 + 1) * 256 + x0];
    float ga = g_scal[0], ba = g_scal[1];
    const size_t ks = (size_t)128 * 16384;

    #pragma unroll 1
    for (int ic = 0; ic < 32; ic++) {
        int co = co0 + ic;
        const __half2* Mp = g_M + (size_t)co * 16384 + gtile;
        float2 Mv[16];
        #pragma unroll
        for (int k = 0; k < 16; k++) Mv[k] = __half22float2(Mp[(size_t)k * ks]);
        float tg[2][4], tb[2][4];
        #pragma unroll
        for (int j = 0; j < 4; j++) {
            tg[0][j] = Mv[j].x + Mv[4 + j].x + Mv[8 + j].x;
            tg[1][j] = Mv[4 + j].x - Mv[8 + j].x - Mv[12 + j].x;
            tb[0][j] = Mv[j].y + Mv[4 + j].y + Mv[8 + j].y;
            tb[1][j] = Mv[4 + j].y - Mv[8 + j].y - Mv[12 + j].y;
        }
        float Yg[2][2], Yb[2][2];
        #pragma unroll
        for (int h = 0; h < 2; h++) {
            Yg[h][0] = tg[h][0] + tg[h][1] + tg[h][2];
            Yg[h][1] = tg[h][1] - tg[h][2] - tg[h][3];
            Yb[h][0] = tb[h][0] + tb[h][1] + tb[h][2];
            Yb[h][1] = tb[h][1] - tb[h][2] - tb[h][3];
        }
        float mean = g_mean[b * 128 + co];
        float rs = g_rstd[b * 128 + co];
        float nv = nvar[co];
        float cg = g_Cg[co], cb = g_Cb[co];
        size_t base = (((size_t)b * 128 + co) * 256 + y0) * 256 + x0;
        float2 xv0 = *(const float2*)&x[base];
        float2 xv1 = *(const float2*)&x[base + 256];
        float xa[2][2] = { { xv0.x, xv0.y }, { xv1.x, xv1.y } };
        float na[2][2] = { { nz0.x, nz0.y }, { nz1.x, nz1.y } };
        float oo[2][2];
        #pragma unroll
        for (int h = 0; h < 2; h++)
            #pragma unroll
            for (int w = 0; w < 2; w++) {
                float ag = 0.f, ab = 0.f;
                #pragma unroll
                for (int kk = 0; kk < 4; kk++) {
                    float2 gg = *(const float2*)&g_G4[rowb[h][w][kk] + (unsigned)co * 2u];
                    ag += gg.x; ab += gg.y;
                }
                float gf = ga * ag + (1.f - ga) * Yg[h][w] + cg;
                float bf = ba * ab + (1.f - ba) * Yb[h][w] + cb;
                float val = (xa[h][w] + na[h][w] * nv - mean) * rs;
                oo[h][w] = fmaf(val, gf, val + bf);
            }
        *(float2*)&out[base] = make_float2(oo[0][0], oo[0][1]);
        *(float2*)&out[base + 256] = make_float2(oo[1][0], oo[1][1]);
    }
}

// ----------------------------- launch -----------------------------
extern "C" void kernel_launch(void* const* d_in, const int* in_sizes, int n_in,
                              void* d_out, int out_size) {
    const float* x     = (const float*)d_in[0];
    const float* seg   = (const float*)d_in[1];
    const float* sc    = (const float*)d_in[2];
    const float* noise = (const float*)d_in[3];
    const float* nvar  = (const float*)d_in[4];
    const float* bg    = (const float*)d_in[5];
    const float* bb    = (const float*)d_in[6];
    const float* fcw   = (const float*)d_in[7];
    const float* fcb   = (const float*)d_in[8];
    const float* cgw   = (const float*)d_in[9];
    const float* cgb   = (const float*)d_in[10];
    const float* cbw   = (const float*)d_in[11];
    const float* ssw   = (const float*)d_in[13];
    const float* ssb   = (const float*)d_in[14];
    const float* sgw   = (const float*)d_in[15];
    const float* sbw   = (const float*)d_in[17];
    float* out = (float*)d_out;

    k_prep<<<1345, 256>>>(bg, bb, cgb, (const float*)d_in[12], (const float*)d_in[16],
                          (const float*)d_in[18], sc, fcw, fcb, seg, ssw, sgw, sbw, noise);
    k_stats<<<1024, 256>>>(x, nvar);
    k_lut1<<<160, 128>>>(cgw, cbw);
    k_actv<<<dim3(16, 64, 8), 256>>>(seg, ssb);
    k_vt<<<dim3(64, 128), 256>>>(0);
    k_gemm<<<dim3(128, 32), 256>>>();
    k_lut2<<<160, 256>>>();
    k_inv<<<dim3(64, 4), 256>>>(0, x, nvar, out);
    for (int b = 1; b < 8; b++) {
        k_vt<<<dim3(64, 128), 256>>>(b);
        k_gemm<<<dim3(128, 32), 256>>>();
        k_inv<<<dim3(64, 4), 256>>>(b, x, nvar, out);
    }
}

// round 14
// speedup vs baseline: 4.0051x; 1.4854x over previous
#include <cuda_runtime.h>
#include <cstdint>
#include <math.h>

#define B_ 8
#define C_ 128
#define HW (256*256)
typedef unsigned long long ull;

// ----------------------------- device scratch -----------------------------
__device__ __align__(16) float g_actv[(size_t)B_*C_*HW];          // 268MB
__device__ __align__(16) float g_V[(size_t)36*B_*C_*4096];        // 604MB [k][b][ci][tile]
__device__ __align__(16) float g_M[(size_t)36*B_*C_*4096*2];      // 1.21GB [k][b][co][tile]{g,b}
__device__ __align__(16) float g_U[36*C_*256];                    // [k][ci][n]
__device__ __align__(16) float g_Wp[19*16*128];                   // [j][slot][co]
__device__ float g_nT[(size_t)B_*HW];
__device__ float g_mean[B_*C_];
__device__ float g_rstd[B_*C_];
__device__ float g_mu[B_*20*64];
__device__ __align__(16) float g_G2[B_*20*9*C_*2];
__device__ __align__(16) float g_G4[B_*20*16*C_*2];
__device__ unsigned char g_cls[B_*128*128];
__device__ float g_Cg[C_], g_Cb[C_], g_scal[2];

// ----------------------------- helpers -----------------------------
__device__ __forceinline__ ull fma2(ull a, ull b, ull c) {
    ull d;
    asm("fma.rn.f32x2 %0, %1, %2, %3;" : "=l"(d) : "l"(a), "l"(b), "l"(c));
    return d;
}
__device__ __forceinline__ ull pack2(float x, float y) {
    ull d;
    asm("mov.b64 %0, {%1, %2};" : "=l"(d) : "f"(x), "f"(y));
    return d;
}
__device__ __forceinline__ uint32_t smem_u32(const void* p) {
    uint32_t a;
    asm("{ .reg .u64 t; cvta.to.shared.u64 t, %1; cvt.u32.u64 %0, t; }" : "=r"(a) : "l"(p));
    return a;
}
__device__ __forceinline__ void cpa16(uint32_t d, const void* g) {
    asm volatile("cp.async.ca.shared.global [%0], [%1], 16;" :: "r"(d), "l"(g) : "memory");
}
__device__ __forceinline__ void cp_commit() { asm volatile("cp.async.commit_group;" ::: "memory"); }
__device__ __forceinline__ void cp_wait0() { asm volatile("cp.async.wait_group 0;" ::: "memory"); }
__device__ __forceinline__ float2 f2add(float2 a, float2 b) { return make_float2(a.x + b.x, a.y + b.y); }
__device__ __forceinline__ float2 f2sub(float2 a, float2 b) { return make_float2(a.x - b.x, a.y - b.y); }
__device__ __forceinline__ float2 f2fma(float k, float2 a, float2 b) {
    return make_float2(fmaf(k, a.x, b.x), fmaf(k, a.y, b.y));
}

// ----------------------------- launch #1: merged prep -----------------------------
// [0] scal | [1,41) mu | [41,553) cls | [553,705) Wp | [705,833) U | [833,1345) ntr
__global__ __launch_bounds__(256) void k_prep(
    const float* bg, const float* bb, const float* cgb, const float* cbb,
    const float* sgb, const float* sbb, const float* sc, const float* fcw,
    const float* fcb, const float* segmap, const float* ssw,
    const float* sgw, const float* sbw, const float* noise) {
    __shared__ float tsh[32][33];
    int bk = blockIdx.x, tid = threadIdx.x;
    if (bk == 0) {
        if (tid < 128) {
            float ga = 1.f / (1.f + expf(-bg[0]));
            float ba = 1.f / (1.f + expf(-bb[0]));
            g_Cg[tid] = ga * cgb[tid] + (1.f - ga) * sgb[tid];
            g_Cb[tid] = ba * cbb[tid] + (1.f - ba) * sbb[tid];
            if (tid == 0) { g_scal[0] = ga; g_scal[1] = ba; }
        }
    } else if (bk < 41) {
        int bj = (bk - 1) * 4 + (tid >> 6), o = tid & 63;
        int b = bj / 20, j = bj - b * 20;
        float r = 0.f;
        if (j < 19) {
            const float* s = sc + (b * 19 + j) * 64;
            const float* w = fcw + (j * 64 + o) * 64;
            #pragma unroll 8
            for (int i = 0; i < 64; i++) r = fmaf(s[i], w[i], r);
            r = fmaxf(r + fcb[j * 64 + o], 0.f);
        }
        g_mu[bj * 64 + o] = r;
    } else if (bk < 553) {
        int idx = (bk - 41) * 256 + tid;
        int b = idx >> 14, p = idx & 16383;
        int cls = 19;
        for (int j = 18; j >= 0; j--)
            if (segmap[(((size_t)b * 19 + j) << 14) + p] > 0.f) { cls = j; break; }
        g_cls[idx] = (unsigned char)cls;
    } else if (bk < 705) {
        int idx = (bk - 553) * 256 + tid;       // 19*16*128 = 38912
        if (idx < 38912) {
            int j = idx >> 11, rem = idx & 2047;
            int slot = rem >> 7, co = rem & 127;
            int ph = slot >> 3, pw = (slot >> 2) & 1, u = (slot >> 1) & 1, v = slot & 1;
            int ylo = (ph == 0) ? (u ? 0 : -1) : (u ? 1 : -1);
            int yhi = (ph == 0) ? (u ? 1 : -1) : (u ? 1 : 0);
            int xlo = (pw == 0) ? (v ? 0 : -1) : (v ? 1 : -1);
            int xhi = (pw == 0) ? (v ? 1 : -1) : (v ? 1 : 0);
            float s = 0.f;
            for (int dy = ylo; dy <= yhi; dy++)
                for (int dx = xlo; dx <= xhi; dx++)
                    s += ssw[(co * 19 + j) * 9 + (dy + 1) * 3 + (dx + 1)];
            g_Wp[idx] = s;
        }
    } else if (bk < 833) {
        int idx = (bk - 705) * 256 + tid;   // 32768 = 128ci x 256n
        int ci = idx >> 8, n = idx & 255;
        int co = n >> 1, sel = n & 1;
        const float* w = sel ? sbw : sgw;
        float g[3][3];
        #pragma unroll
        for (int t = 0; t < 9; t++) g[t / 3][t % 3] = w[(co * 128 + ci) * 9 + t];
        // t = G g  (G: 6x3 Lavin F(4,3))
        float t6[6][3];
        #pragma unroll
        for (int c = 0; c < 3; c++) {
            t6[0][c] = 0.25f * g[0][c];
            t6[1][c] = -(g[0][c] + g[1][c] + g[2][c]) * (1.f / 6.f);
            t6[2][c] = (-g[0][c] + g[1][c] - g[2][c]) * (1.f / 6.f);
            t6[3][c] = g[0][c] * (1.f / 24.f) + g[1][c] * (1.f / 12.f) + g[2][c] * (1.f / 6.f);
            t6[4][c] = g[0][c] * (1.f / 24.f) - g[1][c] * (1.f / 12.f) + g[2][c] * (1.f / 6.f);
            t6[5][c] = g[2][c];
        }
        #pragma unroll
        for (int i = 0; i < 6; i++) {
            float a = t6[i][0], bb2 = t6[i][1], c2 = t6[i][2];
            float u6[6];
            u6[0] = 0.25f * a;
            u6[1] = -(a + bb2 + c2) * (1.f / 6.f);
            u6[2] = (-a + bb2 - c2) * (1.f / 6.f);
            u6[3] = a * (1.f / 24.f) + bb2 * (1.f / 12.f) + c2 * (1.f / 6.f);
            u6[4] = a * (1.f / 24.f) - bb2 * (1.f / 12.f) + c2 * (1.f / 6.f);
            u6[5] = c2;
            #pragma unroll
            for (int kk = 0; kk < 6; kk++)
                g_U[((i * 6 + kk) * 128 + ci) * 256 + n] = u6[kk];
        }
    } else {
        int bl = bk - 833;
        int b = bl >> 6, rem = bl & 63;
        int w0 = (rem & 7) * 32, h0 = (rem >> 3) * 32;
        int tx = tid & 31, ty = tid >> 5;
        for (int i = 0; i < 32; i += 8)
            tsh[ty + i][tx] = noise[((size_t)b * 256 + w0 + ty + i) * 256 + h0 + tx];
        __syncthreads();
        for (int i = 0; i < 32; i += 8)
            g_nT[((size_t)b * 256 + h0 + ty + i) * 256 + w0 + tx] = tsh[tx][ty + i];
    }
}

// ----------------------------- launch #2: stats -----------------------------
__global__ __launch_bounds__(256) void k_stats(const float* x, const float* nvar) {
    int bc = blockIdx.x;
    int b = bc >> 7, c = bc & 127;
    float nv = nvar[c];
    const float* xb = x + (size_t)bc * HW;
    const float* nb = g_nT + (size_t)b * HW;
    float s = 0.f, q = 0.f;
    for (int i = threadIdx.x; i < HW; i += 256) {
        float v = xb[i] + nb[i] * nv;
        s += v; q = fmaf(v, v, q);
    }
    __shared__ float ss[8], sq[8];
    #pragma unroll
    for (int o = 16; o; o >>= 1) {
        s += __shfl_xor_sync(0xffffffffu, s, o);
        q += __shfl_xor_sync(0xffffffffu, q, o);
    }
    int wid = threadIdx.x >> 5, lane = threadIdx.x & 31;
    if (!lane) { ss[wid] = s; sq[wid] = q; }
    __syncthreads();
    if (threadIdx.x == 0) {
        float S = 0.f, Q = 0.f;
        #pragma unroll
        for (int k = 0; k < 8; k++) { S += ss[k]; Q += sq[k]; }
        float m = S * (1.f / HW);
        g_mean[bc] = m;
        g_rstd[bc] = rsqrtf(Q * (1.f / HW) - m * m + 1e-5f);
    }
}

// ----------------------------- LUTs -----------------------------
__global__ __launch_bounds__(128) void k_lut1(const float* gw, const float* bw) {
    int bj = blockIdx.x, co = threadIdx.x;
    __shared__ float mu_s[64];
    if (co < 64) mu_s[co] = g_mu[bj * 64 + co];
    __syncthreads();
    for (int t = 0; t < 9; t++) {
        float sg = 0.f, sb = 0.f;
        #pragma unroll 8
        for (int ci = 0; ci < 64; ci++) {
            float m = mu_s[ci];
            sg = fmaf(gw[(co * 64 + ci) * 9 + t], m, sg);
            sb = fmaf(bw[(co * 64 + ci) * 9 + t], m, sb);
        }
        int o = ((bj * 9 + t) * 128 + co) * 2;
        g_G2[o] = sg; g_G2[o + 1] = sb;
    }
}

__global__ __launch_bounds__(256) void k_lut2() {
    int bj = blockIdx.x, n = threadIdx.x;
    const float* G = g_G2 + (size_t)bj * 9 * 256;
    float* O = g_G4 + (size_t)bj * 16 * 256;
    for (int ph = 0; ph < 2; ph++)
    for (int pw = 0; pw < 2; pw++)
    for (int u = 0; u < 2; u++)
    for (int v = 0; v < 2; v++) {
        int rlo = (u == 0) ? 0 : (ph == 0 ? 1 : 2);
        int rhi = (u == 0) ? (ph == 0 ? 0 : 1) : 2;
        int clo = (v == 0) ? 0 : (pw == 0 ? 1 : 2);
        int chi = (v == 0) ? (pw == 0 ? 0 : 1) : 2;
        float s = 0.f;
        for (int dy = rlo; dy <= rhi; dy++)
            for (int dx = clo; dx <= chi; dx++)
                s += G[(dy * 3 + dx) * 256 + n];
        O[(((ph * 2 + pw) * 2 + u) * 2 + v) * 256 + n] = s;
    }
}

// ----------------------------- actv via parity LUT (unchanged from R12) ---------------
__global__ __launch_bounds__(256, 2) void k_actv(const float* segmap, const float* ssb) {
    __shared__ float Sh[19][4][10];
    __shared__ __align__(16) float Wb[2][16][128];
    uint32_t Wb_u = smem_u32(Wb);
    int b = blockIdx.z;
    int x0 = blockIdx.x * 16, y0 = blockIdx.y * 4;
    int tid = threadIdx.x;
    int tx = tid & 15, ty = tid >> 4;
    int r = ty >> 2, c = (ty & 3) * 4;

    int hb = (y0 >> 1) - 1, cbh = (x0 >> 1) - 1;
    for (int idx = tid; idx < 19 * 40; idx += 256) {
        int j = idx / 40, pos = idx - j * 40;
        int hr = pos / 10, hc = pos - hr * 10;
        int gy = hb + hr, gx = cbh + hc;
        float v = 0.f;
        if ((unsigned)gy < 128u && (unsigned)gx < 128u)
            v = segmap[(((size_t)b * 19 + j) << 14) + gy * 128 + gx];
        Sh[j][hr][hc] = v;
    }
    int ph = r & 1;
    int row0 = (r >> 1) + ph;
    int col0 = c >> 1;

    ull acc[4][4];
    #pragma unroll
    for (int i = 0; i < 4; i++)
        #pragma unroll
        for (int q = 0; q < 4; q++) acc[i][q] = 0ull;

    auto issueW = [&](int j, int buf) {
        const float* src = g_Wp + j * 2048;
        #pragma unroll
        for (int k = 0; k < 2; k++) {
            int idx = tid * 2 + k;
            cpa16(Wb_u + (uint32_t)(buf * 2048 + idx * 4) * 4u, src + idx * 4);
        }
        cp_commit();
    };

    issueW(0, 0);
    #pragma unroll 1
    for (int j = 0; j < 19; j++) {
        cp_wait0();
        __syncthreads();
        if (j + 1 < 19) issueW(j + 1, (j + 1) & 1);
        int buf = j & 1;
        float Sv[2][4];
        #pragma unroll
        for (int u = 0; u < 2; u++)
            #pragma unroll
            for (int v = 0; v < 4; v++) Sv[u][v] = Sh[j][row0 + u][col0 + v];
        ulonglong2 Wl[2][2][2][2];
        #pragma unroll
        for (int pw = 0; pw < 2; pw++)
            #pragma unroll
            for (int u = 0; u < 2; u++)
                #pragma unroll
                for (int v = 0; v < 2; v++) {
                    int slot = ((ph * 2 + pw) * 2 + u) * 2 + v;
                    Wl[pw][u][v][0] = *(const ulonglong2*)&Wb[buf][slot][tx * 4];
                    Wl[pw][u][v][1] = *(const ulonglong2*)&Wb[buf][slot][tx * 4 + 64];
                }
        #pragma unroll
        for (int i = 0; i < 4; i++) {
            int pw = i & 1, cb2 = (i >> 1) + (i & 1);
            #pragma unroll
            for (int u = 0; u < 2; u++)
                #pragma unroll
                for (int v = 0; v < 2; v++) {
                    float s = Sv[u][cb2 + v];
                    ull a = pack2(s, s);
                    acc[i][0] = fma2(a, Wl[pw][u][v][0].x, acc[i][0]);
                    acc[i][1] = fma2(a, Wl[pw][u][v][0].y, acc[i][1]);
                    acc[i][2] = fma2(a, Wl[pw][u][v][1].x, acc[i][2]);
                    acc[i][3] = fma2(a, Wl[pw][u][v][1].y, acc[i][3]);
                }
        }
        __syncthreads();
    }

    int y = y0 + r, xg0 = x0 + c;
    #pragma unroll
    for (int q = 0; q < 4; q++) {
        int co0 = (q < 2) ? (tx * 4 + q * 2) : (tx * 4 + 64 + (q - 2) * 2);
        #pragma unroll
        for (int h2 = 0; h2 < 2; h2++) {
            int co = co0 + h2;
            float bias = ssb[co];
            float4 o;
            float* op = (float*)&o;
            #pragma unroll
            for (int p = 0; p < 4; p++) {
                ull v = acc[p][q];
                unsigned w32 = h2 ? (unsigned)(v >> 32) : (unsigned)v;
                op[p] = fmaxf(__uint_as_float(w32) + bias, 0.f);
            }
            *(float4*)&g_actv[(((size_t)b * 128 + co) * 256 + y) * 256 + xg0] = o;
        }
    }
}

// ----------------------------- F(4,3) input transform V = Bt d B -----------------------
// grid (16 regions, 128 ci, 8 b); region = 16x16 tiles = 64x64 px, halo 66x66.
__global__ __launch_bounds__(256) void k_vt() {
    __shared__ float sm[66][68];
    int tid = threadIdx.x;
    int ci = blockIdx.y, b = blockIdx.z;
    int ry = blockIdx.x >> 2, rx = blockIdx.x & 3;
    int y0 = ry * 64, x0 = rx * 64;
    const float* src = g_actv + ((size_t)b * 128 + ci) * HW;
    for (int idx = tid; idx < 66 * 66; idx += 256) {
        int r = idx / 66, c = idx - r * 66;
        int gy = y0 - 1 + r, gx = x0 - 1 + c;
        float v = 0.f;
        if ((unsigned)gy < 256u && (unsigned)gx < 256u) v = src[gy * 256 + gx];
        sm[r][c] = v;
    }
    __syncthreads();
    int ty = tid >> 4, tx = tid & 15;
    float t6[6][6];
    // t = BT d, column-wise
    #pragma unroll
    for (int j = 0; j < 6; j++) {
        float d0 = sm[4 * ty + 0][4 * tx + j], d1 = sm[4 * ty + 1][4 * tx + j];
        float d2 = sm[4 * ty + 2][4 * tx + j], d3 = sm[4 * ty + 3][4 * tx + j];
        float d4 = sm[4 * ty + 4][4 * tx + j], d5 = sm[4 * ty + 5][4 * tx + j];
        t6[0][j] = 4.f * d0 - 5.f * d2 + d4;
        t6[1][j] = -4.f * (d1 + d2) + d3 + d4;
        t6[2][j] = 4.f * (d1 - d2) - d3 + d4;
        t6[3][j] = -2.f * d1 - d2 + 2.f * d3 + d4;
        t6[4][j] = 2.f * d1 - d2 - 2.f * d3 + d4;
        t6[5][j] = 4.f * d1 - 5.f * d3 + d5;
    }
    int gtile = (ry * 16 + ty) * 64 + rx * 16 + tx;
    float* dst = g_V + ((size_t)b * 128 + ci) * 4096 + gtile;
    const size_t ks = (size_t)8 * 128 * 4096;
    #pragma unroll
    for (int i = 0; i < 6; i++) {
        float s0 = t6[i][0], s1 = t6[i][1], s2 = t6[i][2];
        float s3 = t6[i][3], s4 = t6[i][4], s5 = t6[i][5];
        dst[(size_t)(i * 6 + 0) * ks] = 4.f * s0 - 5.f * s2 + s4;
        dst[(size_t)(i * 6 + 1) * ks] = -4.f * (s1 + s2) + s3 + s4;
        dst[(size_t)(i * 6 + 2) * ks] = 4.f * (s1 - s2) - s3 + s4;
        dst[(size_t)(i * 6 + 3) * ks] = -2.f * s1 - s2 + 2.f * s3 + s4;
        dst[(size_t)(i * 6 + 4) * ks] = 2.f * s1 - s2 - 2.f * s3 + s4;
        dst[(size_t)(i * 6 + 5) * ks] = 4.f * s1 - 5.f * s3 + s5;
    }
}

// ----------------------------- 36x batched GEMM -> fp32 M ---------------------------
// grid (32 mb, 72 = k*2+nb, 8 b). CTA 128 tiles x 128 n.
__global__ __launch_bounds__(256, 2) void k_gemm() {
    __shared__ __align__(16) float As[2][16][128];
    __shared__ __align__(16) float Us[2][16][128];
    uint32_t As_u = smem_u32(As), Us_u = smem_u32(Us);
    int tid = threadIdx.x, mg = tid & 15, ng = tid >> 4;
    int mb = blockIdx.x;
    int k = blockIdx.y >> 1, nb = blockIdx.y & 1;
    int b = blockIdx.z;
    const float* Vb = g_V + ((size_t)(k * 8 + b) * 128) * 4096 + mb * 128;
    const float* Ub = g_U + (size_t)k * 128 * 256 + nb * 128;

    ull acc[8][4];
    #pragma unroll
    for (int i = 0; i < 8; i++)
        #pragma unroll
        for (int c = 0; c < 4; c++) acc[i][c] = 0ull;

    auto issue = [&](int c, int buf) {
        #pragma unroll
        for (int j = 0; j < 2; j++) {
            int idx = tid * 2 + j;
            int row = idx >> 5, col = (idx & 31) * 4;
            cpa16(As_u + (uint32_t)((buf * 16 + row) * 128 + col) * 4u,
                  Vb + (size_t)(c * 16 + row) * 4096 + col);
            cpa16(Us_u + (uint32_t)((buf * 16 + row) * 128 + col) * 4u,
                  Ub + (size_t)(c * 16 + row) * 256 + col);
        }
        cp_commit();
    };

    issue(0, 0);
    #pragma unroll 1
    for (int c = 0; c < 8; c++) {
        cp_wait0();
        __syncthreads();
        if (c + 1 < 8) issue(c + 1, (c + 1) & 1);
        int buf = c & 1;
        #pragma unroll
        for (int ci = 0; ci < 16; ci++) {
            float4 a0 = *(const float4*)&As[buf][ci][mg * 8];
            float4 a1 = *(const float4*)&As[buf][ci][mg * 8 + 4];
            ulonglong2 u0 = *(const ulonglong2*)&Us[buf][ci][ng * 8];
            ulonglong2 u1 = *(const ulonglong2*)&Us[buf][ci][ng * 8 + 4];
            ull ap[8];
            ap[0] = pack2(a0.x, a0.x); ap[1] = pack2(a0.y, a0.y);
            ap[2] = pack2(a0.z, a0.z); ap[3] = pack2(a0.w, a0.w);
            ap[4] = pack2(a1.x, a1.x); ap[5] = pack2(a1.y, a1.y);
            ap[6] = pack2(a1.z, a1.z); ap[7] = pack2(a1.w, a1.w);
            #pragma unroll
            for (int i = 0; i < 8; i++) {
                acc[i][0] = fma2(ap[i], u0.x, acc[i][0]);
                acc[i][1] = fma2(ap[i], u0.y, acc[i][1]);
                acc[i][2] = fma2(ap[i], u1.x, acc[i][2]);
                acc[i][3] = fma2(ap[i], u1.y, acc[i][3]);
            }
        }
        __syncthreads();
    }
    #pragma unroll
    for (int c = 0; c < 4; c++) {
        int co = nb * 64 + ng * 4 + c;
        ull* Mr = (ull*)g_M + ((size_t)(k * 8 + b) * 128 + co) * 4096 + mb * 128 + mg * 8;
        ulonglong2 s0, s1, s2, s3;
        s0.x = acc[0][c]; s0.y = acc[1][c];
        s1.x = acc[2][c]; s1.y = acc[3][c];
        s2.x = acc[4][c]; s2.y = acc[5][c];
        s3.x = acc[6][c]; s3.y = acc[7][c];
        *(ulonglong2*)(Mr + 0) = s0;
        *(ulonglong2*)(Mr + 2) = s1;
        *(ulonglong2*)(Mr + 4) = s2;
        *(ulonglong2*)(Mr + 6) = s3;
    }
}

// ----------------------------- inverse transform + fused epilogue -------------------
// grid (16, 4, 8): thread = one 4x4 output tile, loop 32 co.
__global__ __launch_bounds__(256) void k_inv(const float* __restrict__ x,
                                             const float* __restrict__ nvar,
                                             float* __restrict__ out) {
    int tid = threadIdx.x;
    int b = blockIdx.z;
    int tile = blockIdx.x * 256 + tid;
    int ty = tile >> 6, tx = tile & 63;
    int co0 = blockIdx.y * 32;
    int y0 = 4 * ty, x0 = 4 * tx;

    int cls16[4][4];
    #pragma unroll
    for (int i = 0; i < 4; i++)
        #pragma unroll
        for (int j = 0; j < 4; j++) {
            int cy = 2 * ty - 1 + i, cx = 2 * tx - 1 + j;
            int cls = 19;
            if ((unsigned)cy < 128u && (unsigned)cx < 128u)
                cls = g_cls[((size_t)b << 14) + cy * 128 + cx];
            cls16[i][j] = cls;
        }
    float nz[4][4];
    #pragma unroll
    for (int rr = 0; rr < 4; rr++)
        *(float4*)nz[rr] = *(const float4*)&g_nT[((size_t)b * 256 + y0 + rr) * 256 + x0];
    float ga = g_scal[0], ba = g_scal[1];
    const size_t ks = (size_t)8 * 128 * 4096;
    const float c1t[6] = {0.f, 1.f, -1.f, 2.f, -2.f, 0.f};
    const float c2t[6] = {0.f, 1.f, 1.f, 4.f, 4.f, 0.f};
    const float c3t[6] = {0.f, 1.f, -1.f, 8.f, -8.f, 1.f};

    #pragma unroll 1
    for (int ic = 0; ic < 32; ic++) {
        int co = co0 + ic;
        const float2* Mp = (const float2*)g_M + ((size_t)b * 128 + co) * 4096 + tile;
        float2 Y[4][4];
        #pragma unroll
        for (int h = 0; h < 4; h++)
            #pragma unroll
            for (int w = 0; w < 4; w++) Y[h][w] = make_float2(0.f, 0.f);
        #pragma unroll
        for (int i = 0; i < 6; i++) {
            float2 m[6];
            #pragma unroll
            for (int j = 0; j < 6; j++) m[j] = Mp[(size_t)(i * 6 + j) * ks];
            float2 s12 = f2add(m[1], m[2]), d12 = f2sub(m[1], m[2]);
            float2 s34 = f2add(m[3], m[4]), d34 = f2sub(m[3], m[4]);
            float2 P[4];
            P[0] = f2add(f2add(m[0], s12), s34);
            P[1] = f2fma(2.f, d34, d12);
            P[2] = f2fma(4.f, s34, s12);
            P[3] = f2add(f2fma(8.f, d34, d12), m[5]);
            float a1 = c1t[i], a2 = c2t[i], a3 = c3t[i];
            #pragma unroll
            for (int w = 0; w < 4; w++) {
                if (i < 5) Y[0][w] = f2add(Y[0][w], P[w]);
                Y[1][w] = f2fma(a1, P[w], Y[1][w]);
                Y[2][w] = f2fma(a2, P[w], Y[2][w]);
                Y[3][w] = f2fma(a3, P[w], Y[3][w]);
            }
        }
        float mean = g_mean[b * 128 + co];
        float rs = g_rstd[b * 128 + co];
        float nv = nvar[co];
        float cg = g_Cg[co], cb = g_Cb[co];
        size_t base = (((size_t)b * 128 + co) * 256 + y0) * 256 + x0;
        #pragma unroll
        for (int h = 0; h < 4; h++) {
            float4 xv = *(const float4*)&x[base + h * 256];
            const float* xp = (const float*)&xv;
            float o4[4];
            int ph = h & 1;
            int cr = ((h - 1) >> 1) + 1;
            #pragma unroll
            for (int w = 0; w < 4; w++) {
                int pw = w & 1;
                int cc = ((w - 1) >> 1) + 1;
                float ag = 0.f, ab = 0.f;
                #pragma unroll
                for (int u = 0; u < 2; u++)
                    #pragma unroll
                    for (int v = 0; v < 2; v++) {
                        unsigned row = (unsigned)(((((b * 20 + cls16[cr + u][cc + v]) * 2 + ph) * 2 + pw) * 2 + u) * 2 + v) * 256u;
                        float2 gg = *(const float2*)&g_G4[row + (unsigned)co * 2u];
                        ag += gg.x; ab += gg.y;
                    }
                float gf = ga * ag + (1.f - ga) * Y[h][w].x + cg;
                float bf = ba * ab + (1.f - ba) * Y[h][w].y + cb;
                float val = (xp[w] + nz[h][w] * nv - mean) * rs;
                o4[w] = fmaf(val, gf, val + bf);
            }
            *(float4*)&out[base + h * 256] = make_float4(o4[0], o4[1], o4[2], o4[3]);
        }
    }
}

// ----------------------------- launch -----------------------------
extern "C" void kernel_launch(void* const* d_in, const int* in_sizes, int n_in,
                              void* d_out, int out_size) {
    const float* x     = (const float*)d_in[0];
    const float* seg   = (const float*)d_in[1];
    const float* sc    = (const float*)d_in[2];
    const float* noise = (const float*)d_in[3];
    const float* nvar  = (const float*)d_in[4];
    const float* bg    = (const float*)d_in[5];
    const float* bb    = (const float*)d_in[6];
    const float* fcw   = (const float*)d_in[7];
    const float* fcb   = (const float*)d_in[8];
    const float* cgw   = (const float*)d_in[9];
    const float* cbw   = (const float*)d_in[11];
    const float* ssw   = (const float*)d_in[13];
    const float* ssb   = (const float*)d_in[14];
    const float* sgw   = (const float*)d_in[15];
    const float* sbw   = (const float*)d_in[17];
    float* out = (float*)d_out;

    k_prep<<<1345, 256>>>(bg, bb, (const float*)d_in[10], (const float*)d_in[12],
                          (const float*)d_in[16], (const float*)d_in[18],
                          sc, fcw, fcb, seg, ssw, sgw, sbw, noise);
    k_stats<<<1024, 256>>>(x, nvar);
    k_lut1<<<160, 128>>>(cgw, cbw);
    k_lut2<<<160, 256>>>();
    k_actv<<<dim3(16, 64, 8), 256>>>(seg, ssb);
    k_vt<<<dim3(16, 128, 8), 256>>>();
    k_gemm<<<dim3(32, 72, 8), 256>>>();
    k_inv<<<dim3(16, 4, 8), 256>>>(x, nvar, out);
}

// round 15
// speedup vs baseline: 4.2408x; 1.0589x over previous
#include <cuda_runtime.h>
#include <cstdint>
#include <math.h>

#define B_ 8
#define C_ 128
#define HW (256*256)
typedef unsigned long long ull;

// ----------------------------- device scratch -----------------------------
__device__ __align__(16) float g_actv[(size_t)B_*C_*HW];          // 268MB
__device__ __align__(16) float g_V[(size_t)36*B_*C_*4096];        // 604MB [k][b][ci][tile]
__device__ __align__(16) float g_M[(size_t)36*B_*C_*4096*2];      // 1.21GB [k][b][co][tile]{g,b}
__device__ __align__(16) float g_U[36*C_*256];                    // [k][ci][n]
__device__ __align__(16) float g_Wp[19*16*128];                   // [j][slot][co]
__device__ float g_nT[(size_t)B_*HW];
__device__ float g_mean[B_*C_];
__device__ float g_rstd[B_*C_];
__device__ float g_mu[B_*20*64];
__device__ __align__(16) float g_G2[B_*20*9*C_*2];
__device__ __align__(16) float g_G4[B_*20*16*C_*2];
__device__ unsigned char g_cls[B_*128*128];
__device__ float g_Cg[C_], g_Cb[C_], g_scal[2];

// ----------------------------- helpers -----------------------------
__device__ __forceinline__ ull fma2(ull a, ull b, ull c) {
    ull d;
    asm("fma.rn.f32x2 %0, %1, %2, %3;" : "=l"(d) : "l"(a), "l"(b), "l"(c));
    return d;
}
__device__ __forceinline__ ull pack2(float x, float y) {
    ull d;
    asm("mov.b64 %0, {%1, %2};" : "=l"(d) : "f"(x), "f"(y));
    return d;
}
__device__ __forceinline__ uint32_t smem_u32(const void* p) {
    uint32_t a;
    asm("{ .reg .u64 t; cvta.to.shared.u64 t, %1; cvt.u32.u64 %0, t; }" : "=r"(a) : "l"(p));
    return a;
}
__device__ __forceinline__ void cpa16(uint32_t d, const void* g) {
    asm volatile("cp.async.ca.shared.global [%0], [%1], 16;" :: "r"(d), "l"(g) : "memory");
}
__device__ __forceinline__ void cp_commit() { asm volatile("cp.async.commit_group;" ::: "memory"); }
__device__ __forceinline__ void cp_wait0() { asm volatile("cp.async.wait_group 0;" ::: "memory"); }
__device__ __forceinline__ float2 f2add(float2 a, float2 b) { return make_float2(a.x + b.x, a.y + b.y); }
__device__ __forceinline__ float2 f2sub(float2 a, float2 b) { return make_float2(a.x - b.x, a.y - b.y); }
__device__ __forceinline__ float2 f2fma(float k, float2 a, float2 b) {
    return make_float2(fmaf(k, a.x, b.x), fmaf(k, a.y, b.y));
}

// ----------------------------- launch #1: merged prep -----------------------------
// [0] scal | [1,41) mu | [41,553) cls | [553,705) Wp | [705,833) U | [833,1345) ntr
__global__ __launch_bounds__(256) void k_prep(
    const float* bg, const float* bb, const float* cgb, const float* cbb,
    const float* sgb, const float* sbb, const float* sc, const float* fcw,
    const float* fcb, const float* segmap, const float* ssw,
    const float* sgw, const float* sbw, const float* noise) {
    __shared__ float tsh[32][33];
    int bk = blockIdx.x, tid = threadIdx.x;
    if (bk == 0) {
        if (tid < 128) {
            float ga = 1.f / (1.f + expf(-bg[0]));
            float ba = 1.f / (1.f + expf(-bb[0]));
            g_Cg[tid] = ga * cgb[tid] + (1.f - ga) * sgb[tid];
            g_Cb[tid] = ba * cbb[tid] + (1.f - ba) * sbb[tid];
            if (tid == 0) { g_scal[0] = ga; g_scal[1] = ba; }
        }
    } else if (bk < 41) {
        int bj = (bk - 1) * 4 + (tid >> 6), o = tid & 63;
        int b = bj / 20, j = bj - b * 20;
        float r = 0.f;
        if (j < 19) {
            const float* s = sc + (b * 19 + j) * 64;
            const float* w = fcw + (j * 64 + o) * 64;
            #pragma unroll 8
            for (int i = 0; i < 64; i++) r = fmaf(s[i], w[i], r);
            r = fmaxf(r + fcb[j * 64 + o], 0.f);
        }
        g_mu[bj * 64 + o] = r;
    } else if (bk < 553) {
        int idx = (bk - 41) * 256 + tid;
        int b = idx >> 14, p = idx & 16383;
        int cls = 19;
        for (int j = 18; j >= 0; j--)
            if (segmap[(((size_t)b * 19 + j) << 14) + p] > 0.f) { cls = j; break; }
        g_cls[idx] = (unsigned char)cls;
    } else if (bk < 705) {
        int idx = (bk - 553) * 256 + tid;       // 19*16*128 = 38912
        if (idx < 38912) {
            int j = idx >> 11, rem = idx & 2047;
            int slot = rem >> 7, co = rem & 127;
            int ph = slot >> 3, pw = (slot >> 2) & 1, u = (slot >> 1) & 1, v = slot & 1;
            int ylo = (ph == 0) ? (u ? 0 : -1) : (u ? 1 : -1);
            int yhi = (ph == 0) ? (u ? 1 : -1) : (u ? 1 : 0);
            int xlo = (pw == 0) ? (v ? 0 : -1) : (v ? 1 : -1);
            int xhi = (pw == 0) ? (v ? 1 : -1) : (v ? 1 : 0);
            float s = 0.f;
            for (int dy = ylo; dy <= yhi; dy++)
                for (int dx = xlo; dx <= xhi; dx++)
                    s += ssw[(co * 19 + j) * 9 + (dy + 1) * 3 + (dx + 1)];
            g_Wp[idx] = s;
        }
    } else if (bk < 833) {
        int idx = (bk - 705) * 256 + tid;   // 32768 = 128ci x 256n
        int ci = idx >> 8, n = idx & 255;
        int co = n >> 1, sel = n & 1;
        const float* w = sel ? sbw : sgw;
        float g[3][3];
        #pragma unroll
        for (int t = 0; t < 9; t++) g[t / 3][t % 3] = w[(co * 128 + ci) * 9 + t];
        float t6[6][3];
        #pragma unroll
        for (int c = 0; c < 3; c++) {
            t6[0][c] = 0.25f * g[0][c];
            t6[1][c] = -(g[0][c] + g[1][c] + g[2][c]) * (1.f / 6.f);
            t6[2][c] = (-g[0][c] + g[1][c] - g[2][c]) * (1.f / 6.f);
            t6[3][c] = g[0][c] * (1.f / 24.f) + g[1][c] * (1.f / 12.f) + g[2][c] * (1.f / 6.f);
            t6[4][c] = g[0][c] * (1.f / 24.f) - g[1][c] * (1.f / 12.f) + g[2][c] * (1.f / 6.f);
            t6[5][c] = g[2][c];
        }
        #pragma unroll
        for (int i = 0; i < 6; i++) {
            float a = t6[i][0], bb2 = t6[i][1], c2 = t6[i][2];
            float u6[6];
            u6[0] = 0.25f * a;
            u6[1] = -(a + bb2 + c2) * (1.f / 6.f);
            u6[2] = (-a + bb2 - c2) * (1.f / 6.f);
            u6[3] = a * (1.f / 24.f) + bb2 * (1.f / 12.f) + c2 * (1.f / 6.f);
            u6[4] = a * (1.f / 24.f) - bb2 * (1.f / 12.f) + c2 * (1.f / 6.f);
            u6[5] = c2;
            #pragma unroll
            for (int kk = 0; kk < 6; kk++)
                g_U[((i * 6 + kk) * 128 + ci) * 256 + n] = u6[kk];
        }
    } else {
        int bl = bk - 833;
        int b = bl >> 6, rem = bl & 63;
        int w0 = (rem & 7) * 32, h0 = (rem >> 3) * 32;
        int tx = tid & 31, ty = tid >> 5;
        for (int i = 0; i < 32; i += 8)
            tsh[ty + i][tx] = noise[((size_t)b * 256 + w0 + ty + i) * 256 + h0 + tx];
        __syncthreads();
        for (int i = 0; i < 32; i += 8)
            g_nT[((size_t)b * 256 + h0 + ty + i) * 256 + w0 + tx] = tsh[tx][ty + i];
    }
}

// ----------------------------- launch #2: stats -----------------------------
__global__ __launch_bounds__(256) void k_stats(const float* x, const float* nvar) {
    int bc = blockIdx.x;
    int b = bc >> 7, c = bc & 127;
    float nv = nvar[c];
    const float* xb = x + (size_t)bc * HW;
    const float* nb = g_nT + (size_t)b * HW;
    float s = 0.f, q = 0.f;
    for (int i = threadIdx.x; i < HW; i += 256) {
        float v = xb[i] + nb[i] * nv;
        s += v; q = fmaf(v, v, q);
    }
    __shared__ float ss[8], sq[8];
    #pragma unroll
    for (int o = 16; o; o >>= 1) {
        s += __shfl_xor_sync(0xffffffffu, s, o);
        q += __shfl_xor_sync(0xffffffffu, q, o);
    }
    int wid = threadIdx.x >> 5, lane = threadIdx.x & 31;
    if (!lane) { ss[wid] = s; sq[wid] = q; }
    __syncthreads();
    if (threadIdx.x == 0) {
        float S = 0.f, Q = 0.f;
        #pragma unroll
        for (int k = 0; k < 8; k++) { S += ss[k]; Q += sq[k]; }
        float m = S * (1.f / HW);
        g_mean[bc] = m;
        g_rstd[bc] = rsqrtf(Q * (1.f / HW) - m * m + 1e-5f);
    }
}

// ----------------------------- LUTs -----------------------------
__global__ __launch_bounds__(128) void k_lut1(const float* gw, const float* bw) {
    int bj = blockIdx.x, co = threadIdx.x;
    __shared__ float mu_s[64];
    if (co < 64) mu_s[co] = g_mu[bj * 64 + co];
    __syncthreads();
    for (int t = 0; t < 9; t++) {
        float sg = 0.f, sb = 0.f;
        #pragma unroll 8
        for (int ci = 0; ci < 64; ci++) {
            float m = mu_s[ci];
            sg = fmaf(gw[(co * 64 + ci) * 9 + t], m, sg);
            sb = fmaf(bw[(co * 64 + ci) * 9 + t], m, sb);
        }
        int o = ((bj * 9 + t) * 128 + co) * 2;
        g_G2[o] = sg; g_G2[o + 1] = sb;
    }
}

__global__ __launch_bounds__(256) void k_lut2() {
    int bj = blockIdx.x, n = threadIdx.x;
    const float* G = g_G2 + (size_t)bj * 9 * 256;
    float* O = g_G4 + (size_t)bj * 16 * 256;
    for (int ph = 0; ph < 2; ph++)
    for (int pw = 0; pw < 2; pw++)
    for (int u = 0; u < 2; u++)
    for (int v = 0; v < 2; v++) {
        int rlo = (u == 0) ? 0 : (ph == 0 ? 1 : 2);
        int rhi = (u == 0) ? (ph == 0 ? 0 : 1) : 2;
        int clo = (v == 0) ? 0 : (pw == 0 ? 1 : 2);
        int chi = (v == 0) ? (pw == 0 ? 0 : 1) : 2;
        float s = 0.f;
        for (int dy = rlo; dy <= rhi; dy++)
            for (int dx = clo; dx <= chi; dx++)
                s += G[(dy * 3 + dx) * 256 + n];
        O[(((ph * 2 + pw) * 2 + u) * 2 + v) * 256 + n] = s;
    }
}

// ----------------------------- actv via parity LUT, 8 px/thread -----------------------
// grid (16, 32, 8): tile 16x8 px. Thread: rows r and r+4 (same parity), 4 px each x 8 co.
__global__ __launch_bounds__(256, 2) void k_actv(const float* segmap, const float* ssb) {
    __shared__ float Sh[19][6][10];
    __shared__ __align__(16) float Wb[2][16][128];
    uint32_t Wb_u = smem_u32(Wb);
    int b = blockIdx.z;
    int x0 = blockIdx.x * 16, y0 = blockIdx.y * 8;
    int tid = threadIdx.x;
    int tx = tid & 15, ty = tid >> 4;
    int r = ty >> 2, c = (ty & 3) * 4;

    int hb = (y0 >> 1) - 1, cbh = (x0 >> 1) - 1;
    for (int idx = tid; idx < 19 * 60; idx += 256) {
        int j = idx / 60, pos = idx - j * 60;
        int hr = pos / 10, hc = pos - hr * 10;
        int gy = hb + hr, gx = cbh + hc;
        float v = 0.f;
        if ((unsigned)gy < 128u && (unsigned)gx < 128u)
            v = segmap[(((size_t)b * 19 + j) << 14) + gy * 128 + gx];
        Sh[j][hr][hc] = v;
    }
    int ph = r & 1;
    int row0 = (r >> 1) + ph;    // group 0; group 1 = row0 + 2
    int col0 = c >> 1;

    ull acc[2][4][4];
    #pragma unroll
    for (int g = 0; g < 2; g++)
        #pragma unroll
        for (int i = 0; i < 4; i++)
            #pragma unroll
            for (int q = 0; q < 4; q++) acc[g][i][q] = 0ull;

    auto issueW = [&](int j, int buf) {
        const float* src = g_Wp + j * 2048;
        #pragma unroll
        for (int k = 0; k < 2; k++) {
            int idx = tid * 2 + k;
            cpa16(Wb_u + (uint32_t)(buf * 2048 + idx * 4) * 4u, src + idx * 4);
        }
        cp_commit();
    };

    issueW(0, 0);
    #pragma unroll 1
    for (int j = 0; j < 19; j++) {
        cp_wait0();
        __syncthreads();
        if (j + 1 < 19) issueW(j + 1, (j + 1) & 1);
        int buf = j & 1;
        float Sv[2][2][4];
        #pragma unroll
        for (int g = 0; g < 2; g++)
            #pragma unroll
            for (int u = 0; u < 2; u++)
                #pragma unroll
                for (int v = 0; v < 4; v++)
                    Sv[g][u][v] = Sh[j][row0 + 2 * g + u][col0 + v];
        #pragma unroll
        for (int u = 0; u < 2; u++)
            #pragma unroll
            for (int v = 0; v < 2; v++) {
                ulonglong2 W0a = *(const ulonglong2*)&Wb[buf][((ph * 2 + 0) * 2 + u) * 2 + v][tx * 4];
                ulonglong2 W0b = *(const ulonglong2*)&Wb[buf][((ph * 2 + 0) * 2 + u) * 2 + v][tx * 4 + 64];
                ulonglong2 W1a = *(const ulonglong2*)&Wb[buf][((ph * 2 + 1) * 2 + u) * 2 + v][tx * 4];
                ulonglong2 W1b = *(const ulonglong2*)&Wb[buf][((ph * 2 + 1) * 2 + u) * 2 + v][tx * 4 + 64];
                #pragma unroll
                for (int i = 0; i < 4; i++) {
                    int pw = i & 1, cb2 = (i >> 1) + (i & 1);
                    const ulonglong2& Wa = pw ? W1a : W0a;
                    const ulonglong2& Wc = pw ? W1b : W0b;
                    #pragma unroll
                    for (int g = 0; g < 2; g++) {
                        float s = Sv[g][u][cb2 + v];
                        ull a = pack2(s, s);
                        acc[g][i][0] = fma2(a, Wa.x, acc[g][i][0]);
                        acc[g][i][1] = fma2(a, Wa.y, acc[g][i][1]);
                        acc[g][i][2] = fma2(a, Wc.x, acc[g][i][2]);
                        acc[g][i][3] = fma2(a, Wc.y, acc[g][i][3]);
                    }
                }
            }
        __syncthreads();
    }

    int xg0 = x0 + c;
    #pragma unroll
    for (int g = 0; g < 2; g++) {
        int y = y0 + r + 4 * g;
        #pragma unroll
        for (int q = 0; q < 4; q++) {
            int co0 = (q < 2) ? (tx * 4 + q * 2) : (tx * 4 + 64 + (q - 2) * 2);
            #pragma unroll
            for (int h2 = 0; h2 < 2; h2++) {
                int co = co0 + h2;
                float bias = ssb[co];
                float4 o;
                float* op = (float*)&o;
                #pragma unroll
                for (int p = 0; p < 4; p++) {
                    ull v = acc[g][p][q];
                    unsigned w32 = h2 ? (unsigned)(v >> 32) : (unsigned)v;
                    op[p] = fmaxf(__uint_as_float(w32) + bias, 0.f);
                }
                *(float4*)&g_actv[(((size_t)b * 128 + co) * 256 + y) * 256 + xg0] = o;
            }
        }
    }
}

// ----------------------------- F(4,3) input transform V = Bt d B -----------------------
__global__ __launch_bounds__(256) void k_vt() {
    __shared__ float sm[66][68];
    int tid = threadIdx.x;
    int ci = blockIdx.y, b = blockIdx.z;
    int ry = blockIdx.x >> 2, rx = blockIdx.x & 3;
    int y0 = ry * 64, x0 = rx * 64;
    const float* src = g_actv + ((size_t)b * 128 + ci) * HW;
    for (int idx = tid; idx < 66 * 66; idx += 256) {
        int r = idx / 66, c = idx - r * 66;
        int gy = y0 - 1 + r, gx = x0 - 1 + c;
        float v = 0.f;
        if ((unsigned)gy < 256u && (unsigned)gx < 256u) v = src[gy * 256 + gx];
        sm[r][c] = v;
    }
    __syncthreads();
    int ty = tid >> 4, tx = tid & 15;
    float t6[6][6];
    #pragma unroll
    for (int j = 0; j < 6; j++) {
        float d0 = sm[4 * ty + 0][4 * tx + j], d1 = sm[4 * ty + 1][4 * tx + j];
        float d2 = sm[4 * ty + 2][4 * tx + j], d3 = sm[4 * ty + 3][4 * tx + j];
        float d4 = sm[4 * ty + 4][4 * tx + j], d5 = sm[4 * ty + 5][4 * tx + j];
        t6[0][j] = 4.f * d0 - 5.f * d2 + d4;
        t6[1][j] = -4.f * (d1 + d2) + d3 + d4;
        t6[2][j] = 4.f * (d1 - d2) - d3 + d4;
        t6[3][j] = -2.f * d1 - d2 + 2.f * d3 + d4;
        t6[4][j] = 2.f * d1 - d2 - 2.f * d3 + d4;
        t6[5][j] = 4.f * d1 - 5.f * d3 + d5;
    }
    int gtile = (ry * 16 + ty) * 64 + rx * 16 + tx;
    float* dst = g_V + ((size_t)b * 128 + ci) * 4096 + gtile;
    const size_t ks = (size_t)8 * 128 * 4096;
    #pragma unroll
    for (int i = 0; i < 6; i++) {
        float s0 = t6[i][0], s1 = t6[i][1], s2 = t6[i][2];
        float s3 = t6[i][3], s4 = t6[i][4], s5 = t6[i][5];
        dst[(size_t)(i * 6 + 0) * ks] = 4.f * s0 - 5.f * s2 + s4;
        dst[(size_t)(i * 6 + 1) * ks] = -4.f * (s1 + s2) + s3 + s4;
        dst[(size_t)(i * 6 + 2) * ks] = 4.f * (s1 - s2) - s3 + s4;
        dst[(size_t)(i * 6 + 3) * ks] = -2.f * s1 - s2 + 2.f * s3 + s4;
        dst[(size_t)(i * 6 + 4) * ks] = 2.f * s1 - s2 - 2.f * s3 + s4;
        dst[(size_t)(i * 6 + 5) * ks] = 4.f * s1 - 5.f * s3 + s5;
    }
}

// ----------------------------- 36x batched GEMM -> fp32 M ---------------------------
__global__ __launch_bounds__(256, 2) void k_gemm() {
    __shared__ __align__(16) float As[2][16][128];
    __shared__ __align__(16) float Us[2][16][128];
    uint32_t As_u = smem_u32(As), Us_u = smem_u32(Us);
    int tid = threadIdx.x, mg = tid & 15, ng = tid >> 4;
    int mb = blockIdx.x;
    int k = blockIdx.y >> 1, nb = blockIdx.y & 1;
    int b = blockIdx.z;
    const float* Vb = g_V + ((size_t)(k * 8 + b) * 128) * 4096 + mb * 128;
    const float* Ub = g_U + (size_t)k * 128 * 256 + nb * 128;

    ull acc[8][4];
    #pragma unroll
    for (int i = 0; i < 8; i++)
        #pragma unroll
        for (int c = 0; c < 4; c++) acc[i][c] = 0ull;

    auto issue = [&](int c, int buf) {
        #pragma unroll
        for (int j = 0; j < 2; j++) {
            int idx = tid * 2 + j;
            int row = idx >> 5, col = (idx & 31) * 4;
            cpa16(As_u + (uint32_t)((buf * 16 + row) * 128 + col) * 4u,
                  Vb + (size_t)(c * 16 + row) * 4096 + col);
            cpa16(Us_u + (uint32_t)((buf * 16 + row) * 128 + col) * 4u,
                  Ub + (size_t)(c * 16 + row) * 256 + col);
        }
        cp_commit();
    };

    issue(0, 0);
    #pragma unroll 1
    for (int c = 0; c < 8; c++) {
        cp_wait0();
        __syncthreads();
        if (c + 1 < 8) issue(c + 1, (c + 1) & 1);
        int buf = c & 1;
        #pragma unroll
        for (int ci = 0; ci < 16; ci++) {
            float4 a0 = *(const float4*)&As[buf][ci][mg * 8];
            float4 a1 = *(const float4*)&As[buf][ci][mg * 8 + 4];
            ulonglong2 u0 = *(const ulonglong2*)&Us[buf][ci][ng * 8];
            ulonglong2 u1 = *(const ulonglong2*)&Us[buf][ci][ng * 8 + 4];
            ull ap[8];
            ap[0] = pack2(a0.x, a0.x); ap[1] = pack2(a0.y, a0.y);
            ap[2] = pack2(a0.z, a0.z); ap[3] = pack2(a0.w, a0.w);
            ap[4] = pack2(a1.x, a1.x); ap[5] = pack2(a1.y, a1.y);
            ap[6] = pack2(a1.z, a1.z); ap[7] = pack2(a1.w, a1.w);
            #pragma unroll
            for (int i = 0; i < 8; i++) {
                acc[i][0] = fma2(ap[i], u0.x, acc[i][0]);
                acc[i][1] = fma2(ap[i], u0.y, acc[i][1]);
                acc[i][2] = fma2(ap[i], u1.x, acc[i][2]);
                acc[i][3] = fma2(ap[i], u1.y, acc[i][3]);
            }
        }
        __syncthreads();
    }
    #pragma unroll
    for (int c = 0; c < 4; c++) {
        int co = nb * 64 + ng * 4 + c;
        ull* Mr = (ull*)g_M + ((size_t)(k * 8 + b) * 128 + co) * 4096 + mb * 128 + mg * 8;
        ulonglong2 s0, s1, s2, s3;
        s0.x = acc[0][c]; s0.y = acc[1][c];
        s1.x = acc[2][c]; s1.y = acc[3][c];
        s2.x = acc[4][c]; s2.y = acc[5][c];
        s3.x = acc[6][c]; s3.y = acc[7][c];
        *(ulonglong2*)(Mr + 0) = s0;
        *(ulonglong2*)(Mr + 2) = s1;
        *(ulonglong2*)(Mr + 4) = s2;
        *(ulonglong2*)(Mr + 6) = s3;
    }
}

// ----------------------------- inverse transform + fused epilogue -------------------
__global__ __launch_bounds__(256) void k_inv(const float* __restrict__ x,
                                             const float* __restrict__ nvar,
                                             float* __restrict__ out) {
    int tid = threadIdx.x;
    int b = blockIdx.z;
    int tile = blockIdx.x * 256 + tid;
    int ty = tile >> 6, tx = tile & 63;
    int co0 = blockIdx.y * 32;
    int y0 = 4 * ty, x0 = 4 * tx;

    int cls16[4][4];
    #pragma unroll
    for (int i = 0; i < 4; i++)
        #pragma unroll
        for (int j = 0; j < 4; j++) {
            int cy = 2 * ty - 1 + i, cx = 2 * tx - 1 + j;
            int cls = 19;
            if ((unsigned)cy < 128u && (unsigned)cx < 128u)
                cls = g_cls[((size_t)b << 14) + cy * 128 + cx];
            cls16[i][j] = cls;
        }
    float nz[4][4];
    #pragma unroll
    for (int rr = 0; rr < 4; rr++)
        *(float4*)nz[rr] = *(const float4*)&g_nT[((size_t)b * 256 + y0 + rr) * 256 + x0];
    float ga = g_scal[0], ba = g_scal[1];
    const size_t ks = (size_t)8 * 128 * 4096;
    const float c1t[6] = {0.f, 1.f, -1.f, 2.f, -2.f, 0.f};
    const float c2t[6] = {0.f, 1.f, 1.f, 4.f, 4.f, 0.f};
    const float c3t[6] = {0.f, 1.f, -1.f, 8.f, -8.f, 1.f};

    #pragma unroll 1
    for (int ic = 0; ic < 32; ic++) {
        int co = co0 + ic;
        const float2* Mp = (const float2*)g_M + ((size_t)b * 128 + co) * 4096 + tile;
        float2 Y[4][4];
        #pragma unroll
        for (int h = 0; h < 4; h++)
            #pragma unroll
            for (int w = 0; w < 4; w++) Y[h][w] = make_float2(0.f, 0.f);
        #pragma unroll
        for (int i = 0; i < 6; i++) {
            float2 m[6];
            #pragma unroll
            for (int j = 0; j < 6; j++) m[j] = Mp[(size_t)(i * 6 + j) * ks];
            float2 s12 = f2add(m[1], m[2]), d12 = f2sub(m[1], m[2]);
            float2 s34 = f2add(m[3], m[4]), d34 = f2sub(m[3], m[4]);
            float2 P[4];
            P[0] = f2add(f2add(m[0], s12), s34);
            P[1] = f2fma(2.f, d34, d12);
            P[2] = f2fma(4.f, s34, s12);
            P[3] = f2add(f2fma(8.f, d34, d12), m[5]);
            float a1 = c1t[i], a2 = c2t[i], a3 = c3t[i];
            #pragma unroll
            for (int w = 0; w < 4; w++) {
                if (i < 5) Y[0][w] = f2add(Y[0][w], P[w]);
                Y[1][w] = f2fma(a1, P[w], Y[1][w]);
                Y[2][w] = f2fma(a2, P[w], Y[2][w]);
                Y[3][w] = f2fma(a3, P[w], Y[3][w]);
            }
        }
        float mean = g_mean[b * 128 + co];
        float rs = g_rstd[b * 128 + co];
        float nv = nvar[co];
        float cg = g_Cg[co], cb = g_Cb[co];
        size_t base = (((size_t)b * 128 + co) * 256 + y0) * 256 + x0;
        #pragma unroll
        for (int h = 0; h < 4; h++) {
            float4 xv = *(const float4*)&x[base + h * 256];
            const float* xp = (const float*)&xv;
            float o4[4];
            int ph = h & 1;
            int cr = ((h - 1) >> 1) + 1;
            #pragma unroll
            for (int w = 0; w < 4; w++) {
                int pw = w & 1;
                int cc = ((w - 1) >> 1) + 1;
                float ag = 0.f, ab = 0.f;
                #pragma unroll
                for (int u = 0; u < 2; u++)
                    #pragma unroll
                    for (int v = 0; v < 2; v++) {
                        unsigned row = (unsigned)(((((b * 20 + cls16[cr + u][cc + v]) * 2 + ph) * 2 + pw) * 2 + u) * 2 + v) * 256u;
                        float2 gg = *(const float2*)&g_G4[row + (unsigned)co * 2u];
                        ag += gg.x; ab += gg.y;
                    }
                float gf = ga * ag + (1.f - ga) * Y[h][w].x + cg;
                float bf = ba * ab + (1.f - ba) * Y[h][w].y + cb;
                float val = (xp[w] + nz[h][w] * nv - mean) * rs;
                o4[w] = fmaf(val, gf, val + bf);
            }
            *(float4*)&out[base + h * 256] = make_float4(o4[0], o4[1], o4[2], o4[3]);
        }
    }
}

// ----------------------------- launch -----------------------------
extern "C" void kernel_launch(void* const* d_in, const int* in_sizes, int n_in,
                              void* d_out, int out_size) {
    const float* x     = (const float*)d_in[0];
    const float* seg   = (const float*)d_in[1];
    const float* sc    = (const float*)d_in[2];
    const float* noise = (const float*)d_in[3];
    const float* nvar  = (const float*)d_in[4];
    const float* bg    = (const float*)d_in[5];
    const float* bb    = (const float*)d_in[6];
    const float* fcw   = (const float*)d_in[7];
    const float* fcb   = (const float*)d_in[8];
    const float* cgw   = (const float*)d_in[9];
    const float* cbw   = (const float*)d_in[11];
    const float* ssw   = (const float*)d_in[13];
    const float* ssb   = (const float*)d_in[14];
    const float* sgw   = (const float*)d_in[15];
    const float* sbw   = (const float*)d_in[17];
    float* out = (float*)d_out;

    // order: k_gemm is launch #6 for the ncu -s 5 -c 1 window
    k_prep<<<1345, 256>>>(bg, bb, (const float*)d_in[10], (const float*)d_in[12],
                          (const float*)d_in[16], (const float*)d_in[18],
                          sc, fcw, fcb, seg, ssw, sgw, sbw, noise);
    k_stats<<<1024, 256>>>(x, nvar);
    k_lut1<<<160, 128>>>(cgw, cbw);
    k_actv<<<dim3(16, 32, 8), 256>>>(seg, ssb);
    k_vt<<<dim3(16, 128, 8), 256>>>();
    k_gemm<<<dim3(32, 72, 8), 256>>>();
    k_lut2<<<160, 256>>>();
    k_inv<<<dim3(16, 4, 8), 256>>>(x, nvar, out);
}

// round 16
// speedup vs baseline: 4.4106x; 1.0400x over previous
#include <cuda_runtime.h>
#include <cstdint>
#include <math.h>

#define B_ 8
#define C_ 128
#define HW (256*256)
typedef unsigned long long ull;

// ----------------------------- device scratch -----------------------------
__device__ __align__(16) float g_actv[(size_t)B_*C_*HW];          // 268MB
__device__ __align__(16) float g_V[(size_t)36*B_*C_*4096];        // 604MB [k][b][ci][tile]
__device__ __align__(16) float g_M[(size_t)36*B_*C_*4096*2];      // 1.21GB [k][b][co][tile]{g,b}
__device__ __align__(16) float g_U[36*C_*256];                    // [k][ci][n]
__device__ __align__(16) float g_Wp[19*16*128];                   // [j][slot][co]
__device__ float g_nT[(size_t)B_*HW];
__device__ float g_mean[B_*C_];
__device__ float g_rstd[B_*C_];
__device__ float g_mu[B_*20*64];
__device__ __align__(16) float g_G2[B_*20*9*C_*2];
__device__ __align__(16) float g_G4[B_*20*16*C_*2];
__device__ unsigned char g_cls[B_*128*128];
__device__ float g_Cg[C_], g_Cb[C_], g_scal[2];

// ----------------------------- helpers -----------------------------
__device__ __forceinline__ ull fma2(ull a, ull b, ull c) {
    ull d;
    asm("fma.rn.f32x2 %0, %1, %2, %3;" : "=l"(d) : "l"(a), "l"(b), "l"(c));
    return d;
}
__device__ __forceinline__ ull pack2(float x, float y) {
    ull d;
    asm("mov.b64 %0, {%1, %2};" : "=l"(d) : "f"(x), "f"(y));
    return d;
}
__device__ __forceinline__ uint32_t smem_u32(const void* p) {
    uint32_t a;
    asm("{ .reg .u64 t; cvta.to.shared.u64 t, %1; cvt.u32.u64 %0, t; }" : "=r"(a) : "l"(p));
    return a;
}
__device__ __forceinline__ void cpa16(uint32_t d, const void* g) {
    asm volatile("cp.async.ca.shared.global [%0], [%1], 16;" :: "r"(d), "l"(g) : "memory");
}
__device__ __forceinline__ void cp_commit() { asm volatile("cp.async.commit_group;" ::: "memory"); }
__device__ __forceinline__ void cp_wait0() { asm volatile("cp.async.wait_group 0;" ::: "memory"); }
__device__ __forceinline__ float2 f2add(float2 a, float2 b) { return make_float2(a.x + b.x, a.y + b.y); }
__device__ __forceinline__ float2 f2sub(float2 a, float2 b) { return make_float2(a.x - b.x, a.y - b.y); }
__device__ __forceinline__ float2 f2fma(float k, float2 a, float2 b) {
    return make_float2(fmaf(k, a.x, b.x), fmaf(k, a.y, b.y));
}

// ----------------------------- launch #1: merged prep -----------------------------
// [0] scal | [1,41) mu | [41,553) cls | [553,705) Wp | [705,833) U | [833,1345) ntr
__global__ __launch_bounds__(256) void k_prep(
    const float* bg, const float* bb, const float* cgb, const float* cbb,
    const float* sgb, const float* sbb, const float* sc, const float* fcw,
    const float* fcb, const float* segmap, const float* ssw,
    const float* sgw, const float* sbw, const float* noise) {
    __shared__ float tsh[32][33];
    int bk = blockIdx.x, tid = threadIdx.x;
    if (bk == 0) {
        if (tid < 128) {
            float ga = 1.f / (1.f + expf(-bg[0]));
            float ba = 1.f / (1.f + expf(-bb[0]));
            g_Cg[tid] = ga * cgb[tid] + (1.f - ga) * sgb[tid];
            g_Cb[tid] = ba * cbb[tid] + (1.f - ba) * sbb[tid];
            if (tid == 0) { g_scal[0] = ga; g_scal[1] = ba; }
        }
    } else if (bk < 41) {
        int bj = (bk - 1) * 4 + (tid >> 6), o = tid & 63;
        int b = bj / 20, j = bj - b * 20;
        float r = 0.f;
        if (j < 19) {
            const float* s = sc + (b * 19 + j) * 64;
            const float* w = fcw + (j * 64 + o) * 64;
            #pragma unroll 8
            for (int i = 0; i < 64; i++) r = fmaf(s[i], w[i], r);
            r = fmaxf(r + fcb[j * 64 + o], 0.f);
        }
        g_mu[bj * 64 + o] = r;
    } else if (bk < 553) {
        int idx = (bk - 41) * 256 + tid;
        int b = idx >> 14, p = idx & 16383;
        int cls = 19;
        for (int j = 18; j >= 0; j--)
            if (segmap[(((size_t)b * 19 + j) << 14) + p] > 0.f) { cls = j; break; }
        g_cls[idx] = (unsigned char)cls;
    } else if (bk < 705) {
        int idx = (bk - 553) * 256 + tid;       // 19*16*128 = 38912
        if (idx < 38912) {
            int j = idx >> 11, rem = idx & 2047;
            int slot = rem >> 7, co = rem & 127;
            int ph = slot >> 3, pw = (slot >> 2) & 1, u = (slot >> 1) & 1, v = slot & 1;
            int ylo = (ph == 0) ? (u ? 0 : -1) : (u ? 1 : -1);
            int yhi = (ph == 0) ? (u ? 1 : -1) : (u ? 1 : 0);
            int xlo = (pw == 0) ? (v ? 0 : -1) : (v ? 1 : -1);
            int xhi = (pw == 0) ? (v ? 1 : -1) : (v ? 1 : 0);
            float s = 0.f;
            for (int dy = ylo; dy <= yhi; dy++)
                for (int dx = xlo; dx <= xhi; dx++)
                    s += ssw[(co * 19 + j) * 9 + (dy + 1) * 3 + (dx + 1)];
            g_Wp[idx] = s;
        }
    } else if (bk < 833) {
        int idx = (bk - 705) * 256 + tid;   // 32768 = 128ci x 256n
        int ci = idx >> 8, n = idx & 255;
        int co = n >> 1, sel = n & 1;
        const float* w = sel ? sbw : sgw;
        float g[3][3];
        #pragma unroll
        for (int t = 0; t < 9; t++) g[t / 3][t % 3] = w[(co * 128 + ci) * 9 + t];
        float t6[6][3];
        #pragma unroll
        for (int c = 0; c < 3; c++) {
            t6[0][c] = 0.25f * g[0][c];
            t6[1][c] = -(g[0][c] + g[1][c] + g[2][c]) * (1.f / 6.f);
            t6[2][c] = (-g[0][c] + g[1][c] - g[2][c]) * (1.f / 6.f);
            t6[3][c] = g[0][c] * (1.f / 24.f) + g[1][c] * (1.f / 12.f) + g[2][c] * (1.f / 6.f);
            t6[4][c] = g[0][c] * (1.f / 24.f) - g[1][c] * (1.f / 12.f) + g[2][c] * (1.f / 6.f);
            t6[5][c] = g[2][c];
        }
        #pragma unroll
        for (int i = 0; i < 6; i++) {
            float a = t6[i][0], bb2 = t6[i][1], c2 = t6[i][2];
            float u6[6];
            u6[0] = 0.25f * a;
            u6[1] = -(a + bb2 + c2) * (1.f / 6.f);
            u6[2] = (-a + bb2 - c2) * (1.f / 6.f);
            u6[3] = a * (1.f / 24.f) + bb2 * (1.f / 12.f) + c2 * (1.f / 6.f);
            u6[4] = a * (1.f / 24.f) - bb2 * (1.f / 12.f) + c2 * (1.f / 6.f);
            u6[5] = c2;
            #pragma unroll
            for (int kk = 0; kk < 6; kk++)
                g_U[((i * 6 + kk) * 128 + ci) * 256 + n] = u6[kk];
        }
    } else {
        int bl = bk - 833;
        int b = bl >> 6, rem = bl & 63;
        int w0 = (rem & 7) * 32, h0 = (rem >> 3) * 32;
        int tx = tid & 31, ty = tid >> 5;
        for (int i = 0; i < 32; i += 8)
            tsh[ty + i][tx] = noise[((size_t)b * 256 + w0 + ty + i) * 256 + h0 + tx];
        __syncthreads();
        for (int i = 0; i < 32; i += 8)
            g_nT[((size_t)b * 256 + h0 + ty + i) * 256 + w0 + tx] = tsh[tx][ty + i];
    }
}

// ----------------------------- launch #2: stats -----------------------------
__global__ __launch_bounds__(256) void k_stats(const float* x, const float* nvar) {
    int bc = blockIdx.x;
    int b = bc >> 7, c = bc & 127;
    float nv = nvar[c];
    const float* xb = x + (size_t)bc * HW;
    const float* nb = g_nT + (size_t)b * HW;
    float s = 0.f, q = 0.f;
    for (int i = threadIdx.x; i < HW; i += 256) {
        float v = xb[i] + nb[i] * nv;
        s += v; q = fmaf(v, v, q);
    }
    __shared__ float ss[8], sq[8];
    #pragma unroll
    for (int o = 16; o; o >>= 1) {
        s += __shfl_xor_sync(0xffffffffu, s, o);
        q += __shfl_xor_sync(0xffffffffu, q, o);
    }
    int wid = threadIdx.x >> 5, lane = threadIdx.x & 31;
    if (!lane) { ss[wid] = s; sq[wid] = q; }
    __syncthreads();
    if (threadIdx.x == 0) {
        float S = 0.f, Q = 0.f;
        #pragma unroll
        for (int k = 0; k < 8; k++) { S += ss[k]; Q += sq[k]; }
        float m = S * (1.f / HW);
        g_mean[bc] = m;
        g_rstd[bc] = rsqrtf(Q * (1.f / HW) - m * m + 1e-5f);
    }
}

// ----------------------------- LUTs -----------------------------
__global__ __launch_bounds__(128) void k_lut1(const float* gw, const float* bw) {
    int bj = blockIdx.x, co = threadIdx.x;
    __shared__ float mu_s[64];
    if (co < 64) mu_s[co] = g_mu[bj * 64 + co];
    __syncthreads();
    for (int t = 0; t < 9; t++) {
        float sg = 0.f, sb = 0.f;
        #pragma unroll 8
        for (int ci = 0; ci < 64; ci++) {
            float m = mu_s[ci];
            sg = fmaf(gw[(co * 64 + ci) * 9 + t], m, sg);
            sb = fmaf(bw[(co * 64 + ci) * 9 + t], m, sb);
        }
        int o = ((bj * 9 + t) * 128 + co) * 2;
        g_G2[o] = sg; g_G2[o + 1] = sb;
    }
}

__global__ __launch_bounds__(256) void k_lut2() {
    int bj = blockIdx.x, n = threadIdx.x;
    const float* G = g_G2 + (size_t)bj * 9 * 256;
    float* O = g_G4 + (size_t)bj * 16 * 256;
    for (int ph = 0; ph < 2; ph++)
    for (int pw = 0; pw < 2; pw++)
    for (int u = 0; u < 2; u++)
    for (int v = 0; v < 2; v++) {
        int rlo = (u == 0) ? 0 : (ph == 0 ? 1 : 2);
        int rhi = (u == 0) ? (ph == 0 ? 0 : 1) : 2;
        int clo = (v == 0) ? 0 : (pw == 0 ? 1 : 2);
        int chi = (v == 0) ? (pw == 0 ? 0 : 1) : 2;
        float s = 0.f;
        for (int dy = rlo; dy <= rhi; dy++)
            for (int dx = clo; dx <= chi; dx++)
                s += G[(dy * 3 + dx) * 256 + n];
        O[(((ph * 2 + pw) * 2 + u) * 2 + v) * 256 + n] = s;
    }
}

// ----------------------------- actv via parity LUT, 8 px/thread -----------------------
__global__ __launch_bounds__(256, 2) void k_actv(const float* segmap, const float* ssb) {
    __shared__ float Sh[19][6][10];
    __shared__ __align__(16) float Wb[2][16][128];
    uint32_t Wb_u = smem_u32(Wb);
    int b = blockIdx.z;
    int x0 = blockIdx.x * 16, y0 = blockIdx.y * 8;
    int tid = threadIdx.x;
    int tx = tid & 15, ty = tid >> 4;
    int r = ty >> 2, c = (ty & 3) * 4;

    int hb = (y0 >> 1) - 1, cbh = (x0 >> 1) - 1;
    for (int idx = tid; idx < 19 * 60; idx += 256) {
        int j = idx / 60, pos = idx - j * 60;
        int hr = pos / 10, hc = pos - hr * 10;
        int gy = hb + hr, gx = cbh + hc;
        float v = 0.f;
        if ((unsigned)gy < 128u && (unsigned)gx < 128u)
            v = segmap[(((size_t)b * 19 + j) << 14) + gy * 128 + gx];
        Sh[j][hr][hc] = v;
    }
    int ph = r & 1;
    int row0 = (r >> 1) + ph;
    int col0 = c >> 1;

    ull acc[2][4][4];
    #pragma unroll
    for (int g = 0; g < 2; g++)
        #pragma unroll
        for (int i = 0; i < 4; i++)
            #pragma unroll
            for (int q = 0; q < 4; q++) acc[g][i][q] = 0ull;

    auto issueW = [&](int j, int buf) {
        const float* src = g_Wp + j * 2048;
        #pragma unroll
        for (int k = 0; k < 2; k++) {
            int idx = tid * 2 + k;
            cpa16(Wb_u + (uint32_t)(buf * 2048 + idx * 4) * 4u, src + idx * 4);
        }
        cp_commit();
    };

    issueW(0, 0);
    #pragma unroll 1
    for (int j = 0; j < 19; j++) {
        cp_wait0();
        __syncthreads();
        if (j + 1 < 19) issueW(j + 1, (j + 1) & 1);
        int buf = j & 1;
        float Sv[2][2][4];
        #pragma unroll
        for (int g = 0; g < 2; g++)
            #pragma unroll
            for (int u = 0; u < 2; u++)
                #pragma unroll
                for (int v = 0; v < 4; v++)
                    Sv[g][u][v] = Sh[j][row0 + 2 * g + u][col0 + v];
        #pragma unroll
        for (int u = 0; u < 2; u++)
            #pragma unroll
            for (int v = 0; v < 2; v++) {
                ulonglong2 W0a = *(const ulonglong2*)&Wb[buf][((ph * 2 + 0) * 2 + u) * 2 + v][tx * 4];
                ulonglong2 W0b = *(const ulonglong2*)&Wb[buf][((ph * 2 + 0) * 2 + u) * 2 + v][tx * 4 + 64];
                ulonglong2 W1a = *(const ulonglong2*)&Wb[buf][((ph * 2 + 1) * 2 + u) * 2 + v][tx * 4];
                ulonglong2 W1b = *(const ulonglong2*)&Wb[buf][((ph * 2 + 1) * 2 + u) * 2 + v][tx * 4 + 64];
                #pragma unroll
                for (int i = 0; i < 4; i++) {
                    int pw = i & 1, cb2 = (i >> 1) + (i & 1);
                    const ulonglong2& Wa = pw ? W1a : W0a;
                    const ulonglong2& Wc = pw ? W1b : W0b;
                    #pragma unroll
                    for (int g = 0; g < 2; g++) {
                        float s = Sv[g][u][cb2 + v];
                        ull a = pack2(s, s);
                        acc[g][i][0] = fma2(a, Wa.x, acc[g][i][0]);
                        acc[g][i][1] = fma2(a, Wa.y, acc[g][i][1]);
                        acc[g][i][2] = fma2(a, Wc.x, acc[g][i][2]);
                        acc[g][i][3] = fma2(a, Wc.y, acc[g][i][3]);
                    }
                }
            }
        __syncthreads();
    }

    int xg0 = x0 + c;
    #pragma unroll
    for (int g = 0; g < 2; g++) {
        int y = y0 + r + 4 * g;
        #pragma unroll
        for (int q = 0; q < 4; q++) {
            int co0 = (q < 2) ? (tx * 4 + q * 2) : (tx * 4 + 64 + (q - 2) * 2);
            #pragma unroll
            for (int h2 = 0; h2 < 2; h2++) {
                int co = co0 + h2;
                float bias = ssb[co];
                float4 o;
                float* op = (float*)&o;
                #pragma unroll
                for (int p = 0; p < 4; p++) {
                    ull v = acc[g][p][q];
                    unsigned w32 = h2 ? (unsigned)(v >> 32) : (unsigned)v;
                    op[p] = fmaxf(__uint_as_float(w32) + bias, 0.f);
                }
                *(float4*)&g_actv[(((size_t)b * 128 + co) * 256 + y) * 256 + xg0] = o;
            }
        }
    }
}

// ----------------------------- F(4,3) input transform V = Bt d B -----------------------
__global__ __launch_bounds__(256) void k_vt() {
    __shared__ float sm[66][68];
    int tid = threadIdx.x;
    int ci = blockIdx.y, b = blockIdx.z;
    int ry = blockIdx.x >> 2, rx = blockIdx.x & 3;
    int y0 = ry * 64, x0 = rx * 64;
    const float* src = g_actv + ((size_t)b * 128 + ci) * HW;
    for (int idx = tid; idx < 66 * 66; idx += 256) {
        int r = idx / 66, c = idx - r * 66;
        int gy = y0 - 1 + r, gx = x0 - 1 + c;
        float v = 0.f;
        if ((unsigned)gy < 256u && (unsigned)gx < 256u) v = src[gy * 256 + gx];
        sm[r][c] = v;
    }
    __syncthreads();
    int ty = tid >> 4, tx = tid & 15;
    float t6[6][6];
    #pragma unroll
    for (int j = 0; j < 6; j++) {
        float d0 = sm[4 * ty + 0][4 * tx + j], d1 = sm[4 * ty + 1][4 * tx + j];
        float d2 = sm[4 * ty + 2][4 * tx + j], d3 = sm[4 * ty + 3][4 * tx + j];
        float d4 = sm[4 * ty + 4][4 * tx + j], d5 = sm[4 * ty + 5][4 * tx + j];
        t6[0][j] = 4.f * d0 - 5.f * d2 + d4;
        t6[1][j] = -4.f * (d1 + d2) + d3 + d4;
        t6[2][j] = 4.f * (d1 - d2) - d3 + d4;
        t6[3][j] = -2.f * d1 - d2 + 2.f * d3 + d4;
        t6[4][j] = 2.f * d1 - d2 - 2.f * d3 + d4;
        t6[5][j] = 4.f * d1 - 5.f * d3 + d5;
    }
    int gtile = (ry * 16 + ty) * 64 + rx * 16 + tx;
    float* dst = g_V + ((size_t)b * 128 + ci) * 4096 + gtile;
    const size_t ks = (size_t)8 * 128 * 4096;
    #pragma unroll
    for (int i = 0; i < 6; i++) {
        float s0 = t6[i][0], s1 = t6[i][1], s2 = t6[i][2];
        float s3 = t6[i][3], s4 = t6[i][4], s5 = t6[i][5];
        dst[(size_t)(i * 6 + 0) * ks] = 4.f * s0 - 5.f * s2 + s4;
        dst[(size_t)(i * 6 + 1) * ks] = -4.f * (s1 + s2) + s3 + s4;
        dst[(size_t)(i * 6 + 2) * ks] = 4.f * (s1 - s2) - s3 + s4;
        dst[(size_t)(i * 6 + 3) * ks] = -2.f * s1 - s2 + 2.f * s3 + s4;
        dst[(size_t)(i * 6 + 4) * ks] = 2.f * s1 - s2 - 2.f * s3 + s4;
        dst[(size_t)(i * 6 + 5) * ks] = 4.f * s1 - 5.f * s3 + s5;
    }
}

// ----------------------------- 36x batched GEMM -> fp32 M ---------------------------
// Warp-broadcast mapping: warp owns 16 m (wid*16), lane owns 2 (gamma,beta) pairs
// (n floats lane*4..+4). A loads are warp-uniform broadcasts.
__global__ __launch_bounds__(256, 2) void k_gemm() {
    __shared__ __align__(16) float As[2][16][128];
    __shared__ __align__(16) float Us[2][16][128];
    uint32_t As_u = smem_u32(As), Us_u = smem_u32(Us);
    int tid = threadIdx.x, lane = tid & 31, wid = tid >> 5;
    int mb = blockIdx.x;
    int k = blockIdx.y >> 1, nb = blockIdx.y & 1;
    int b = blockIdx.z;
    const float* Vb = g_V + ((size_t)(k * 8 + b) * 128) * 4096 + mb * 128;
    const float* Ub = g_U + (size_t)k * 128 * 256 + nb * 128;

    ull acc[16][2];
    #pragma unroll
    for (int i = 0; i < 16; i++) { acc[i][0] = 0ull; acc[i][1] = 0ull; }

    auto issue = [&](int c, int buf) {
        #pragma unroll
        for (int j = 0; j < 2; j++) {
            int idx = tid * 2 + j;
            int row = idx >> 5, col = (idx & 31) * 4;
            cpa16(As_u + (uint32_t)((buf * 16 + row) * 128 + col) * 4u,
                  Vb + (size_t)(c * 16 + row) * 4096 + col);
            cpa16(Us_u + (uint32_t)((buf * 16 + row) * 128 + col) * 4u,
                  Ub + (size_t)(c * 16 + row) * 256 + col);
        }
        cp_commit();
    };

    issue(0, 0);
    #pragma unroll 1
    for (int c = 0; c < 8; c++) {
        cp_wait0();
        __syncthreads();
        if (c + 1 < 8) issue(c + 1, (c + 1) & 1);
        int buf = c & 1;
        #pragma unroll
        for (int ci = 0; ci < 16; ci++) {
            const float* ar = &As[buf][ci][wid * 16];
            float4 A0 = *(const float4*)(ar + 0);
            float4 A1 = *(const float4*)(ar + 4);
            float4 A2 = *(const float4*)(ar + 8);
            float4 A3 = *(const float4*)(ar + 12);
            ulonglong2 u = *(const ulonglong2*)&Us[buf][ci][lane * 4];
            float am[16] = { A0.x, A0.y, A0.z, A0.w, A1.x, A1.y, A1.z, A1.w,
                             A2.x, A2.y, A2.z, A2.w, A3.x, A3.y, A3.z, A3.w };
            #pragma unroll
            for (int i = 0; i < 16; i++) {
                ull a = pack2(am[i], am[i]);
                acc[i][0] = fma2(a, u.x, acc[i][0]);
                acc[i][1] = fma2(a, u.y, acc[i][1]);
            }
        }
        __syncthreads();
    }
    #pragma unroll
    for (int c2 = 0; c2 < 2; c2++) {
        int co = nb * 64 + lane * 2 + c2;
        ull* Mr = (ull*)g_M + ((size_t)(k * 8 + b) * 128 + co) * 4096 + mb * 128 + wid * 16;
        #pragma unroll
        for (int i = 0; i < 8; i++) {
            ulonglong2 s;
            s.x = acc[2 * i][c2]; s.y = acc[2 * i + 1][c2];
            *(ulonglong2*)(Mr + 2 * i) = s;
        }
    }
}

// ----------------------------- inverse transform + fused epilogue -------------------
// grid (16, 8, 8): thread = one 4x4 output tile, loop 16 co.
__global__ __launch_bounds__(256) void k_inv(const float* __restrict__ x,
                                             const float* __restrict__ nvar,
                                             float* __restrict__ out) {
    int tid = threadIdx.x;
    int b = blockIdx.z;
    int tile = blockIdx.x * 256 + tid;
    int ty = tile >> 6, tx = tile & 63;
    int co0 = blockIdx.y * 16;
    int y0 = 4 * ty, x0 = 4 * tx;

    int cls16[4][4];
    #pragma unroll
    for (int i = 0; i < 4; i++)
        #pragma unroll
        for (int j = 0; j < 4; j++) {
            int cy = 2 * ty - 1 + i, cx = 2 * tx - 1 + j;
            int cls = 19;
            if ((unsigned)cy < 128u && (unsigned)cx < 128u)
                cls = g_cls[((size_t)b << 14) + cy * 128 + cx];
            cls16[i][j] = cls;
        }
    float nz[4][4];
    #pragma unroll
    for (int rr = 0; rr < 4; rr++)
        *(float4*)nz[rr] = *(const float4*)&g_nT[((size_t)b * 256 + y0 + rr) * 256 + x0];
    float ga = g_scal[0], ba = g_scal[1];
    const size_t ks = (size_t)8 * 128 * 4096;
    const float c1t[6] = {0.f, 1.f, -1.f, 2.f, -2.f, 0.f};
    const float c2t[6] = {0.f, 1.f, 1.f, 4.f, 4.f, 0.f};
    const float c3t[6] = {0.f, 1.f, -1.f, 8.f, -8.f, 1.f};

    #pragma unroll 1
    for (int ic = 0; ic < 16; ic++) {
        int co = co0 + ic;
        const float2* Mp = (const float2*)g_M + ((size_t)b * 128 + co) * 4096 + tile;
        float2 Y[4][4];
        #pragma unroll
        for (int h = 0; h < 4; h++)
            #pragma unroll
            for (int w = 0; w < 4; w++) Y[h][w] = make_float2(0.f, 0.f);
        #pragma unroll
        for (int i = 0; i < 6; i++) {
            float2 m[6];
            #pragma unroll
            for (int j = 0; j < 6; j++) m[j] = Mp[(size_t)(i * 6 + j) * ks];
            float2 s12 = f2add(m[1], m[2]), d12 = f2sub(m[1], m[2]);
            float2 s34 = f2add(m[3], m[4]), d34 = f2sub(m[3], m[4]);
            float2 P[4];
            P[0] = f2add(f2add(m[0], s12), s34);
            P[1] = f2fma(2.f, d34, d12);
            P[2] = f2fma(4.f, s34, s12);
            P[3] = f2add(f2fma(8.f, d34, d12), m[5]);
            float a1 = c1t[i], a2 = c2t[i], a3 = c3t[i];
            #pragma unroll
            for (int w = 0; w < 4; w++) {
                if (i < 5) Y[0][w] = f2add(Y[0][w], P[w]);
                Y[1][w] = f2fma(a1, P[w], Y[1][w]);
                Y[2][w] = f2fma(a2, P[w], Y[2][w]);
                Y[3][w] = f2fma(a3, P[w], Y[3][w]);
            }
        }
        float mean = g_mean[b * 128 + co];
        float rs = g_rstd[b * 128 + co];
        float nv = nvar[co];
        float cg = g_Cg[co], cb = g_Cb[co];
        size_t base = (((size_t)b * 128 + co) * 256 + y0) * 256 + x0;
        #pragma unroll
        for (int h = 0; h < 4; h++) {
            float4 xv = *(const float4*)&x[base + h * 256];
            const float* xp = (const float*)&xv;
            float o4[4];
            int ph = h & 1;
            int cr = ((h - 1) >> 1) + 1;
            #pragma unroll
            for (int w = 0; w < 4; w++) {
                int pw = w & 1;
                int cc = ((w - 1) >> 1) + 1;
                float ag = 0.f, ab = 0.f;
                #pragma unroll
                for (int u = 0; u < 2; u++)
                    #pragma unroll
                    for (int v = 0; v < 2; v++) {
                        unsigned row = (unsigned)(((((b * 20 + cls16[cr + u][cc + v]) * 2 + ph) * 2 + pw) * 2 + u) * 2 + v) * 256u;
                        float2 gg = *(const float2*)&g_G4[row + (unsigned)co * 2u];
                        ag += gg.x; ab += gg.y;
                    }
                float gf = ga * ag + (1.f - ga) * Y[h][w].x + cg;
                float bf = ba * ab + (1.f - ba) * Y[h][w].y + cb;
                float val = (xp[w] + nz[h][w] * nv - mean) * rs;
                o4[w] = fmaf(val, gf, val + bf);
            }
            *(float4*)&out[base + h * 256] = make_float4(o4[0], o4[1], o4[2], o4[3]);
        }
    }
}

// ----------------------------- launch -----------------------------
extern "C" void kernel_launch(void* const* d_in, const int* in_sizes, int n_in,
                              void* d_out, int out_size) {
    const float* x     = (const float*)d_in[0];
    const float* seg   = (const float*)d_in[1];
    const float* sc    = (const float*)d_in[2];
    const float* noise = (const float*)d_in[3];
    const float* nvar  = (const float*)d_in[4];
    const float* bg    = (const float*)d_in[5];
    const float* bb    = (const float*)d_in[6];
    const float* fcw   = (const float*)d_in[7];
    const float* fcb   = (const float*)d_in[8];
    const float* cgw   = (const float*)d_in[9];
    const float* cbw   = (const float*)d_in[11];
    const float* ssw   = (const float*)d_in[13];
    const float* ssb   = (const float*)d_in[14];
    const float* sgw   = (const float*)d_in[15];
    const float* sbw   = (const float*)d_in[17];
    float* out = (float*)d_out;

    k_prep<<<1345, 256>>>(bg, bb, (const float*)d_in[10], (const float*)d_in[12],
                          (const float*)d_in[16], (const float*)d_in[18],
                          sc, fcw, fcb, seg, ssw, sgw, sbw, noise);
    k_stats<<<1024, 256>>>(x, nvar);
    k_lut1<<<160, 128>>>(cgw, cbw);
    k_actv<<<dim3(16, 32, 8), 256>>>(seg, ssb);
    k_vt<<<dim3(16, 128, 8), 256>>>();
    k_gemm<<<dim3(32, 72, 8), 256>>>();
    k_lut2<<<160, 256>>>();
    k_inv<<<dim3(16, 8, 8), 256>>>(x, nvar, out);
}